// round 1
// baseline (speedup 1.0000x reference)
#include <cuda_runtime.h>
#include <math.h>

#define SEQ   2048
#define EMB   4096
#define KVD   1024
#define NH    32
#define HD    128

// -------- scratch (no allocation allowed; static device globals) --------
__device__ float g_Q[SEQ * EMB];   // 32 MB
__device__ float g_K[SEQ * KVD];   // 8 MB
__device__ float g_V[SEQ * KVD];   // 8 MB
__device__ float g_A[SEQ * EMB];   // 32 MB  (attention output, head-concat layout)

// ============================================================================
// GEMM (NT): C[M,N] = A[M,K] @ B[N,K]^T + bias[N]
// A row-major [M,K], B row-major [N,K] (both K contiguous -> coalesced loads).
// Block tile 128x128, K-step 8, 256 threads, 8x8 per-thread microtile.
// ============================================================================
__global__ __launch_bounds__(256)
void gemm_nt_bias(const float* __restrict__ A, const float* __restrict__ B,
                  const float* __restrict__ bias, float* __restrict__ C,
                  int M, int N, int K)
{
    __shared__ float As[8][128];
    __shared__ float Bs[8][128];

    const int tid = threadIdx.x;
    const int ty = tid >> 4;          // 0..15
    const int tx = tid & 15;          // 0..15
    const int row0 = blockIdx.y * 128;
    const int col0 = blockIdx.x * 128;

    // loader: each thread brings one float4 of A and one of B per K-step
    const int lr = tid >> 1;          // 0..127
    const int lk = (tid & 1) * 4;     // 0 or 4
    const float* ap = A + (size_t)(row0 + lr) * K + lk;
    const float* bp = B + (size_t)(col0 + lr) * K + lk;

    float acc[8][8];
#pragma unroll
    for (int i = 0; i < 8; i++)
#pragma unroll
        for (int j = 0; j < 8; j++) acc[i][j] = 0.0f;

    for (int k0 = 0; k0 < K; k0 += 8) {
        float4 a4 = *(const float4*)(ap + k0);
        float4 b4 = *(const float4*)(bp + k0);
        __syncthreads();   // previous compute phase done before overwrite
        As[lk + 0][lr] = a4.x; As[lk + 1][lr] = a4.y;
        As[lk + 2][lr] = a4.z; As[lk + 3][lr] = a4.w;
        Bs[lk + 0][lr] = b4.x; Bs[lk + 1][lr] = b4.y;
        Bs[lk + 2][lr] = b4.z; Bs[lk + 3][lr] = b4.w;
        __syncthreads();

#pragma unroll
        for (int kk = 0; kk < 8; kk++) {
            float4 a0 = *(const float4*)&As[kk][ty * 8];
            float4 a1 = *(const float4*)&As[kk][ty * 8 + 4];
            float4 b0 = *(const float4*)&Bs[kk][tx * 8];
            float4 b1 = *(const float4*)&Bs[kk][tx * 8 + 4];
            float ra[8] = {a0.x, a0.y, a0.z, a0.w, a1.x, a1.y, a1.z, a1.w};
            float rb[8] = {b0.x, b0.y, b0.z, b0.w, b1.x, b1.y, b1.z, b1.w};
#pragma unroll
            for (int i = 0; i < 8; i++)
#pragma unroll
                for (int j = 0; j < 8; j++)
                    acc[i][j] = fmaf(ra[i], rb[j], acc[i][j]);
        }
    }

    // epilogue with bias
    float bi[8];
#pragma unroll
    for (int j = 0; j < 8; j++) bi[j] = bias[col0 + tx * 8 + j];

#pragma unroll
    for (int i = 0; i < 8; i++) {
        float* cp = C + (size_t)(row0 + ty * 8 + i) * N + col0 + tx * 8;
        float4 r0, r1;
        r0.x = acc[i][0] + bi[0]; r0.y = acc[i][1] + bi[1];
        r0.z = acc[i][2] + bi[2]; r0.w = acc[i][3] + bi[3];
        r1.x = acc[i][4] + bi[4]; r1.y = acc[i][5] + bi[5];
        r1.z = acc[i][6] + bi[6]; r1.w = acc[i][7] + bi[7];
        *(float4*)cp = r0;
        *(float4*)(cp + 4) = r1;
    }
}

// ============================================================================
// Flash-style attention with base-2 softermax.
// Grid: (SEQ/64, NH). One CTA = 64 queries x 1 head. 256 threads.
// smem: Qs[64][128] (pre-scaled), Kst[128][64] (d-major), Vs[64][128],
//       Ps[64][68].
// Per-thread: S microtile 4x4 (q=ty*4+i, kv=tx*4+j),
//             O microtile 4x8 (q=ty*4+i, d=tx*8+j). m/l replicated over tx.
// ============================================================================
#define ATT_SMEM_FLOATS (64*128 + 128*64 + 64*128 + 64*68)

__global__ __launch_bounds__(256)
void flash_attn()
{
    extern __shared__ float sm[];
    float* Qs  = sm;                       // 64 x 128
    float* Kst = Qs  + 64 * 128;           // 128 x 64 (d-major)
    float* Vs  = Kst + 128 * 64;           // 64 x 128
    float* Ps  = Vs  + 64 * 128;           // 64 x 68 (padded)

    const int tid = threadIdx.x;
    const int ty = tid >> 4;
    const int tx = tid & 15;
    const int h  = blockIdx.y;
    const int hk = h >> 2;                 // GQA: 4 query heads per kv head
    const int q0 = blockIdx.x * 64;
    const float scale = 0.08838834764831845f;   // 1/sqrt(128)

    // load Q tile, pre-scaled
    for (int idx = tid; idx < 64 * 32; idx += 256) {
        int q = idx >> 5, dv = (idx & 31) * 4;
        float4 v = *(const float4*)(g_Q + (size_t)(q0 + q) * EMB + h * HD + dv);
        float* dst = Qs + q * 128 + dv;
        dst[0] = v.x * scale; dst[1] = v.y * scale;
        dst[2] = v.z * scale; dst[3] = v.w * scale;
    }

    float m[4], l[4], o[4][8];
#pragma unroll
    for (int i = 0; i < 4; i++) {
        m[i] = -1e30f; l[i] = 0.0f;
#pragma unroll
        for (int j = 0; j < 8; j++) o[i][j] = 0.0f;
    }

    for (int kt = 0; kt < SEQ / 64; kt++) {
        __syncthreads();   // previous iteration's smem reads done
        // load K (transposed to d-major) and V tiles
        for (int idx = tid; idx < 64 * 32; idx += 256) {
            int kv = idx >> 5, dv = (idx & 31) * 4;
            size_t gro = (size_t)(kt * 64 + kv) * KVD + hk * HD + dv;
            float4 k4 = *(const float4*)(g_K + gro);
            Kst[(dv + 0) * 64 + kv] = k4.x;
            Kst[(dv + 1) * 64 + kv] = k4.y;
            Kst[(dv + 2) * 64 + kv] = k4.z;
            Kst[(dv + 3) * 64 + kv] = k4.w;
            float4 v4 = *(const float4*)(g_V + gro);
            *(float4*)(Vs + kv * 128 + dv) = v4;
        }
        __syncthreads();

        // S = Qs @ K^T  (scale folded into Qs)
        float s[4][4];
#pragma unroll
        for (int i = 0; i < 4; i++)
#pragma unroll
            for (int j = 0; j < 4; j++) s[i][j] = 0.0f;

#pragma unroll 8
        for (int d = 0; d < 128; d++) {
            float4 kf = *(const float4*)(Kst + d * 64 + tx * 4);
            float rq0 = Qs[(ty * 4 + 0) * 128 + d];
            float rq1 = Qs[(ty * 4 + 1) * 128 + d];
            float rq2 = Qs[(ty * 4 + 2) * 128 + d];
            float rq3 = Qs[(ty * 4 + 3) * 128 + d];
            s[0][0] = fmaf(rq0, kf.x, s[0][0]); s[0][1] = fmaf(rq0, kf.y, s[0][1]);
            s[0][2] = fmaf(rq0, kf.z, s[0][2]); s[0][3] = fmaf(rq0, kf.w, s[0][3]);
            s[1][0] = fmaf(rq1, kf.x, s[1][0]); s[1][1] = fmaf(rq1, kf.y, s[1][1]);
            s[1][2] = fmaf(rq1, kf.z, s[1][2]); s[1][3] = fmaf(rq1, kf.w, s[1][3]);
            s[2][0] = fmaf(rq2, kf.x, s[2][0]); s[2][1] = fmaf(rq2, kf.y, s[2][1]);
            s[2][2] = fmaf(rq2, kf.z, s[2][2]); s[2][3] = fmaf(rq2, kf.w, s[2][3]);
            s[3][0] = fmaf(rq3, kf.x, s[3][0]); s[3][1] = fmaf(rq3, kf.y, s[3][1]);
            s[3][2] = fmaf(rq3, kf.z, s[3][2]); s[3][3] = fmaf(rq3, kf.w, s[3][3]);
        }

        // online base-2 softmax; row q spread across the 16 tx lanes
#pragma unroll
        for (int i = 0; i < 4; i++) {
            float tmax = fmaxf(fmaxf(s[i][0], s[i][1]), fmaxf(s[i][2], s[i][3]));
#pragma unroll
            for (int off = 8; off >= 1; off >>= 1)
                tmax = fmaxf(tmax, __shfl_xor_sync(0xffffffffu, tmax, off));
            float newm = fmaxf(m[i], tmax);
            float corr = exp2f(m[i] - newm);
            m[i] = newm;
            float p0 = exp2f(s[i][0] - newm);
            float p1 = exp2f(s[i][1] - newm);
            float p2 = exp2f(s[i][2] - newm);
            float p3 = exp2f(s[i][3] - newm);
            float psum = (p0 + p1) + (p2 + p3);
#pragma unroll
            for (int off = 8; off >= 1; off >>= 1)
                psum += __shfl_xor_sync(0xffffffffu, psum, off);
            l[i] = l[i] * corr + psum;
#pragma unroll
            for (int j = 0; j < 8; j++) o[i][j] *= corr;
            float4 pv; pv.x = p0; pv.y = p1; pv.z = p2; pv.w = p3;
            *(float4*)(Ps + (ty * 4 + i) * 68 + tx * 4) = pv;
        }
        __syncthreads();

        // O += P @ V
#pragma unroll 4
        for (int kv = 0; kv < 64; kv++) {
            float4 v0 = *(const float4*)(Vs + kv * 128 + tx * 8);
            float4 v1 = *(const float4*)(Vs + kv * 128 + tx * 8 + 4);
#pragma unroll
            for (int i = 0; i < 4; i++) {
                float p = Ps[(ty * 4 + i) * 68 + kv];
                o[i][0] = fmaf(p, v0.x, o[i][0]);
                o[i][1] = fmaf(p, v0.y, o[i][1]);
                o[i][2] = fmaf(p, v0.z, o[i][2]);
                o[i][3] = fmaf(p, v0.w, o[i][3]);
                o[i][4] = fmaf(p, v1.x, o[i][4]);
                o[i][5] = fmaf(p, v1.y, o[i][5]);
                o[i][6] = fmaf(p, v1.z, o[i][6]);
                o[i][7] = fmaf(p, v1.w, o[i][7]);
            }
        }
    }

    // finalize and store to g_A in [s][h*128+d] layout
#pragma unroll
    for (int i = 0; i < 4; i++) {
        float inv = 1.0f / l[i];
        float* dst = g_A + (size_t)(q0 + ty * 4 + i) * EMB + h * HD + tx * 8;
        float4 r0, r1;
        r0.x = o[i][0] * inv; r0.y = o[i][1] * inv;
        r0.z = o[i][2] * inv; r0.w = o[i][3] * inv;
        r1.x = o[i][4] * inv; r1.y = o[i][5] * inv;
        r1.z = o[i][6] * inv; r1.w = o[i][7] * inv;
        *(float4*)dst = r0;
        *(float4*)(dst + 4) = r1;
    }
}

// ============================================================================
// launch
// ============================================================================
extern "C" void kernel_launch(void* const* d_in, const int* in_sizes, int n_in,
                              void* d_out, int out_size)
{
    const float* x   = (const float*)d_in[0];
    const float* q_w = (const float*)d_in[1];
    const float* q_b = (const float*)d_in[2];
    const float* k_w = (const float*)d_in[3];
    const float* k_b = (const float*)d_in[4];
    const float* v_w = (const float*)d_in[5];
    const float* v_b = (const float*)d_in[6];
    const float* o_w = (const float*)d_in[7];
    const float* o_b = (const float*)d_in[8];
    float* out = (float*)d_out;

    float *qp, *kp, *vp, *ap;
    cudaGetSymbolAddress((void**)&qp, g_Q);
    cudaGetSymbolAddress((void**)&kp, g_K);
    cudaGetSymbolAddress((void**)&vp, g_V);
    cudaGetSymbolAddress((void**)&ap, g_A);

    const int smem_att = ATT_SMEM_FLOATS * (int)sizeof(float);
    cudaFuncSetAttribute(flash_attn, cudaFuncAttributeMaxDynamicSharedMemorySize,
                         smem_att);

    dim3 blk(256);
    // Q = x @ q_w^T + q_b          [2048, 4096]
    gemm_nt_bias<<<dim3(EMB / 128, SEQ / 128), blk>>>(x, q_w, q_b, qp, SEQ, EMB, EMB);
    // K = x @ k_w^T + k_b          [2048, 1024]
    gemm_nt_bias<<<dim3(KVD / 128, SEQ / 128), blk>>>(x, k_w, k_b, kp, SEQ, KVD, EMB);
    // V = x @ v_w^T + v_b          [2048, 1024]
    gemm_nt_bias<<<dim3(KVD / 128, SEQ / 128), blk>>>(x, v_w, v_b, vp, SEQ, KVD, EMB);
    // attention (softermax) -> g_A [2048, 4096]
    flash_attn<<<dim3(SEQ / 64, NH), blk, smem_att>>>();
    // out = g_A @ o_w^T + o_b      [2048, 4096]
    gemm_nt_bias<<<dim3(EMB / 128, SEQ / 128), blk>>>(ap, o_w, o_b, out, SEQ, EMB, EMB);
}

// round 3
// speedup vs baseline: 1.5776x; 1.5776x over previous
#include <cuda_runtime.h>
#include <cuda_bf16.h>
#include <cstdint>
#include <math.h>

#define SEQ   2048
#define EMB   4096
#define KVD   1024
#define NH    32
#define HD    128

// -------- scratch (no allocation allowed; static device globals) --------
__device__ float g_Q[SEQ * EMB];
__device__ float g_K[SEQ * KVD];
__device__ float g_V[SEQ * KVD];
__device__ float g_A[SEQ * EMB];

// bf16 split buffers (hi + residual lo)
__device__ __nv_bfloat16 g_xh[SEQ * EMB];
__device__ __nv_bfloat16 g_xl[SEQ * EMB];
__device__ __nv_bfloat16 g_qwh[EMB * EMB];
__device__ __nv_bfloat16 g_qwl[EMB * EMB];
__device__ __nv_bfloat16 g_kwh[KVD * EMB];
__device__ __nv_bfloat16 g_kwl[KVD * EMB];
__device__ __nv_bfloat16 g_vwh[KVD * EMB];
__device__ __nv_bfloat16 g_vwl[KVD * EMB];
__device__ __nv_bfloat16 g_owh[EMB * EMB];
__device__ __nv_bfloat16 g_owl[EMB * EMB];
__device__ __nv_bfloat16 g_awh[SEQ * EMB];
__device__ __nv_bfloat16 g_awl[SEQ * EMB];

// ============================================================================
// fp32 -> (bf16 hi, bf16 lo residual) split. n4 = n/4 float4 elements.
// ============================================================================
__global__ __launch_bounds__(256)
void cvt_split(const float4* __restrict__ in,
               __nv_bfloat162* __restrict__ hi,
               __nv_bfloat162* __restrict__ lo, int n4)
{
    int i = blockIdx.x * blockDim.x + threadIdx.x;
    if (i >= n4) return;
    float4 v = in[i];
    __nv_bfloat16 h0 = __float2bfloat16(v.x);
    __nv_bfloat16 h1 = __float2bfloat16(v.y);
    __nv_bfloat16 h2 = __float2bfloat16(v.z);
    __nv_bfloat16 h3 = __float2bfloat16(v.w);
    __nv_bfloat16 l0 = __float2bfloat16(v.x - __bfloat162float(h0));
    __nv_bfloat16 l1 = __float2bfloat16(v.y - __bfloat162float(h1));
    __nv_bfloat16 l2 = __float2bfloat16(v.z - __bfloat162float(h2));
    __nv_bfloat16 l3 = __float2bfloat16(v.w - __bfloat162float(h3));
    hi[i * 2 + 0] = __halves2bfloat162(h0, h1);
    hi[i * 2 + 1] = __halves2bfloat162(h2, h3);
    lo[i * 2 + 0] = __halves2bfloat162(l0, l1);
    lo[i * 2 + 1] = __halves2bfloat162(l2, l3);
}

// ============================================================================
// Split-bf16 tensor-core GEMM (NT): C[M,N] = A[M,K] @ B[N,K]^T + bias[N]
// 3 mma passes: Ah*Bh + Ah*Bl + Al*Bh, fp32 accumulate.
// Block 128x128x32, 256 threads (8 warps), warp tile 64x32.
// ============================================================================
#define BKP 40

__device__ __forceinline__ void ldsm_x4(uint32_t* r, const __nv_bfloat16* p)
{
    uint32_t addr = (uint32_t)__cvta_generic_to_shared(p);
    asm volatile("ldmatrix.sync.aligned.m8n8.x4.shared.b16 {%0,%1,%2,%3}, [%4];"
                 : "=r"(r[0]), "=r"(r[1]), "=r"(r[2]), "=r"(r[3])
                 : "r"(addr));
}

__device__ __forceinline__ void mma16816(float* c, const uint32_t* a,
                                         uint32_t b0, uint32_t b1)
{
    asm volatile(
        "mma.sync.aligned.m16n8k16.row.col.f32.bf16.bf16.f32 "
        "{%0,%1,%2,%3}, {%4,%5,%6,%7}, {%8,%9}, {%0,%1,%2,%3};"
        : "+f"(c[0]), "+f"(c[1]), "+f"(c[2]), "+f"(c[3])
        : "r"(a[0]), "r"(a[1]), "r"(a[2]), "r"(a[3]), "r"(b0), "r"(b1));
}

__global__ __launch_bounds__(256)
void gemm_bf16split(const __nv_bfloat16* __restrict__ Ahg,
                    const __nv_bfloat16* __restrict__ Alg,
                    const __nv_bfloat16* __restrict__ Bhg,
                    const __nv_bfloat16* __restrict__ Blg,
                    const float* __restrict__ bias,
                    float* __restrict__ C,
                    int M, int N, int K)
{
    __shared__ __nv_bfloat16 Ah[128][BKP];
    __shared__ __nv_bfloat16 Al[128][BKP];
    __shared__ __nv_bfloat16 Bh[128][BKP];
    __shared__ __nv_bfloat16 Bl[128][BKP];

    const int tid  = threadIdx.x;
    const int warp = tid >> 5;
    const int lane = tid & 31;
    const int wm = (warp >> 2) * 64;
    const int wn = (warp & 3) * 32;
    const int row0 = blockIdx.y * 128;
    const int col0 = blockIdx.x * 128;

    const int lr = tid >> 1;
    const int lc = (tid & 1) * 16;

    const __nv_bfloat16* pAh = Ahg + (size_t)(row0 + lr) * K + lc;
    const __nv_bfloat16* pAl = Alg + (size_t)(row0 + lr) * K + lc;
    const __nv_bfloat16* pBh = Bhg + (size_t)(col0 + lr) * K + lc;
    const __nv_bfloat16* pBl = Blg + (size_t)(col0 + lr) * K + lc;

    float acc[4][4][4];
#pragma unroll
    for (int i = 0; i < 4; i++) {
#pragma unroll
        for (int j = 0; j < 4; j++) {
#pragma unroll
            for (int r = 0; r < 4; r++) {
                acc[i][j][r] = 0.0f;
            }
        }
    }

    const int lrow = lane & 15;
    const int lcol = (lane >> 4) * 8;

    for (int k0 = 0; k0 < K; k0 += 32) {
        uint4 vah0 = *(const uint4*)(pAh + k0);
        uint4 vah1 = *(const uint4*)(pAh + k0 + 8);
        uint4 val0 = *(const uint4*)(pAl + k0);
        uint4 val1 = *(const uint4*)(pAl + k0 + 8);
        uint4 vbh0 = *(const uint4*)(pBh + k0);
        uint4 vbh1 = *(const uint4*)(pBh + k0 + 8);
        uint4 vbl0 = *(const uint4*)(pBl + k0);
        uint4 vbl1 = *(const uint4*)(pBl + k0 + 8);
        __syncthreads();
        *(uint4*)&Ah[lr][lc]     = vah0;
        *(uint4*)&Ah[lr][lc + 8] = vah1;
        *(uint4*)&Al[lr][lc]     = val0;
        *(uint4*)&Al[lr][lc + 8] = val1;
        *(uint4*)&Bh[lr][lc]     = vbh0;
        *(uint4*)&Bh[lr][lc + 8] = vbh1;
        *(uint4*)&Bl[lr][lc]     = vbl0;
        *(uint4*)&Bl[lr][lc + 8] = vbl1;
        __syncthreads();

#pragma unroll
        for (int ks = 0; ks < 2; ks++) {
            const int kk = ks * 16;
            uint32_t ah[4][4];
            uint32_t al[4][4];
            uint32_t bh[2][4];
            uint32_t bl[2][4];
#pragma unroll
            for (int mi = 0; mi < 4; mi++) {
                ldsm_x4(ah[mi], &Ah[wm + mi * 16 + lrow][kk + lcol]);
                ldsm_x4(al[mi], &Al[wm + mi * 16 + lrow][kk + lcol]);
            }
#pragma unroll
            for (int nb = 0; nb < 2; nb++) {
                ldsm_x4(bh[nb], &Bh[wn + nb * 16 + lrow][kk + lcol]);
                ldsm_x4(bl[nb], &Bl[wn + nb * 16 + lrow][kk + lcol]);
            }
#pragma unroll
            for (int mi = 0; mi < 4; mi++) {
#pragma unroll
                for (int nj = 0; nj < 4; nj++) {
                    const int nb = nj >> 1;
                    const int ns = nj & 1;
                    uint32_t b0h = bh[nb][ns];
                    uint32_t b1h = bh[nb][ns + 2];
                    uint32_t b0l = bl[nb][ns];
                    uint32_t b1l = bl[nb][ns + 2];
                    mma16816(acc[mi][nj], ah[mi], b0h, b1h);
                    mma16816(acc[mi][nj], ah[mi], b0l, b1l);
                    mma16816(acc[mi][nj], al[mi], b0h, b1h);
                }
            }
        }
    }

#pragma unroll
    for (int mi = 0; mi < 4; mi++) {
#pragma unroll
        for (int nj = 0; nj < 4; nj++) {
            int row = row0 + wm + mi * 16 + (lane >> 2);
            int col = col0 + wn + nj * 8 + (lane & 3) * 2;
            float b0 = bias[col];
            float b1 = bias[col + 1];
            float2 r0;
            float2 r1;
            r0.x = acc[mi][nj][0] + b0;
            r0.y = acc[mi][nj][1] + b1;
            r1.x = acc[mi][nj][2] + b0;
            r1.y = acc[mi][nj][3] + b1;
            *(float2*)(C + (size_t)row * N + col) = r0;
            *(float2*)(C + (size_t)(row + 8) * N + col) = r1;
        }
    }
}

// ============================================================================
// Flash-style attention with base-2 softermax (fp32, unchanged).
// ============================================================================
#define ATT_SMEM_FLOATS (64*128 + 128*64 + 64*128 + 64*68)

__global__ __launch_bounds__(256)
void flash_attn()
{
    extern __shared__ float sm[];
    float* Qs  = sm;
    float* Kst = Qs  + 64 * 128;
    float* Vs  = Kst + 128 * 64;
    float* Ps  = Vs  + 64 * 128;

    const int tid = threadIdx.x;
    const int ty = tid >> 4;
    const int tx = tid & 15;
    const int h  = blockIdx.y;
    const int hk = h >> 2;
    const int q0 = blockIdx.x * 64;
    const float scale = 0.08838834764831845f;

    for (int idx = tid; idx < 64 * 32; idx += 256) {
        int q = idx >> 5;
        int dv = (idx & 31) * 4;
        float4 v = *(const float4*)(g_Q + (size_t)(q0 + q) * EMB + h * HD + dv);
        float* dst = Qs + q * 128 + dv;
        dst[0] = v.x * scale;
        dst[1] = v.y * scale;
        dst[2] = v.z * scale;
        dst[3] = v.w * scale;
    }

    float m[4];
    float l[4];
    float o[4][8];
#pragma unroll
    for (int i = 0; i < 4; i++) {
        m[i] = -1e30f;
        l[i] = 0.0f;
#pragma unroll
        for (int j = 0; j < 8; j++) {
            o[i][j] = 0.0f;
        }
    }

    for (int kt = 0; kt < SEQ / 64; kt++) {
        __syncthreads();
        for (int idx = tid; idx < 64 * 32; idx += 256) {
            int kv = idx >> 5;
            int dv = (idx & 31) * 4;
            size_t gro = (size_t)(kt * 64 + kv) * KVD + hk * HD + dv;
            float4 k4 = *(const float4*)(g_K + gro);
            Kst[(dv + 0) * 64 + kv] = k4.x;
            Kst[(dv + 1) * 64 + kv] = k4.y;
            Kst[(dv + 2) * 64 + kv] = k4.z;
            Kst[(dv + 3) * 64 + kv] = k4.w;
            float4 v4 = *(const float4*)(g_V + gro);
            *(float4*)(Vs + kv * 128 + dv) = v4;
        }
        __syncthreads();

        float s[4][4];
#pragma unroll
        for (int i = 0; i < 4; i++) {
#pragma unroll
            for (int j = 0; j < 4; j++) {
                s[i][j] = 0.0f;
            }
        }

#pragma unroll 8
        for (int d = 0; d < 128; d++) {
            float4 kf = *(const float4*)(Kst + d * 64 + tx * 4);
            float rq0 = Qs[(ty * 4 + 0) * 128 + d];
            float rq1 = Qs[(ty * 4 + 1) * 128 + d];
            float rq2 = Qs[(ty * 4 + 2) * 128 + d];
            float rq3 = Qs[(ty * 4 + 3) * 128 + d];
            s[0][0] = fmaf(rq0, kf.x, s[0][0]);
            s[0][1] = fmaf(rq0, kf.y, s[0][1]);
            s[0][2] = fmaf(rq0, kf.z, s[0][2]);
            s[0][3] = fmaf(rq0, kf.w, s[0][3]);
            s[1][0] = fmaf(rq1, kf.x, s[1][0]);
            s[1][1] = fmaf(rq1, kf.y, s[1][1]);
            s[1][2] = fmaf(rq1, kf.z, s[1][2]);
            s[1][3] = fmaf(rq1, kf.w, s[1][3]);
            s[2][0] = fmaf(rq2, kf.x, s[2][0]);
            s[2][1] = fmaf(rq2, kf.y, s[2][1]);
            s[2][2] = fmaf(rq2, kf.z, s[2][2]);
            s[2][3] = fmaf(rq2, kf.w, s[2][3]);
            s[3][0] = fmaf(rq3, kf.x, s[3][0]);
            s[3][1] = fmaf(rq3, kf.y, s[3][1]);
            s[3][2] = fmaf(rq3, kf.z, s[3][2]);
            s[3][3] = fmaf(rq3, kf.w, s[3][3]);
        }

#pragma unroll
        for (int i = 0; i < 4; i++) {
            float tmax = fmaxf(fmaxf(s[i][0], s[i][1]), fmaxf(s[i][2], s[i][3]));
#pragma unroll
            for (int off = 8; off >= 1; off >>= 1) {
                tmax = fmaxf(tmax, __shfl_xor_sync(0xffffffffu, tmax, off));
            }
            float newm = fmaxf(m[i], tmax);
            float corr = exp2f(m[i] - newm);
            m[i] = newm;
            float p0 = exp2f(s[i][0] - newm);
            float p1 = exp2f(s[i][1] - newm);
            float p2 = exp2f(s[i][2] - newm);
            float p3 = exp2f(s[i][3] - newm);
            float psum = (p0 + p1) + (p2 + p3);
#pragma unroll
            for (int off = 8; off >= 1; off >>= 1) {
                psum += __shfl_xor_sync(0xffffffffu, psum, off);
            }
            l[i] = l[i] * corr + psum;
#pragma unroll
            for (int j = 0; j < 8; j++) {
                o[i][j] *= corr;
            }
            float4 pv;
            pv.x = p0;
            pv.y = p1;
            pv.z = p2;
            pv.w = p3;
            *(float4*)(Ps + (ty * 4 + i) * 68 + tx * 4) = pv;
        }
        __syncthreads();

#pragma unroll 4
        for (int kv = 0; kv < 64; kv++) {
            float4 v0 = *(const float4*)(Vs + kv * 128 + tx * 8);
            float4 v1 = *(const float4*)(Vs + kv * 128 + tx * 8 + 4);
#pragma unroll
            for (int i = 0; i < 4; i++) {
                float p = Ps[(ty * 4 + i) * 68 + kv];
                o[i][0] = fmaf(p, v0.x, o[i][0]);
                o[i][1] = fmaf(p, v0.y, o[i][1]);
                o[i][2] = fmaf(p, v0.z, o[i][2]);
                o[i][3] = fmaf(p, v0.w, o[i][3]);
                o[i][4] = fmaf(p, v1.x, o[i][4]);
                o[i][5] = fmaf(p, v1.y, o[i][5]);
                o[i][6] = fmaf(p, v1.z, o[i][6]);
                o[i][7] = fmaf(p, v1.w, o[i][7]);
            }
        }
    }

#pragma unroll
    for (int i = 0; i < 4; i++) {
        float inv = 1.0f / l[i];
        float* dst = g_A + (size_t)(q0 + ty * 4 + i) * EMB + h * HD + tx * 8;
        float4 r0;
        float4 r1;
        r0.x = o[i][0] * inv;
        r0.y = o[i][1] * inv;
        r0.z = o[i][2] * inv;
        r0.w = o[i][3] * inv;
        r1.x = o[i][4] * inv;
        r1.y = o[i][5] * inv;
        r1.z = o[i][6] * inv;
        r1.w = o[i][7] * inv;
        *(float4*)dst = r0;
        *(float4*)(dst + 4) = r1;
    }
}

// ============================================================================
// host helpers + launch
// ============================================================================
static void run_cvt(const float* src, __nv_bfloat16* h, __nv_bfloat16* l, int n)
{
    int n4 = n / 4;
    int grid = (n4 + 255) / 256;
    cvt_split<<<grid, 256>>>((const float4*)src, (__nv_bfloat162*)h,
                             (__nv_bfloat162*)l, n4);
}

extern "C" void kernel_launch(void* const* d_in, const int* in_sizes, int n_in,
                              void* d_out, int out_size)
{
    const float* x   = (const float*)d_in[0];
    const float* q_w = (const float*)d_in[1];
    const float* q_b = (const float*)d_in[2];
    const float* k_w = (const float*)d_in[3];
    const float* k_b = (const float*)d_in[4];
    const float* v_w = (const float*)d_in[5];
    const float* v_b = (const float*)d_in[6];
    const float* o_w = (const float*)d_in[7];
    const float* o_b = (const float*)d_in[8];
    float* out = (float*)d_out;

    float* qp = 0;
    float* kp = 0;
    float* vp = 0;
    float* ap = 0;
    cudaGetSymbolAddress((void**)&qp, g_Q);
    cudaGetSymbolAddress((void**)&kp, g_K);
    cudaGetSymbolAddress((void**)&vp, g_V);
    cudaGetSymbolAddress((void**)&ap, g_A);

    __nv_bfloat16* xh = 0;
    __nv_bfloat16* xl = 0;
    __nv_bfloat16* qwh = 0;
    __nv_bfloat16* qwl = 0;
    __nv_bfloat16* kwh = 0;
    __nv_bfloat16* kwl = 0;
    __nv_bfloat16* vwh = 0;
    __nv_bfloat16* vwl = 0;
    __nv_bfloat16* owh = 0;
    __nv_bfloat16* owl = 0;
    __nv_bfloat16* awh = 0;
    __nv_bfloat16* awl = 0;
    cudaGetSymbolAddress((void**)&xh,  g_xh);
    cudaGetSymbolAddress((void**)&xl,  g_xl);
    cudaGetSymbolAddress((void**)&qwh, g_qwh);
    cudaGetSymbolAddress((void**)&qwl, g_qwl);
    cudaGetSymbolAddress((void**)&kwh, g_kwh);
    cudaGetSymbolAddress((void**)&kwl, g_kwl);
    cudaGetSymbolAddress((void**)&vwh, g_vwh);
    cudaGetSymbolAddress((void**)&vwl, g_vwl);
    cudaGetSymbolAddress((void**)&owh, g_owh);
    cudaGetSymbolAddress((void**)&owl, g_owl);
    cudaGetSymbolAddress((void**)&awh, g_awh);
    cudaGetSymbolAddress((void**)&awl, g_awl);

    const int smem_att = ATT_SMEM_FLOATS * (int)sizeof(float);
    cudaFuncSetAttribute(flash_attn, cudaFuncAttributeMaxDynamicSharedMemorySize,
                         smem_att);

    dim3 blk(256);

    run_cvt(x,   xh,  xl,  SEQ * EMB);
    run_cvt(q_w, qwh, qwl, EMB * EMB);
    run_cvt(k_w, kwh, kwl, KVD * EMB);
    run_cvt(v_w, vwh, vwl, KVD * EMB);
    run_cvt(o_w, owh, owl, EMB * EMB);

    gemm_bf16split<<<dim3(EMB / 128, SEQ / 128), blk>>>(xh, xl, qwh, qwl, q_b, qp,
                                                        SEQ, EMB, EMB);
    gemm_bf16split<<<dim3(KVD / 128, SEQ / 128), blk>>>(xh, xl, kwh, kwl, k_b, kp,
                                                        SEQ, KVD, EMB);
    gemm_bf16split<<<dim3(KVD / 128, SEQ / 128), blk>>>(xh, xl, vwh, vwl, v_b, vp,
                                                        SEQ, KVD, EMB);

    flash_attn<<<dim3(SEQ / 64, NH), blk, smem_att>>>();

    run_cvt(ap, awh, awl, SEQ * EMB);
    gemm_bf16split<<<dim3(EMB / 128, SEQ / 128), blk>>>(awh, awl, owh, owl, o_b, out,
                                                        SEQ, EMB, EMB);
}

// round 4
// speedup vs baseline: 2.3815x; 1.5096x over previous
#include <cuda_runtime.h>
#include <cuda_bf16.h>
#include <cstdint>
#include <math.h>

#define SEQ   2048
#define EMB   4096
#define KVD   1024
#define NH    32
#define HD    128

// -------- scratch (device globals; no allocation allowed) --------
__device__ __nv_bfloat16 g_xh[SEQ * EMB];
__device__ __nv_bfloat16 g_xl[SEQ * EMB];
__device__ __nv_bfloat16 g_qwh[EMB * EMB];
__device__ __nv_bfloat16 g_qwl[EMB * EMB];
__device__ __nv_bfloat16 g_kwh[KVD * EMB];
__device__ __nv_bfloat16 g_kwl[KVD * EMB];
__device__ __nv_bfloat16 g_vwh[KVD * EMB];
__device__ __nv_bfloat16 g_vwl[KVD * EMB];
__device__ __nv_bfloat16 g_owh[EMB * EMB];
__device__ __nv_bfloat16 g_owl[EMB * EMB];

__device__ __nv_bfloat16 g_qh[SEQ * EMB];   // scaled Q split
__device__ __nv_bfloat16 g_ql[SEQ * EMB];
__device__ __nv_bfloat16 g_kh[SEQ * KVD];
__device__ __nv_bfloat16 g_kl[SEQ * KVD];
__device__ __nv_bfloat16 g_vh[SEQ * KVD];
__device__ __nv_bfloat16 g_vl[SEQ * KVD];
__device__ __nv_bfloat16 g_awh[SEQ * EMB];  // attention out split
__device__ __nv_bfloat16 g_awl[SEQ * EMB];

// ============================================================================
// helpers
// ============================================================================
__device__ __forceinline__ void ldsm_x4(uint32_t* r, const __nv_bfloat16* p)
{
    uint32_t addr = (uint32_t)__cvta_generic_to_shared(p);
    asm volatile("ldmatrix.sync.aligned.m8n8.x4.shared.b16 {%0,%1,%2,%3}, [%4];"
                 : "=r"(r[0]), "=r"(r[1]), "=r"(r[2]), "=r"(r[3])
                 : "r"(addr));
}

__device__ __forceinline__ void mma16816(float* c, const uint32_t* a,
                                         uint32_t b0, uint32_t b1)
{
    asm volatile(
        "mma.sync.aligned.m16n8k16.row.col.f32.bf16.bf16.f32 "
        "{%0,%1,%2,%3}, {%4,%5,%6,%7}, {%8,%9}, {%0,%1,%2,%3};"
        : "+f"(c[0]), "+f"(c[1]), "+f"(c[2]), "+f"(c[3])
        : "r"(a[0]), "r"(a[1]), "r"(a[2]), "r"(a[3]), "r"(b0), "r"(b1));
}

__device__ __forceinline__ void splitpack(float a, float b,
                                          uint32_t& hi, uint32_t& lo)
{
    __nv_bfloat16 ha = __float2bfloat16(a);
    __nv_bfloat16 hb = __float2bfloat16(b);
    __nv_bfloat16 la = __float2bfloat16(a - __bfloat162float(ha));
    __nv_bfloat16 lb = __float2bfloat16(b - __bfloat162float(hb));
    __nv_bfloat162 th = __halves2bfloat162(ha, hb);
    __nv_bfloat162 tl = __halves2bfloat162(la, lb);
    hi = *(uint32_t*)&th;
    lo = *(uint32_t*)&tl;
}

// ============================================================================
// fp32 -> (bf16 hi, bf16 lo) split conversion
// ============================================================================
__global__ __launch_bounds__(256)
void cvt_split(const float4* __restrict__ in,
               __nv_bfloat162* __restrict__ hi,
               __nv_bfloat162* __restrict__ lo, int n4)
{
    int i = blockIdx.x * blockDim.x + threadIdx.x;
    if (i >= n4) return;
    float4 v = in[i];
    uint32_t h0, l0, h1, l1;
    splitpack(v.x, v.y, h0, l0);
    splitpack(v.z, v.w, h1, l1);
    *((uint32_t*)hi + i * 2 + 0) = h0;
    *((uint32_t*)hi + i * 2 + 1) = h1;
    *((uint32_t*)lo + i * 2 + 0) = l0;
    *((uint32_t*)lo + i * 2 + 1) = l1;
}

// ============================================================================
// Split-bf16 tensor-core GEMM (NT): C = A @ B^T + bias
// If Ch != null: writes bf16 split (hi/lo) of (acc+bias)*oscale instead of fp32.
// ============================================================================
#define BKP 40

__global__ __launch_bounds__(256)
void gemm_bf16split(const __nv_bfloat16* __restrict__ Ahg,
                    const __nv_bfloat16* __restrict__ Alg,
                    const __nv_bfloat16* __restrict__ Bhg,
                    const __nv_bfloat16* __restrict__ Blg,
                    const float* __restrict__ bias,
                    float* __restrict__ C,
                    __nv_bfloat16* __restrict__ Ch,
                    __nv_bfloat16* __restrict__ Cl,
                    float oscale,
                    int M, int N, int K)
{
    __shared__ __nv_bfloat16 Ah[128][BKP];
    __shared__ __nv_bfloat16 Al[128][BKP];
    __shared__ __nv_bfloat16 Bh[128][BKP];
    __shared__ __nv_bfloat16 Bl[128][BKP];

    const int tid  = threadIdx.x;
    const int warp = tid >> 5;
    const int lane = tid & 31;
    const int wm = (warp >> 2) * 64;
    const int wn = (warp & 3) * 32;
    const int row0 = blockIdx.y * 128;
    const int col0 = blockIdx.x * 128;

    const int lr = tid >> 1;
    const int lc = (tid & 1) * 16;

    const __nv_bfloat16* pAh = Ahg + (size_t)(row0 + lr) * K + lc;
    const __nv_bfloat16* pAl = Alg + (size_t)(row0 + lr) * K + lc;
    const __nv_bfloat16* pBh = Bhg + (size_t)(col0 + lr) * K + lc;
    const __nv_bfloat16* pBl = Blg + (size_t)(col0 + lr) * K + lc;

    float acc[4][4][4];
#pragma unroll
    for (int i = 0; i < 4; i++)
#pragma unroll
        for (int j = 0; j < 4; j++)
#pragma unroll
            for (int r = 0; r < 4; r++)
                acc[i][j][r] = 0.0f;

    const int lrow = lane & 15;
    const int lcol = (lane >> 4) * 8;

    for (int k0 = 0; k0 < K; k0 += 32) {
        uint4 vah0 = *(const uint4*)(pAh + k0);
        uint4 vah1 = *(const uint4*)(pAh + k0 + 8);
        uint4 val0 = *(const uint4*)(pAl + k0);
        uint4 val1 = *(const uint4*)(pAl + k0 + 8);
        uint4 vbh0 = *(const uint4*)(pBh + k0);
        uint4 vbh1 = *(const uint4*)(pBh + k0 + 8);
        uint4 vbl0 = *(const uint4*)(pBl + k0);
        uint4 vbl1 = *(const uint4*)(pBl + k0 + 8);
        __syncthreads();
        *(uint4*)&Ah[lr][lc]     = vah0;
        *(uint4*)&Ah[lr][lc + 8] = vah1;
        *(uint4*)&Al[lr][lc]     = val0;
        *(uint4*)&Al[lr][lc + 8] = val1;
        *(uint4*)&Bh[lr][lc]     = vbh0;
        *(uint4*)&Bh[lr][lc + 8] = vbh1;
        *(uint4*)&Bl[lr][lc]     = vbl0;
        *(uint4*)&Bl[lr][lc + 8] = vbl1;
        __syncthreads();

#pragma unroll
        for (int ks = 0; ks < 2; ks++) {
            const int kk = ks * 16;
            uint32_t ah[4][4];
            uint32_t al[4][4];
            uint32_t bh[2][4];
            uint32_t bl[2][4];
#pragma unroll
            for (int mi = 0; mi < 4; mi++) {
                ldsm_x4(ah[mi], &Ah[wm + mi * 16 + lrow][kk + lcol]);
                ldsm_x4(al[mi], &Al[wm + mi * 16 + lrow][kk + lcol]);
            }
#pragma unroll
            for (int nb = 0; nb < 2; nb++) {
                ldsm_x4(bh[nb], &Bh[wn + nb * 16 + lrow][kk + lcol]);
                ldsm_x4(bl[nb], &Bl[wn + nb * 16 + lrow][kk + lcol]);
            }
#pragma unroll
            for (int mi = 0; mi < 4; mi++) {
#pragma unroll
                for (int nj = 0; nj < 4; nj++) {
                    const int nb = nj >> 1;
                    const int ns = nj & 1;
                    mma16816(acc[mi][nj], ah[mi], bh[nb][ns], bh[nb][ns + 2]);
                    mma16816(acc[mi][nj], ah[mi], bl[nb][ns], bl[nb][ns + 2]);
                    mma16816(acc[mi][nj], al[mi], bh[nb][ns], bh[nb][ns + 2]);
                }
            }
        }
    }

#pragma unroll
    for (int mi = 0; mi < 4; mi++) {
#pragma unroll
        for (int nj = 0; nj < 4; nj++) {
            int row = row0 + wm + mi * 16 + (lane >> 2);
            int col = col0 + wn + nj * 8 + (lane & 3) * 2;
            float b0 = bias[col];
            float b1 = bias[col + 1];
            float v00 = acc[mi][nj][0] + b0;
            float v01 = acc[mi][nj][1] + b1;
            float v10 = acc[mi][nj][2] + b0;
            float v11 = acc[mi][nj][3] + b1;
            if (Ch) {
                v00 *= oscale; v01 *= oscale; v10 *= oscale; v11 *= oscale;
                uint32_t h0, l0, h1, l1;
                splitpack(v00, v01, h0, l0);
                splitpack(v10, v11, h1, l1);
                *(uint32_t*)(Ch + (size_t)row * N + col) = h0;
                *(uint32_t*)(Cl + (size_t)row * N + col) = l0;
                *(uint32_t*)(Ch + (size_t)(row + 8) * N + col) = h1;
                *(uint32_t*)(Cl + (size_t)(row + 8) * N + col) = l1;
            } else {
                float2 r0;
                float2 r1;
                r0.x = v00; r0.y = v01;
                r1.x = v10; r1.y = v11;
                *(float2*)(C + (size_t)row * N + col) = r0;
                *(float2*)(C + (size_t)(row + 8) * N + col) = r1;
            }
        }
    }
}

// ============================================================================
// Tensor-core flash attention with base-2 softermax, split-bf16 (3-pass mma).
// Grid (SEQ/128, NH), 256 threads. Warp w owns query rows w*16..w*16+15.
// ============================================================================
#define QPAD 136
#define VPAD 72
#define FL_SMEM_BYTES ((2 * 64 * QPAD + 2 * 128 * VPAD) * 2)   // 71680

__global__ __launch_bounds__(256)
void flash_mma()
{
    extern __shared__ __nv_bfloat16 smf[];
    __nv_bfloat16* Kh = smf;                      // [64][QPAD]
    __nv_bfloat16* Kl = smf + 64 * QPAD;
    __nv_bfloat16* Vh = smf + 2 * 64 * QPAD;      // [128][VPAD] d-major
    __nv_bfloat16* Vl = Vh + 128 * VPAD;
    __nv_bfloat16* Qh = smf;                      // staging alias [128][QPAD]
    __nv_bfloat16* Ql = smf + 128 * QPAD;

    const int tid  = threadIdx.x;
    const int warp = tid >> 5;
    const int lane = tid & 31;
    const int lrow = lane & 15;
    const int lcol = (lane >> 4) * 8;
    const int wq   = warp * 16;

    const int h  = blockIdx.y;
    const int hk = h >> 2;
    const int q0 = blockIdx.x * 128;

    // ---- stage Q tile, pull fragments into registers ----
    for (int idx = tid; idx < 128 * 16; idx += 256) {
        int r = idx >> 4;
        int c = (idx & 15) * 8;
        size_t g = (size_t)(q0 + r) * EMB + h * HD + c;
        *(uint4*)&Qh[r * QPAD + c] = *(const uint4*)(g_qh + g);
        *(uint4*)&Ql[r * QPAD + c] = *(const uint4*)(g_ql + g);
    }
    __syncthreads();

    uint32_t qfh[8][4];
    uint32_t qfl[8][4];
#pragma unroll
    for (int ks = 0; ks < 8; ks++) {
        ldsm_x4(qfh[ks], &Qh[(wq + lrow) * QPAD + ks * 16 + lcol]);
        ldsm_x4(qfl[ks], &Ql[(wq + lrow) * QPAD + ks * 16 + lcol]);
    }

    float o[16][4];
#pragma unroll
    for (int i = 0; i < 16; i++)
#pragma unroll
        for (int r = 0; r < 4; r++)
            o[i][r] = 0.0f;

    float m1 = -1e30f;
    float m2 = -1e30f;
    float l1 = 0.0f;
    float l2 = 0.0f;

    for (int kt = 0; kt < SEQ / 64; kt++) {
        __syncthreads();
        // load K tile (natural layout) and V tile (transposed to d-major)
        for (int idx = tid; idx < 64 * 16; idx += 256) {
            int r = idx >> 4;
            int c = (idx & 15) * 8;
            size_t g = (size_t)(kt * 64 + r) * KVD + hk * HD + c;
            *(uint4*)&Kh[r * QPAD + c] = *(const uint4*)(g_kh + g);
            *(uint4*)&Kl[r * QPAD + c] = *(const uint4*)(g_kl + g);
            uint4 vh4 = *(const uint4*)(g_vh + g);
            uint4 vl4 = *(const uint4*)(g_vl + g);
            const __nv_bfloat16* ph = (const __nv_bfloat16*)&vh4;
            const __nv_bfloat16* pl = (const __nv_bfloat16*)&vl4;
#pragma unroll
            for (int j = 0; j < 8; j++) {
                Vh[(c + j) * VPAD + r] = ph[j];
                Vl[(c + j) * VPAD + r] = pl[j];
            }
        }
        __syncthreads();

        // ---- S = Q K^T (3-pass split) ----
        float s[8][4];
#pragma unroll
        for (int t = 0; t < 8; t++)
#pragma unroll
            for (int r = 0; r < 4; r++)
                s[t][r] = 0.0f;

#pragma unroll
        for (int ks = 0; ks < 8; ks++) {
#pragma unroll
            for (int nsl = 0; nsl < 4; nsl++) {
                uint32_t kfh[4];
                uint32_t kfl[4];
                ldsm_x4(kfh, &Kh[(nsl * 16 + lrow) * QPAD + ks * 16 + lcol]);
                ldsm_x4(kfl, &Kl[(nsl * 16 + lrow) * QPAD + ks * 16 + lcol]);
#pragma unroll
                for (int ns = 0; ns < 2; ns++) {
                    float* sc = s[nsl * 2 + ns];
                    mma16816(sc, qfh[ks], kfh[ns], kfh[ns + 2]);
                    mma16816(sc, qfh[ks], kfl[ns], kfl[ns + 2]);
                    mma16816(sc, qfl[ks], kfh[ns], kfh[ns + 2]);
                }
            }
        }

        // ---- online base-2 softmax on fragments ----
        float mx1 = -1e30f;
        float mx2 = -1e30f;
#pragma unroll
        for (int t = 0; t < 8; t++) {
            mx1 = fmaxf(mx1, fmaxf(s[t][0], s[t][1]));
            mx2 = fmaxf(mx2, fmaxf(s[t][2], s[t][3]));
        }
        mx1 = fmaxf(mx1, __shfl_xor_sync(0xffffffffu, mx1, 1));
        mx1 = fmaxf(mx1, __shfl_xor_sync(0xffffffffu, mx1, 2));
        mx2 = fmaxf(mx2, __shfl_xor_sync(0xffffffffu, mx2, 1));
        mx2 = fmaxf(mx2, __shfl_xor_sync(0xffffffffu, mx2, 2));

        float newm1 = fmaxf(m1, mx1);
        float newm2 = fmaxf(m2, mx2);
        float corr1 = exp2f(m1 - newm1);
        float corr2 = exp2f(m2 - newm2);
        m1 = newm1;
        m2 = newm2;

        float ps1 = 0.0f;
        float ps2 = 0.0f;
#pragma unroll
        for (int t = 0; t < 8; t++) {
            s[t][0] = exp2f(s[t][0] - newm1);
            s[t][1] = exp2f(s[t][1] - newm1);
            s[t][2] = exp2f(s[t][2] - newm2);
            s[t][3] = exp2f(s[t][3] - newm2);
            ps1 += s[t][0] + s[t][1];
            ps2 += s[t][2] + s[t][3];
        }
        l1 = l1 * corr1 + ps1;
        l2 = l2 * corr2 + ps2;

#pragma unroll
        for (int i = 0; i < 16; i++) {
            o[i][0] *= corr1;
            o[i][1] *= corr1;
            o[i][2] *= corr2;
            o[i][3] *= corr2;
        }

        // ---- O += P V (3-pass split) ----
#pragma unroll
        for (int ks2 = 0; ks2 < 4; ks2++) {
            uint32_t pah[4];
            uint32_t pal[4];
            splitpack(s[2 * ks2][0],     s[2 * ks2][1],     pah[0], pal[0]);
            splitpack(s[2 * ks2][2],     s[2 * ks2][3],     pah[1], pal[1]);
            splitpack(s[2 * ks2 + 1][0], s[2 * ks2 + 1][1], pah[2], pal[2]);
            splitpack(s[2 * ks2 + 1][2], s[2 * ks2 + 1][3], pah[3], pal[3]);
#pragma unroll
            for (int dsl = 0; dsl < 8; dsl++) {
                uint32_t vfh[4];
                uint32_t vfl[4];
                ldsm_x4(vfh, &Vh[(dsl * 16 + lrow) * VPAD + ks2 * 16 + lcol]);
                ldsm_x4(vfl, &Vl[(dsl * 16 + lrow) * VPAD + ks2 * 16 + lcol]);
#pragma unroll
                for (int ns = 0; ns < 2; ns++) {
                    float* oc = o[dsl * 2 + ns];
                    mma16816(oc, pah, vfh[ns], vfh[ns + 2]);
                    mma16816(oc, pah, vfl[ns], vfl[ns + 2]);
                    mma16816(oc, pal, vfh[ns], vfh[ns + 2]);
                }
            }
        }
    }

    // ---- finalize: reduce l across quad, normalize, split-write ----
    l1 += __shfl_xor_sync(0xffffffffu, l1, 1);
    l1 += __shfl_xor_sync(0xffffffffu, l1, 2);
    l2 += __shfl_xor_sync(0xffffffffu, l2, 1);
    l2 += __shfl_xor_sync(0xffffffffu, l2, 2);
    float inv1 = 1.0f / l1;
    float inv2 = 1.0f / l2;

    const int row1 = q0 + wq + (lane >> 2);
    const int row2 = row1 + 8;
#pragma unroll
    for (int nt = 0; nt < 16; nt++) {
        int col = h * HD + nt * 8 + (lane & 3) * 2;
        uint32_t h0, l0, hh1, ll1;
        splitpack(o[nt][0] * inv1, o[nt][1] * inv1, h0, l0);
        splitpack(o[nt][2] * inv2, o[nt][3] * inv2, hh1, ll1);
        *(uint32_t*)(g_awh + (size_t)row1 * EMB + col) = h0;
        *(uint32_t*)(g_awl + (size_t)row1 * EMB + col) = l0;
        *(uint32_t*)(g_awh + (size_t)row2 * EMB + col) = hh1;
        *(uint32_t*)(g_awl + (size_t)row2 * EMB + col) = ll1;
    }
}

// ============================================================================
// host helpers + launch
// ============================================================================
static void run_cvt(const float* src, __nv_bfloat16* h, __nv_bfloat16* l, int n)
{
    int n4 = n / 4;
    int grid = (n4 + 255) / 256;
    cvt_split<<<grid, 256>>>((const float4*)src, (__nv_bfloat162*)h,
                             (__nv_bfloat162*)l, n4);
}

extern "C" void kernel_launch(void* const* d_in, const int* in_sizes, int n_in,
                              void* d_out, int out_size)
{
    const float* x   = (const float*)d_in[0];
    const float* q_w = (const float*)d_in[1];
    const float* q_b = (const float*)d_in[2];
    const float* k_w = (const float*)d_in[3];
    const float* k_b = (const float*)d_in[4];
    const float* v_w = (const float*)d_in[5];
    const float* v_b = (const float*)d_in[6];
    const float* o_w = (const float*)d_in[7];
    const float* o_b = (const float*)d_in[8];
    float* out = (float*)d_out;

    __nv_bfloat16* xh = 0;
    __nv_bfloat16* xl = 0;
    __nv_bfloat16* qwh = 0;
    __nv_bfloat16* qwl = 0;
    __nv_bfloat16* kwh = 0;
    __nv_bfloat16* kwl = 0;
    __nv_bfloat16* vwh = 0;
    __nv_bfloat16* vwl = 0;
    __nv_bfloat16* owh = 0;
    __nv_bfloat16* owl = 0;
    __nv_bfloat16* qh = 0;
    __nv_bfloat16* ql = 0;
    __nv_bfloat16* kh = 0;
    __nv_bfloat16* kl = 0;
    __nv_bfloat16* vh = 0;
    __nv_bfloat16* vl = 0;
    __nv_bfloat16* awh = 0;
    __nv_bfloat16* awl = 0;
    cudaGetSymbolAddress((void**)&xh,  g_xh);
    cudaGetSymbolAddress((void**)&xl,  g_xl);
    cudaGetSymbolAddress((void**)&qwh, g_qwh);
    cudaGetSymbolAddress((void**)&qwl, g_qwl);
    cudaGetSymbolAddress((void**)&kwh, g_kwh);
    cudaGetSymbolAddress((void**)&kwl, g_kwl);
    cudaGetSymbolAddress((void**)&vwh, g_vwh);
    cudaGetSymbolAddress((void**)&vwl, g_vwl);
    cudaGetSymbolAddress((void**)&owh, g_owh);
    cudaGetSymbolAddress((void**)&owl, g_owl);
    cudaGetSymbolAddress((void**)&qh,  g_qh);
    cudaGetSymbolAddress((void**)&ql,  g_ql);
    cudaGetSymbolAddress((void**)&kh,  g_kh);
    cudaGetSymbolAddress((void**)&kl,  g_kl);
    cudaGetSymbolAddress((void**)&vh,  g_vh);
    cudaGetSymbolAddress((void**)&vl,  g_vl);
    cudaGetSymbolAddress((void**)&awh, g_awh);
    cudaGetSymbolAddress((void**)&awl, g_awl);

    cudaFuncSetAttribute(flash_mma, cudaFuncAttributeMaxDynamicSharedMemorySize,
                         FL_SMEM_BYTES);

    dim3 blk(256);
    const float qscale = 0.08838834764831845f;   // 1/sqrt(128)

    run_cvt(x,   xh,  xl,  SEQ * EMB);
    run_cvt(q_w, qwh, qwl, EMB * EMB);
    run_cvt(k_w, kwh, kwl, KVD * EMB);
    run_cvt(v_w, vwh, vwl, KVD * EMB);
    run_cvt(o_w, owh, owl, EMB * EMB);

    // Q (pre-scaled, split output), K, V (split output)
    gemm_bf16split<<<dim3(EMB / 128, SEQ / 128), blk>>>(
        xh, xl, qwh, qwl, q_b, (float*)0, qh, ql, qscale, SEQ, EMB, EMB);
    gemm_bf16split<<<dim3(KVD / 128, SEQ / 128), blk>>>(
        xh, xl, kwh, kwl, k_b, (float*)0, kh, kl, 1.0f, SEQ, KVD, EMB);
    gemm_bf16split<<<dim3(KVD / 128, SEQ / 128), blk>>>(
        xh, xl, vwh, vwl, v_b, (float*)0, vh, vl, 1.0f, SEQ, KVD, EMB);

    // attention -> split output g_awh/g_awl
    flash_mma<<<dim3(SEQ / 128, NH), blk, FL_SMEM_BYTES>>>();

    // out = A @ o_w^T + o_b (fp32 output)
    gemm_bf16split<<<dim3(EMB / 128, SEQ / 128), blk>>>(
        awh, awl, owh, owl, o_b, out, (__nv_bfloat16*)0, (__nv_bfloat16*)0,
        1.0f, SEQ, EMB, EMB);
}

// round 5
// speedup vs baseline: 2.6228x; 1.1013x over previous
#include <cuda_runtime.h>
#include <cuda_bf16.h>
#include <cstdint>
#include <math.h>

#define SEQ   2048
#define EMB   4096
#define KVD   1024
#define NH    32
#define HD    128

// -------- scratch (device globals; no allocation allowed) --------
__device__ __nv_bfloat16 g_xh[SEQ * EMB];
__device__ __nv_bfloat16 g_xl[SEQ * EMB];
__device__ __nv_bfloat16 g_qwh[EMB * EMB];
__device__ __nv_bfloat16 g_qwl[EMB * EMB];
__device__ __nv_bfloat16 g_kwh[KVD * EMB];
__device__ __nv_bfloat16 g_kwl[KVD * EMB];
__device__ __nv_bfloat16 g_vwh[KVD * EMB];
__device__ __nv_bfloat16 g_vwl[KVD * EMB];
__device__ __nv_bfloat16 g_owh[EMB * EMB];
__device__ __nv_bfloat16 g_owl[EMB * EMB];

__device__ __nv_bfloat16 g_qh[SEQ * EMB];
__device__ __nv_bfloat16 g_ql[SEQ * EMB];
__device__ __nv_bfloat16 g_kh[SEQ * KVD];
__device__ __nv_bfloat16 g_kl[SEQ * KVD];
__device__ __nv_bfloat16 g_vh[SEQ * KVD];
__device__ __nv_bfloat16 g_vl[SEQ * KVD];
__device__ __nv_bfloat16 g_awh[SEQ * EMB];
__device__ __nv_bfloat16 g_awl[SEQ * EMB];

// ============================================================================
// helpers
// ============================================================================
__device__ __forceinline__ uint32_t smaddr(const void* p)
{
    return (uint32_t)__cvta_generic_to_shared(p);
}

__device__ __forceinline__ void cp16(uint32_t dst, const void* src)
{
    asm volatile("cp.async.cg.shared.global [%0], [%1], 16;"
                 :: "r"(dst), "l"(src));
}

__device__ __forceinline__ void cp_commit()
{
    asm volatile("cp.async.commit_group;");
}

template <int N>
__device__ __forceinline__ void cp_wait()
{
    asm volatile("cp.async.wait_group %0;" :: "n"(N));
}

__device__ __forceinline__ void ldsm_x4(uint32_t* r, const __nv_bfloat16* p)
{
    uint32_t addr = smaddr(p);
    asm volatile("ldmatrix.sync.aligned.m8n8.x4.shared.b16 {%0,%1,%2,%3}, [%4];"
                 : "=r"(r[0]), "=r"(r[1]), "=r"(r[2]), "=r"(r[3])
                 : "r"(addr));
}

__device__ __forceinline__ void ldsm_x4t(uint32_t* r, const __nv_bfloat16* p)
{
    uint32_t addr = smaddr(p);
    asm volatile("ldmatrix.sync.aligned.m8n8.x4.trans.shared.b16 {%0,%1,%2,%3}, [%4];"
                 : "=r"(r[0]), "=r"(r[1]), "=r"(r[2]), "=r"(r[3])
                 : "r"(addr));
}

__device__ __forceinline__ void mma16816(float* c, const uint32_t* a,
                                         uint32_t b0, uint32_t b1)
{
    asm volatile(
        "mma.sync.aligned.m16n8k16.row.col.f32.bf16.bf16.f32 "
        "{%0,%1,%2,%3}, {%4,%5,%6,%7}, {%8,%9}, {%0,%1,%2,%3};"
        : "+f"(c[0]), "+f"(c[1]), "+f"(c[2]), "+f"(c[3])
        : "r"(a[0]), "r"(a[1]), "r"(a[2]), "r"(a[3]), "r"(b0), "r"(b1));
}

__device__ __forceinline__ void splitpack(float a, float b,
                                          uint32_t& hi, uint32_t& lo)
{
    __nv_bfloat16 ha = __float2bfloat16(a);
    __nv_bfloat16 hb = __float2bfloat16(b);
    __nv_bfloat16 la = __float2bfloat16(a - __bfloat162float(ha));
    __nv_bfloat16 lb = __float2bfloat16(b - __bfloat162float(hb));
    __nv_bfloat162 th = __halves2bfloat162(ha, hb);
    __nv_bfloat162 tl = __halves2bfloat162(la, lb);
    hi = *(uint32_t*)&th;
    lo = *(uint32_t*)&tl;
}

// ============================================================================
// fp32 -> (bf16 hi, bf16 lo) split conversion
// ============================================================================
__global__ __launch_bounds__(256)
void cvt_split(const float4* __restrict__ in,
               __nv_bfloat162* __restrict__ hi,
               __nv_bfloat162* __restrict__ lo, int n4)
{
    int i = blockIdx.x * blockDim.x + threadIdx.x;
    if (i >= n4) return;
    float4 v = in[i];
    uint32_t h0, l0, h1, l1;
    splitpack(v.x, v.y, h0, l0);
    splitpack(v.z, v.w, h1, l1);
    *((uint32_t*)hi + i * 2 + 0) = h0;
    *((uint32_t*)hi + i * 2 + 1) = h1;
    *((uint32_t*)lo + i * 2 + 0) = l0;
    *((uint32_t*)lo + i * 2 + 1) = l1;
}

// ============================================================================
// Split-bf16 tensor-core GEMM (NT), 3-stage cp.async pipeline.
// C = A @ B^T + bias. If Ch != null: bf16-split output (scaled by oscale).
// Block 128x128x32, 256 threads, warp tile 64x32.
// ============================================================================
#define BKP 40
#define GSTG (4 * 128 * BKP)          // halves per stage (4 arrays)
#define GEMM_SMEM_BYTES (3 * GSTG * 2)  // 122880

__global__ __launch_bounds__(256)
void gemm_bf16split(const __nv_bfloat16* __restrict__ Ahg,
                    const __nv_bfloat16* __restrict__ Alg,
                    const __nv_bfloat16* __restrict__ Bhg,
                    const __nv_bfloat16* __restrict__ Blg,
                    const float* __restrict__ bias,
                    float* __restrict__ C,
                    __nv_bfloat16* __restrict__ Ch,
                    __nv_bfloat16* __restrict__ Cl,
                    float oscale,
                    int M, int N, int K)
{
    extern __shared__ __nv_bfloat16 smg[];

    const int tid  = threadIdx.x;
    const int warp = tid >> 5;
    const int lane = tid & 31;
    const int wm = (warp >> 2) * 64;
    const int wn = (warp & 3) * 32;
    const int row0 = blockIdx.y * 128;
    const int col0 = blockIdx.x * 128;

    const int lr = tid >> 1;
    const int lc = (tid & 1) * 16;

    const __nv_bfloat16* pAh = Ahg + (size_t)(row0 + lr) * K + lc;
    const __nv_bfloat16* pAl = Alg + (size_t)(row0 + lr) * K + lc;
    const __nv_bfloat16* pBh = Bhg + (size_t)(col0 + lr) * K + lc;
    const __nv_bfloat16* pBl = Blg + (size_t)(col0 + lr) * K + lc;

    // per-thread smem dst offset within a stage (array-relative, halves)
    const int dstoff = lr * BKP + lc;

    float acc[4][4][4];
#pragma unroll
    for (int i = 0; i < 4; i++)
#pragma unroll
        for (int j = 0; j < 4; j++)
#pragma unroll
            for (int r = 0; r < 4; r++)
                acc[i][j][r] = 0.0f;

    const int lrow = lane & 15;
    const int lcol = (lane >> 4) * 8;

    // prefetch helper (8 x 16B per thread per stage)
#define GPREFETCH(st, k0)                                                     \
    do {                                                                      \
        __nv_bfloat16* sb = smg + (st) * GSTG + dstoff;                       \
        uint32_t d0 = smaddr(sb);                                             \
        cp16(d0,                         pAh + (k0));                         \
        cp16(d0 + 16,                    pAh + (k0) + 8);                     \
        cp16(d0 + 128 * BKP * 2,         pAl + (k0));                         \
        cp16(d0 + 128 * BKP * 2 + 16,    pAl + (k0) + 8);                     \
        cp16(d0 + 2 * 128 * BKP * 2,     pBh + (k0));                         \
        cp16(d0 + 2 * 128 * BKP * 2 + 16, pBh + (k0) + 8);                    \
        cp16(d0 + 3 * 128 * BKP * 2,     pBl + (k0));                         \
        cp16(d0 + 3 * 128 * BKP * 2 + 16, pBl + (k0) + 8);                    \
    } while (0)

    GPREFETCH(0, 0);
    cp_commit();
    GPREFETCH(1, 32);
    cp_commit();

    int st = 0;
    for (int k0 = 0; k0 < K; k0 += 32) {
        if (k0 + 32 < K) cp_wait<1>(); else cp_wait<0>();
        __syncthreads();
        if (k0 + 64 < K) {
            int st2 = st + 2;
            if (st2 >= 3) st2 -= 3;
            GPREFETCH(st2, k0 + 64);
            cp_commit();
        }

        const __nv_bfloat16* Ah = smg + st * GSTG;
        const __nv_bfloat16* Al = Ah + 128 * BKP;
        const __nv_bfloat16* Bh = Al + 128 * BKP;
        const __nv_bfloat16* Bl = Bh + 128 * BKP;

#pragma unroll
        for (int ks = 0; ks < 2; ks++) {
            const int kk = ks * 16;
            uint32_t ah[4][4];
            uint32_t al[4][4];
            uint32_t bh[2][4];
            uint32_t bl[2][4];
#pragma unroll
            for (int mi = 0; mi < 4; mi++) {
                ldsm_x4(ah[mi], Ah + (wm + mi * 16 + lrow) * BKP + kk + lcol);
                ldsm_x4(al[mi], Al + (wm + mi * 16 + lrow) * BKP + kk + lcol);
            }
#pragma unroll
            for (int nb = 0; nb < 2; nb++) {
                ldsm_x4(bh[nb], Bh + (wn + nb * 16 + lrow) * BKP + kk + lcol);
                ldsm_x4(bl[nb], Bl + (wn + nb * 16 + lrow) * BKP + kk + lcol);
            }
#pragma unroll
            for (int mi = 0; mi < 4; mi++) {
#pragma unroll
                for (int nj = 0; nj < 4; nj++) {
                    const int nb = nj >> 1;
                    const int ns = nj & 1;
                    mma16816(acc[mi][nj], ah[mi], bh[nb][ns], bh[nb][ns + 2]);
                    mma16816(acc[mi][nj], ah[mi], bl[nb][ns], bl[nb][ns + 2]);
                    mma16816(acc[mi][nj], al[mi], bh[nb][ns], bh[nb][ns + 2]);
                }
            }
        }
        st = st + 1;
        if (st == 3) st = 0;
    }

#pragma unroll
    for (int mi = 0; mi < 4; mi++) {
#pragma unroll
        for (int nj = 0; nj < 4; nj++) {
            int row = row0 + wm + mi * 16 + (lane >> 2);
            int col = col0 + wn + nj * 8 + (lane & 3) * 2;
            float b0 = bias[col];
            float b1 = bias[col + 1];
            float v00 = acc[mi][nj][0] + b0;
            float v01 = acc[mi][nj][1] + b1;
            float v10 = acc[mi][nj][2] + b0;
            float v11 = acc[mi][nj][3] + b1;
            if (Ch) {
                v00 *= oscale; v01 *= oscale; v10 *= oscale; v11 *= oscale;
                uint32_t h0, l0, h1, l1;
                splitpack(v00, v01, h0, l0);
                splitpack(v10, v11, h1, l1);
                *(uint32_t*)(Ch + (size_t)row * N + col) = h0;
                *(uint32_t*)(Cl + (size_t)row * N + col) = l0;
                *(uint32_t*)(Ch + (size_t)(row + 8) * N + col) = h1;
                *(uint32_t*)(Cl + (size_t)(row + 8) * N + col) = l1;
            } else {
                float2 r0;
                float2 r1;
                r0.x = v00; r0.y = v01;
                r1.x = v10; r1.y = v11;
                *(float2*)(C + (size_t)row * N + col) = r0;
                *(float2*)(C + (size_t)(row + 8) * N + col) = r1;
            }
        }
    }
}

// ============================================================================
// Tensor-core flash attention, split-bf16, 2-stage cp.async KV pipeline.
// V consumed via ldmatrix.trans (natural [kv][d] layout, no transpose).
// Grid (SEQ/128, NH), 256 threads. Warp w owns query rows w*16..w*16+15.
// ============================================================================
#define KVP 136
#define FSTG (4 * 64 * KVP)               // halves per KV stage
#define FL_SMEM_BYTES (2 * FSTG * 2)      // 139264

__global__ __launch_bounds__(256)
void flash_mma()
{
    extern __shared__ __nv_bfloat16 smf[];

    const int tid  = threadIdx.x;
    const int warp = tid >> 5;
    const int lane = tid & 31;
    const int lrow = lane & 15;
    const int lcol = (lane >> 4) * 8;
    const int wq   = warp * 16;

    const int h  = blockIdx.y;
    const int hk = h >> 2;
    const int q0 = blockIdx.x * 128;

    // ---- stage Q (aliases KV stage region), pull fragments ----
    {
        __nv_bfloat16* Qh = smf;
        __nv_bfloat16* Ql = smf + 128 * KVP;
        for (int idx = tid; idx < 128 * 16; idx += 256) {
            int r = idx >> 4;
            int c = (idx & 15) * 8;
            size_t g = (size_t)(q0 + r) * EMB + h * HD + c;
            *(uint4*)&Qh[r * KVP + c] = *(const uint4*)(g_qh + g);
            *(uint4*)&Ql[r * KVP + c] = *(const uint4*)(g_ql + g);
        }
    }
    __syncthreads();

    uint32_t qfh[8][4];
    uint32_t qfl[8][4];
    {
        const __nv_bfloat16* Qh = smf;
        const __nv_bfloat16* Ql = smf + 128 * KVP;
#pragma unroll
        for (int ks = 0; ks < 8; ks++) {
            ldsm_x4(qfh[ks], Qh + (wq + lrow) * KVP + ks * 16 + lcol);
            ldsm_x4(qfl[ks], Ql + (wq + lrow) * KVP + ks * 16 + lcol);
        }
    }
    __syncthreads();   // Q region free for KV prefetch

    // prefetch helper: 4 arrays (Kh,Kl,Vh,Vl), each 64x128 halves
#define FPREFETCH(st, kt)                                                     \
    do {                                                                      \
        __nv_bfloat16* sb = smf + (st) * FSTG;                                \
        _Pragma("unroll")                                                     \
        for (int it = 0; it < 4; it++) {                                      \
            int idx = tid + it * 256;                                         \
            int r = idx >> 4;                                                 \
            int c = (idx & 15) * 8;                                           \
            size_t g = (size_t)((kt) * 64 + r) * KVD + hk * HD + c;           \
            uint32_t d0 = smaddr(sb + r * KVP + c);                           \
            cp16(d0,                  g_kh + g);                              \
            cp16(d0 + 64 * KVP * 2,   g_kl + g);                              \
            cp16(d0 + 2 * 64 * KVP * 2, g_vh + g);                            \
            cp16(d0 + 3 * 64 * KVP * 2, g_vl + g);                            \
        }                                                                     \
    } while (0)

    FPREFETCH(0, 0);
    cp_commit();

    float o[16][4];
#pragma unroll
    for (int i = 0; i < 16; i++)
#pragma unroll
        for (int r = 0; r < 4; r++)
            o[i][r] = 0.0f;

    float m1 = -1e30f;
    float m2 = -1e30f;
    float l1 = 0.0f;
    float l2 = 0.0f;

    int st = 0;
    for (int kt = 0; kt < SEQ / 64; kt++) {
        cp_wait<0>();
        __syncthreads();
        if (kt + 1 < SEQ / 64) {
            FPREFETCH(st ^ 1, kt + 1);
            cp_commit();
        }

        const __nv_bfloat16* Kh = smf + st * FSTG;
        const __nv_bfloat16* Kl = Kh + 64 * KVP;
        const __nv_bfloat16* Vh = Kl + 64 * KVP;
        const __nv_bfloat16* Vl = Vh + 64 * KVP;

        // ---- S = Q K^T (3-pass split) ----
        float s[8][4];
#pragma unroll
        for (int t = 0; t < 8; t++)
#pragma unroll
            for (int r = 0; r < 4; r++)
                s[t][r] = 0.0f;

#pragma unroll
        for (int ks = 0; ks < 8; ks++) {
#pragma unroll
            for (int nsl = 0; nsl < 4; nsl++) {
                uint32_t kfh[4];
                uint32_t kfl[4];
                ldsm_x4(kfh, Kh + (nsl * 16 + lrow) * KVP + ks * 16 + lcol);
                ldsm_x4(kfl, Kl + (nsl * 16 + lrow) * KVP + ks * 16 + lcol);
#pragma unroll
                for (int ns = 0; ns < 2; ns++) {
                    float* sc = s[nsl * 2 + ns];
                    mma16816(sc, qfh[ks], kfh[ns], kfh[ns + 2]);
                    mma16816(sc, qfh[ks], kfl[ns], kfl[ns + 2]);
                    mma16816(sc, qfl[ks], kfh[ns], kfh[ns + 2]);
                }
            }
        }

        // ---- online base-2 softmax ----
        float mx1 = -1e30f;
        float mx2 = -1e30f;
#pragma unroll
        for (int t = 0; t < 8; t++) {
            mx1 = fmaxf(mx1, fmaxf(s[t][0], s[t][1]));
            mx2 = fmaxf(mx2, fmaxf(s[t][2], s[t][3]));
        }
        mx1 = fmaxf(mx1, __shfl_xor_sync(0xffffffffu, mx1, 1));
        mx1 = fmaxf(mx1, __shfl_xor_sync(0xffffffffu, mx1, 2));
        mx2 = fmaxf(mx2, __shfl_xor_sync(0xffffffffu, mx2, 1));
        mx2 = fmaxf(mx2, __shfl_xor_sync(0xffffffffu, mx2, 2));

        float newm1 = fmaxf(m1, mx1);
        float newm2 = fmaxf(m2, mx2);
        float corr1 = exp2f(m1 - newm1);
        float corr2 = exp2f(m2 - newm2);
        m1 = newm1;
        m2 = newm2;

        float ps1 = 0.0f;
        float ps2 = 0.0f;
#pragma unroll
        for (int t = 0; t < 8; t++) {
            s[t][0] = exp2f(s[t][0] - newm1);
            s[t][1] = exp2f(s[t][1] - newm1);
            s[t][2] = exp2f(s[t][2] - newm2);
            s[t][3] = exp2f(s[t][3] - newm2);
            ps1 += s[t][0] + s[t][1];
            ps2 += s[t][2] + s[t][3];
        }
        l1 = l1 * corr1 + ps1;
        l2 = l2 * corr2 + ps2;

#pragma unroll
        for (int i = 0; i < 16; i++) {
            o[i][0] *= corr1;
            o[i][1] *= corr1;
            o[i][2] *= corr2;
            o[i][3] *= corr2;
        }

        // ---- O += P V (3-pass split, V via ldmatrix.trans) ----
#pragma unroll
        for (int ks2 = 0; ks2 < 4; ks2++) {
            uint32_t pah[4];
            uint32_t pal[4];
            splitpack(s[2 * ks2][0],     s[2 * ks2][1],     pah[0], pal[0]);
            splitpack(s[2 * ks2][2],     s[2 * ks2][3],     pah[1], pal[1]);
            splitpack(s[2 * ks2 + 1][0], s[2 * ks2 + 1][1], pah[2], pal[2]);
            splitpack(s[2 * ks2 + 1][2], s[2 * ks2 + 1][3], pah[3], pal[3]);
#pragma unroll
            for (int dsl = 0; dsl < 8; dsl++) {
                uint32_t vfh[4];
                uint32_t vfl[4];
                ldsm_x4t(vfh, Vh + (ks2 * 16 + lrow) * KVP + dsl * 16 + lcol);
                ldsm_x4t(vfl, Vl + (ks2 * 16 + lrow) * KVP + dsl * 16 + lcol);
                float* oc0 = o[dsl * 2];
                float* oc1 = o[dsl * 2 + 1];
                mma16816(oc0, pah, vfh[0], vfh[1]);
                mma16816(oc0, pah, vfl[0], vfl[1]);
                mma16816(oc0, pal, vfh[0], vfh[1]);
                mma16816(oc1, pah, vfh[2], vfh[3]);
                mma16816(oc1, pah, vfl[2], vfl[3]);
                mma16816(oc1, pal, vfh[2], vfh[3]);
            }
        }
        st ^= 1;
    }

    // ---- finalize ----
    l1 += __shfl_xor_sync(0xffffffffu, l1, 1);
    l1 += __shfl_xor_sync(0xffffffffu, l1, 2);
    l2 += __shfl_xor_sync(0xffffffffu, l2, 1);
    l2 += __shfl_xor_sync(0xffffffffu, l2, 2);
    float inv1 = 1.0f / l1;
    float inv2 = 1.0f / l2;

    const int row1 = q0 + wq + (lane >> 2);
    const int row2 = row1 + 8;
#pragma unroll
    for (int nt = 0; nt < 16; nt++) {
        int col = h * HD + nt * 8 + (lane & 3) * 2;
        uint32_t h0, l0, hh1, ll1;
        splitpack(o[nt][0] * inv1, o[nt][1] * inv1, h0, l0);
        splitpack(o[nt][2] * inv2, o[nt][3] * inv2, hh1, ll1);
        *(uint32_t*)(g_awh + (size_t)row1 * EMB + col) = h0;
        *(uint32_t*)(g_awl + (size_t)row1 * EMB + col) = l0;
        *(uint32_t*)(g_awh + (size_t)row2 * EMB + col) = hh1;
        *(uint32_t*)(g_awl + (size_t)row2 * EMB + col) = ll1;
    }
}

// ============================================================================
// host helpers + launch
// ============================================================================
static void run_cvt(const float* src, __nv_bfloat16* h, __nv_bfloat16* l, int n)
{
    int n4 = n / 4;
    int grid = (n4 + 255) / 256;
    cvt_split<<<grid, 256>>>((const float4*)src, (__nv_bfloat162*)h,
                             (__nv_bfloat162*)l, n4);
}

extern "C" void kernel_launch(void* const* d_in, const int* in_sizes, int n_in,
                              void* d_out, int out_size)
{
    const float* x   = (const float*)d_in[0];
    const float* q_w = (const float*)d_in[1];
    const float* q_b = (const float*)d_in[2];
    const float* k_w = (const float*)d_in[3];
    const float* k_b = (const float*)d_in[4];
    const float* v_w = (const float*)d_in[5];
    const float* v_b = (const float*)d_in[6];
    const float* o_w = (const float*)d_in[7];
    const float* o_b = (const float*)d_in[8];
    float* out = (float*)d_out;

    __nv_bfloat16* xh = 0;
    __nv_bfloat16* xl = 0;
    __nv_bfloat16* qwh = 0;
    __nv_bfloat16* qwl = 0;
    __nv_bfloat16* kwh = 0;
    __nv_bfloat16* kwl = 0;
    __nv_bfloat16* vwh = 0;
    __nv_bfloat16* vwl = 0;
    __nv_bfloat16* owh = 0;
    __nv_bfloat16* owl = 0;
    __nv_bfloat16* qh = 0;
    __nv_bfloat16* ql = 0;
    __nv_bfloat16* kh = 0;
    __nv_bfloat16* kl = 0;
    __nv_bfloat16* vh = 0;
    __nv_bfloat16* vl = 0;
    __nv_bfloat16* awh = 0;
    __nv_bfloat16* awl = 0;
    cudaGetSymbolAddress((void**)&xh,  g_xh);
    cudaGetSymbolAddress((void**)&xl,  g_xl);
    cudaGetSymbolAddress((void**)&qwh, g_qwh);
    cudaGetSymbolAddress((void**)&qwl, g_qwl);
    cudaGetSymbolAddress((void**)&kwh, g_kwh);
    cudaGetSymbolAddress((void**)&kwl, g_kwl);
    cudaGetSymbolAddress((void**)&vwh, g_vwh);
    cudaGetSymbolAddress((void**)&vwl, g_vwl);
    cudaGetSymbolAddress((void**)&owh, g_owh);
    cudaGetSymbolAddress((void**)&owl, g_owl);
    cudaGetSymbolAddress((void**)&qh,  g_qh);
    cudaGetSymbolAddress((void**)&ql,  g_ql);
    cudaGetSymbolAddress((void**)&kh,  g_kh);
    cudaGetSymbolAddress((void**)&kl,  g_kl);
    cudaGetSymbolAddress((void**)&vh,  g_vh);
    cudaGetSymbolAddress((void**)&vl,  g_vl);
    cudaGetSymbolAddress((void**)&awh, g_awh);
    cudaGetSymbolAddress((void**)&awl, g_awl);

    cudaFuncSetAttribute(gemm_bf16split,
                         cudaFuncAttributeMaxDynamicSharedMemorySize,
                         GEMM_SMEM_BYTES);
    cudaFuncSetAttribute(flash_mma,
                         cudaFuncAttributeMaxDynamicSharedMemorySize,
                         FL_SMEM_BYTES);

    dim3 blk(256);
    const float qscale = 0.08838834764831845f;   // 1/sqrt(128)

    run_cvt(x,   xh,  xl,  SEQ * EMB);
    run_cvt(q_w, qwh, qwl, EMB * EMB);
    run_cvt(k_w, kwh, kwl, KVD * EMB);
    run_cvt(v_w, vwh, vwl, KVD * EMB);
    run_cvt(o_w, owh, owl, EMB * EMB);

    gemm_bf16split<<<dim3(EMB / 128, SEQ / 128), blk, GEMM_SMEM_BYTES>>>(
        xh, xl, qwh, qwl, q_b, (float*)0, qh, ql, qscale, SEQ, EMB, EMB);
    gemm_bf16split<<<dim3(KVD / 128, SEQ / 128), blk, GEMM_SMEM_BYTES>>>(
        xh, xl, kwh, kwl, k_b, (float*)0, kh, kl, 1.0f, SEQ, KVD, EMB);
    gemm_bf16split<<<dim3(KVD / 128, SEQ / 128), blk, GEMM_SMEM_BYTES>>>(
        xh, xl, vwh, vwl, v_b, (float*)0, vh, vl, 1.0f, SEQ, KVD, EMB);

    flash_mma<<<dim3(SEQ / 128, NH), blk, FL_SMEM_BYTES>>>();

    gemm_bf16split<<<dim3(EMB / 128, SEQ / 128), blk, GEMM_SMEM_BYTES>>>(
        awh, awl, owh, owl, o_b, out, (__nv_bfloat16*)0, (__nv_bfloat16*)0,
        1.0f, SEQ, EMB, EMB);
}

// round 7
// speedup vs baseline: 2.6471x; 1.0093x over previous
#include <cuda_runtime.h>
#include <cuda_bf16.h>
#include <cstdint>
#include <math.h>

#define SEQ   2048
#define EMB   4096
#define KVD   1024
#define NH    32
#define HD    128

// -------- scratch (device globals; no allocation allowed) --------
__device__ __nv_bfloat16 g_xh[SEQ * EMB];
__device__ __nv_bfloat16 g_xl[SEQ * EMB];
__device__ __nv_bfloat16 g_qwh[EMB * EMB];
__device__ __nv_bfloat16 g_qwl[EMB * EMB];
__device__ __nv_bfloat16 g_kwh[KVD * EMB];
__device__ __nv_bfloat16 g_kwl[KVD * EMB];
__device__ __nv_bfloat16 g_vwh[KVD * EMB];
__device__ __nv_bfloat16 g_vwl[KVD * EMB];
__device__ __nv_bfloat16 g_owh[EMB * EMB];
__device__ __nv_bfloat16 g_owl[EMB * EMB];

__device__ __nv_bfloat16 g_qh[SEQ * EMB];
__device__ __nv_bfloat16 g_ql[SEQ * EMB];
__device__ __nv_bfloat16 g_kh[SEQ * KVD];
__device__ __nv_bfloat16 g_kl[SEQ * KVD];
__device__ __nv_bfloat16 g_vh[SEQ * KVD];
__device__ __nv_bfloat16 g_vl[SEQ * KVD];
__device__ __nv_bfloat16 g_awh[SEQ * EMB];
__device__ __nv_bfloat16 g_awl[SEQ * EMB];

// split-KV attention partials
__device__ float g_po[2 * SEQ * EMB];     // unnormalized O halves (fp32)
__device__ float g_pm[2 * NH * SEQ];      // per-row max
__device__ float g_pl[2 * NH * SEQ];      // per-row sum

// ============================================================================
// helpers
// ============================================================================
__device__ __forceinline__ uint32_t smaddr(const void* p)
{
    return (uint32_t)__cvta_generic_to_shared(p);
}

__device__ __forceinline__ void cp16(uint32_t dst, const void* src)
{
    asm volatile("cp.async.cg.shared.global [%0], [%1], 16;"
                 :: "r"(dst), "l"(src));
}

__device__ __forceinline__ void cp_commit()
{
    asm volatile("cp.async.commit_group;");
}

template <int N>
__device__ __forceinline__ void cp_wait()
{
    asm volatile("cp.async.wait_group %0;" :: "n"(N));
}

__device__ __forceinline__ void ldsm_x4(uint32_t* r, const __nv_bfloat16* p)
{
    uint32_t addr = smaddr(p);
    asm volatile("ldmatrix.sync.aligned.m8n8.x4.shared.b16 {%0,%1,%2,%3}, [%4];"
                 : "=r"(r[0]), "=r"(r[1]), "=r"(r[2]), "=r"(r[3])
                 : "r"(addr));
}

__device__ __forceinline__ void ldsm_x4t(uint32_t* r, const __nv_bfloat16* p)
{
    uint32_t addr = smaddr(p);
    asm volatile("ldmatrix.sync.aligned.m8n8.x4.trans.shared.b16 {%0,%1,%2,%3}, [%4];"
                 : "=r"(r[0]), "=r"(r[1]), "=r"(r[2]), "=r"(r[3])
                 : "r"(addr));
}

__device__ __forceinline__ void mma16816(float* c, const uint32_t* a,
                                         uint32_t b0, uint32_t b1)
{
    asm volatile(
        "mma.sync.aligned.m16n8k16.row.col.f32.bf16.bf16.f32 "
        "{%0,%1,%2,%3}, {%4,%5,%6,%7}, {%8,%9}, {%0,%1,%2,%3};"
        : "+f"(c[0]), "+f"(c[1]), "+f"(c[2]), "+f"(c[3])
        : "r"(a[0]), "r"(a[1]), "r"(a[2]), "r"(a[3]), "r"(b0), "r"(b1));
}

__device__ __forceinline__ void splitpack(float a, float b,
                                          uint32_t& hi, uint32_t& lo)
{
    __nv_bfloat16 ha = __float2bfloat16(a);
    __nv_bfloat16 hb = __float2bfloat16(b);
    __nv_bfloat16 la = __float2bfloat16(a - __bfloat162float(ha));
    __nv_bfloat16 lb = __float2bfloat16(b - __bfloat162float(hb));
    __nv_bfloat162 th = __halves2bfloat162(ha, hb);
    __nv_bfloat162 tl = __halves2bfloat162(la, lb);
    hi = *(uint32_t*)&th;
    lo = *(uint32_t*)&tl;
}

__device__ __forceinline__ void split_store(const float4* in,
                                            uint32_t* hi, uint32_t* lo, int i)
{
    float4 v = in[i];
    uint32_t h0, l0, h1, l1;
    splitpack(v.x, v.y, h0, l0);
    splitpack(v.z, v.w, h1, l1);
    hi[i * 2 + 0] = h0;
    hi[i * 2 + 1] = h1;
    lo[i * 2 + 0] = l0;
    lo[i * 2 + 1] = l1;
}

// ============================================================================
// merged fp32 -> split conversion for all 5 input tensors
// cumulative float4 ranges: x 2097152 | qw 4194304 | kw 1048576 | vw 1048576
// | ow 4194304   (total 12582912)
// ============================================================================
__global__ __launch_bounds__(256)
void cvt_all(const float4* __restrict__ x,  const float4* __restrict__ qw,
             const float4* __restrict__ kw, const float4* __restrict__ vw,
             const float4* __restrict__ ow,
             uint32_t* xh, uint32_t* xl, uint32_t* qwh, uint32_t* qwl,
             uint32_t* kwh, uint32_t* kwl, uint32_t* vwh, uint32_t* vwl,
             uint32_t* owh, uint32_t* owl)
{
    int i = blockIdx.x * blockDim.x + threadIdx.x;
    if (i < 2097152) {
        split_store(x, xh, xl, i);
    } else if (i < 6291456) {
        split_store(qw, qwh, qwl, i - 2097152);
    } else if (i < 7340032) {
        split_store(kw, kwh, kwl, i - 6291456);
    } else if (i < 8388608) {
        split_store(vw, vwh, vwl, i - 7340032);
    } else if (i < 12582912) {
        split_store(ow, owh, owl, i - 8388608);
    }
}

// ============================================================================
// Split-bf16 tensor-core GEMM body (NT), 3-stage cp.async pipeline.
// C = A @ B^T + bias; if Ch != null writes bf16 split of (acc+bias)*oscale.
// Block tile 128x128x32, 256 threads, warp tile 64x32.
// ============================================================================
#define BKP 40
#define GSTG (4 * 128 * BKP)
#define GEMM_SMEM_BYTES (3 * GSTG * 2)   // 122880

__device__ __forceinline__
void gemm_body(const __nv_bfloat16* __restrict__ Ahg,
               const __nv_bfloat16* __restrict__ Alg,
               const __nv_bfloat16* __restrict__ Bhg,
               const __nv_bfloat16* __restrict__ Blg,
               const float* __restrict__ bias,
               float* __restrict__ C,
               __nv_bfloat16* __restrict__ Ch,
               __nv_bfloat16* __restrict__ Cl,
               float oscale, int N, int K, int row0, int col0)
{
    extern __shared__ __nv_bfloat16 smg[];

    const int tid  = threadIdx.x;
    const int warp = tid >> 5;
    const int lane = tid & 31;
    const int wm = (warp >> 2) * 64;
    const int wn = (warp & 3) * 32;

    const int lr = tid >> 1;
    const int lc = (tid & 1) * 16;

    const __nv_bfloat16* pAh = Ahg + (size_t)(row0 + lr) * K + lc;
    const __nv_bfloat16* pAl = Alg + (size_t)(row0 + lr) * K + lc;
    const __nv_bfloat16* pBh = Bhg + (size_t)(col0 + lr) * K + lc;
    const __nv_bfloat16* pBl = Blg + (size_t)(col0 + lr) * K + lc;

    const int dstoff = lr * BKP + lc;

    float acc[4][4][4];
#pragma unroll
    for (int i = 0; i < 4; i++)
#pragma unroll
        for (int j = 0; j < 4; j++)
#pragma unroll
            for (int r = 0; r < 4; r++)
                acc[i][j][r] = 0.0f;

    const int lrow = lane & 15;
    const int lcol = (lane >> 4) * 8;

#define GPREFETCH(st, k0)                                                     \
    do {                                                                      \
        __nv_bfloat16* sb = smg + (st) * GSTG + dstoff;                       \
        uint32_t d0 = smaddr(sb);                                             \
        cp16(d0,                          pAh + (k0));                        \
        cp16(d0 + 16,                     pAh + (k0) + 8);                    \
        cp16(d0 + 128 * BKP * 2,          pAl + (k0));                        \
        cp16(d0 + 128 * BKP * 2 + 16,     pAl + (k0) + 8);                    \
        cp16(d0 + 2 * 128 * BKP * 2,      pBh + (k0));                        \
        cp16(d0 + 2 * 128 * BKP * 2 + 16, pBh + (k0) + 8);                    \
        cp16(d0 + 3 * 128 * BKP * 2,      pBl + (k0));                        \
        cp16(d0 + 3 * 128 * BKP * 2 + 16, pBl + (k0) + 8);                    \
    } while (0)

    GPREFETCH(0, 0);
    cp_commit();
    GPREFETCH(1, 32);
    cp_commit();

    int st = 0;
    for (int k0 = 0; k0 < K; k0 += 32) {
        if (k0 + 32 < K) cp_wait<1>(); else cp_wait<0>();
        __syncthreads();
        if (k0 + 64 < K) {
            int st2 = st + 2;
            if (st2 >= 3) st2 -= 3;
            GPREFETCH(st2, k0 + 64);
            cp_commit();
        }

        const __nv_bfloat16* Ah = smg + st * GSTG;
        const __nv_bfloat16* Al = Ah + 128 * BKP;
        const __nv_bfloat16* Bh = Al + 128 * BKP;
        const __nv_bfloat16* Bl = Bh + 128 * BKP;

#pragma unroll
        for (int ks = 0; ks < 2; ks++) {
            const int kk = ks * 16;
            uint32_t ah[4][4];
            uint32_t al[4][4];
            uint32_t bh[2][4];
            uint32_t bl[2][4];
#pragma unroll
            for (int mi = 0; mi < 4; mi++) {
                ldsm_x4(ah[mi], Ah + (wm + mi * 16 + lrow) * BKP + kk + lcol);
                ldsm_x4(al[mi], Al + (wm + mi * 16 + lrow) * BKP + kk + lcol);
            }
#pragma unroll
            for (int nb = 0; nb < 2; nb++) {
                ldsm_x4(bh[nb], Bh + (wn + nb * 16 + lrow) * BKP + kk + lcol);
                ldsm_x4(bl[nb], Bl + (wn + nb * 16 + lrow) * BKP + kk + lcol);
            }
#pragma unroll
            for (int mi = 0; mi < 4; mi++) {
#pragma unroll
                for (int nj = 0; nj < 4; nj++) {
                    const int nb = nj >> 1;
                    const int ns = nj & 1;
                    mma16816(acc[mi][nj], ah[mi], bh[nb][ns], bh[nb][ns + 2]);
                    mma16816(acc[mi][nj], ah[mi], bl[nb][ns], bl[nb][ns + 2]);
                    mma16816(acc[mi][nj], al[mi], bh[nb][ns], bh[nb][ns + 2]);
                }
            }
        }
        st = st + 1;
        if (st == 3) st = 0;
    }

#pragma unroll
    for (int mi = 0; mi < 4; mi++) {
#pragma unroll
        for (int nj = 0; nj < 4; nj++) {
            int row = row0 + wm + mi * 16 + (lane >> 2);
            int col = col0 + wn + nj * 8 + (lane & 3) * 2;
            float b0 = bias[col];
            float b1 = bias[col + 1];
            float v00 = acc[mi][nj][0] + b0;
            float v01 = acc[mi][nj][1] + b1;
            float v10 = acc[mi][nj][2] + b0;
            float v11 = acc[mi][nj][3] + b1;
            if (Ch) {
                v00 *= oscale; v01 *= oscale; v10 *= oscale; v11 *= oscale;
                uint32_t h0, l0, h1, l1;
                splitpack(v00, v01, h0, l0);
                splitpack(v10, v11, h1, l1);
                *(uint32_t*)(Ch + (size_t)row * N + col) = h0;
                *(uint32_t*)(Cl + (size_t)row * N + col) = l0;
                *(uint32_t*)(Ch + (size_t)(row + 8) * N + col) = h1;
                *(uint32_t*)(Cl + (size_t)(row + 8) * N + col) = l1;
            } else {
                float2 r0;
                float2 r1;
                r0.x = v00; r0.y = v01;
                r1.x = v10; r1.y = v11;
                *(float2*)(C + (size_t)row * N + col) = r0;
                *(float2*)(C + (size_t)(row + 8) * N + col) = r1;
            }
        }
    }
}

// merged Q/K/V projection: grid.x in [0,48): 0-31 Q tiles, 32-39 K, 40-47 V
__global__ __launch_bounds__(256)
void gemm_qkv(const __nv_bfloat16* __restrict__ xh,
              const __nv_bfloat16* __restrict__ xl,
              const __nv_bfloat16* __restrict__ qwh,
              const __nv_bfloat16* __restrict__ qwl,
              const __nv_bfloat16* __restrict__ kwh,
              const __nv_bfloat16* __restrict__ kwl,
              const __nv_bfloat16* __restrict__ vwh,
              const __nv_bfloat16* __restrict__ vwl,
              const float* __restrict__ q_b,
              const float* __restrict__ k_b,
              const float* __restrict__ v_b,
              __nv_bfloat16* __restrict__ qh, __nv_bfloat16* __restrict__ ql,
              __nv_bfloat16* __restrict__ kh, __nv_bfloat16* __restrict__ kl,
              __nv_bfloat16* __restrict__ vh, __nv_bfloat16* __restrict__ vl,
              float qscale)
{
    const int bx = blockIdx.x;
    const int row0 = blockIdx.y * 128;

    const __nv_bfloat16* Bh;
    const __nv_bfloat16* Bl;
    const float* bias;
    __nv_bfloat16* Ch;
    __nv_bfloat16* Cl;
    float osc;
    int col0;
    int N;

    if (bx < 32) {
        Bh = qwh; Bl = qwl; bias = q_b; Ch = qh; Cl = ql;
        osc = qscale; col0 = bx * 128; N = EMB;
    } else if (bx < 40) {
        Bh = kwh; Bl = kwl; bias = k_b; Ch = kh; Cl = kl;
        osc = 1.0f; col0 = (bx - 32) * 128; N = KVD;
    } else {
        Bh = vwh; Bl = vwl; bias = v_b; Ch = vh; Cl = vl;
        osc = 1.0f; col0 = (bx - 40) * 128; N = KVD;
    }

    gemm_body(xh, xl, Bh, Bl, bias, (float*)0, Ch, Cl, osc, N, EMB, row0, col0);
}

// O projection (fp32 out)
__global__ __launch_bounds__(256)
void gemm_oproj(const __nv_bfloat16* __restrict__ awh,
                const __nv_bfloat16* __restrict__ awl,
                const __nv_bfloat16* __restrict__ owh,
                const __nv_bfloat16* __restrict__ owl,
                const float* __restrict__ o_b,
                float* __restrict__ out)
{
    gemm_body(awh, awl, owh, owl, o_b, out, (__nv_bfloat16*)0, (__nv_bfloat16*)0,
              1.0f, EMB, EMB, blockIdx.y * 128, blockIdx.x * 128);
}

// ============================================================================
// Split-KV tensor-core flash attention (mma.sync), split-bf16.
// Grid (16, 32, 2): 128-query tile x head x KV-half. Writes fp32 partials.
// ============================================================================
#define KVP 136
#define FSTG (4 * 64 * KVP)
#define FL_SMEM_BYTES (2 * FSTG * 2)

__global__ __launch_bounds__(256)
void flash_mma()
{
    extern __shared__ __nv_bfloat16 smf[];

    const int tid  = threadIdx.x;
    const int warp = tid >> 5;
    const int lane = tid & 31;
    const int lrow = lane & 15;
    const int lcol = (lane >> 4) * 8;
    const int wq   = warp * 16;

    const int h   = blockIdx.y;
    const int hk  = h >> 2;
    const int q0  = blockIdx.x * 128;
    const int z   = blockIdx.z;
    const int kt0 = z * 16;

    {
        __nv_bfloat16* Qh = smf;
        __nv_bfloat16* Ql = smf + 128 * KVP;
        for (int idx = tid; idx < 128 * 16; idx += 256) {
            int r = idx >> 4;
            int c = (idx & 15) * 8;
            size_t g = (size_t)(q0 + r) * EMB + h * HD + c;
            *(uint4*)&Qh[r * KVP + c] = *(const uint4*)(g_qh + g);
            *(uint4*)&Ql[r * KVP + c] = *(const uint4*)(g_ql + g);
        }
    }
    __syncthreads();

    uint32_t qfh[8][4];
    uint32_t qfl[8][4];
    {
        const __nv_bfloat16* Qh = smf;
        const __nv_bfloat16* Ql = smf + 128 * KVP;
#pragma unroll
        for (int ks = 0; ks < 8; ks++) {
            ldsm_x4(qfh[ks], Qh + (wq + lrow) * KVP + ks * 16 + lcol);
            ldsm_x4(qfl[ks], Ql + (wq + lrow) * KVP + ks * 16 + lcol);
        }
    }
    __syncthreads();

#define FPREFETCH(st, kt)                                                     \
    do {                                                                      \
        __nv_bfloat16* sb = smf + (st) * FSTG;                                \
        _Pragma("unroll")                                                     \
        for (int it = 0; it < 4; it++) {                                      \
            int idx = tid + it * 256;                                         \
            int r = idx >> 4;                                                 \
            int c = (idx & 15) * 8;                                           \
            size_t g = (size_t)((kt) * 64 + r) * KVD + hk * HD + c;           \
            uint32_t d0 = smaddr(sb + r * KVP + c);                           \
            cp16(d0,                    g_kh + g);                            \
            cp16(d0 + 64 * KVP * 2,     g_kl + g);                            \
            cp16(d0 + 2 * 64 * KVP * 2, g_vh + g);                            \
            cp16(d0 + 3 * 64 * KVP * 2, g_vl + g);                            \
        }                                                                     \
    } while (0)

    FPREFETCH(0, kt0);
    cp_commit();

    float o[16][4];
#pragma unroll
    for (int i = 0; i < 16; i++)
#pragma unroll
        for (int r = 0; r < 4; r++)
            o[i][r] = 0.0f;

    float m1 = -1e30f;
    float m2 = -1e30f;
    float l1 = 0.0f;
    float l2 = 0.0f;

    int st = 0;
    for (int kt = kt0; kt < kt0 + 16; kt++) {
        cp_wait<0>();
        __syncthreads();
        if (kt + 1 < kt0 + 16) {
            FPREFETCH(st ^ 1, kt + 1);
            cp_commit();
        }

        const __nv_bfloat16* Kh = smf + st * FSTG;
        const __nv_bfloat16* Kl = Kh + 64 * KVP;
        const __nv_bfloat16* Vh = Kl + 64 * KVP;
        const __nv_bfloat16* Vl = Vh + 64 * KVP;

        float s[8][4];
#pragma unroll
        for (int t = 0; t < 8; t++)
#pragma unroll
            for (int r = 0; r < 4; r++)
                s[t][r] = 0.0f;

#pragma unroll
        for (int ks = 0; ks < 8; ks++) {
#pragma unroll
            for (int nsl = 0; nsl < 4; nsl++) {
                uint32_t kfh[4];
                uint32_t kfl[4];
                ldsm_x4(kfh, Kh + (nsl * 16 + lrow) * KVP + ks * 16 + lcol);
                ldsm_x4(kfl, Kl + (nsl * 16 + lrow) * KVP + ks * 16 + lcol);
#pragma unroll
                for (int ns = 0; ns < 2; ns++) {
                    float* sc = s[nsl * 2 + ns];
                    mma16816(sc, qfh[ks], kfh[ns], kfh[ns + 2]);
                    mma16816(sc, qfh[ks], kfl[ns], kfl[ns + 2]);
                    mma16816(sc, qfl[ks], kfh[ns], kfh[ns + 2]);
                }
            }
        }

        float mx1 = -1e30f;
        float mx2 = -1e30f;
#pragma unroll
        for (int t = 0; t < 8; t++) {
            mx1 = fmaxf(mx1, fmaxf(s[t][0], s[t][1]));
            mx2 = fmaxf(mx2, fmaxf(s[t][2], s[t][3]));
        }
        mx1 = fmaxf(mx1, __shfl_xor_sync(0xffffffffu, mx1, 1));
        mx1 = fmaxf(mx1, __shfl_xor_sync(0xffffffffu, mx1, 2));
        mx2 = fmaxf(mx2, __shfl_xor_sync(0xffffffffu, mx2, 1));
        mx2 = fmaxf(mx2, __shfl_xor_sync(0xffffffffu, mx2, 2));

        float newm1 = fmaxf(m1, mx1);
        float newm2 = fmaxf(m2, mx2);
        float corr1 = exp2f(m1 - newm1);
        float corr2 = exp2f(m2 - newm2);
        m1 = newm1;
        m2 = newm2;

        float ps1 = 0.0f;
        float ps2 = 0.0f;
#pragma unroll
        for (int t = 0; t < 8; t++) {
            s[t][0] = exp2f(s[t][0] - newm1);
            s[t][1] = exp2f(s[t][1] - newm1);
            s[t][2] = exp2f(s[t][2] - newm2);
            s[t][3] = exp2f(s[t][3] - newm2);
            ps1 += s[t][0] + s[t][1];
            ps2 += s[t][2] + s[t][3];
        }
        l1 = l1 * corr1 + ps1;
        l2 = l2 * corr2 + ps2;

#pragma unroll
        for (int i = 0; i < 16; i++) {
            o[i][0] *= corr1;
            o[i][1] *= corr1;
            o[i][2] *= corr2;
            o[i][3] *= corr2;
        }

#pragma unroll
        for (int ks2 = 0; ks2 < 4; ks2++) {
            uint32_t pah[4];
            uint32_t pal[4];
            splitpack(s[2 * ks2][0],     s[2 * ks2][1],     pah[0], pal[0]);
            splitpack(s[2 * ks2][2],     s[2 * ks2][3],     pah[1], pal[1]);
            splitpack(s[2 * ks2 + 1][0], s[2 * ks2 + 1][1], pah[2], pal[2]);
            splitpack(s[2 * ks2 + 1][2], s[2 * ks2 + 1][3], pah[3], pal[3]);
#pragma unroll
            for (int dsl = 0; dsl < 8; dsl++) {
                uint32_t vfh[4];
                uint32_t vfl[4];
                ldsm_x4t(vfh, Vh + (ks2 * 16 + lrow) * KVP + dsl * 16 + lcol);
                ldsm_x4t(vfl, Vl + (ks2 * 16 + lrow) * KVP + dsl * 16 + lcol);
                float* oc0 = o[dsl * 2];
                float* oc1 = o[dsl * 2 + 1];
                mma16816(oc0, pah, vfh[0], vfh[1]);
                mma16816(oc0, pah, vfl[0], vfl[1]);
                mma16816(oc0, pal, vfh[0], vfh[1]);
                mma16816(oc1, pah, vfh[2], vfh[3]);
                mma16816(oc1, pah, vfl[2], vfl[3]);
                mma16816(oc1, pal, vfh[2], vfh[3]);
            }
        }
        st ^= 1;
    }

    // ---- write fp32 partials + (m, l) ----
    l1 += __shfl_xor_sync(0xffffffffu, l1, 1);
    l1 += __shfl_xor_sync(0xffffffffu, l1, 2);
    l2 += __shfl_xor_sync(0xffffffffu, l2, 1);
    l2 += __shfl_xor_sync(0xffffffffu, l2, 2);

    const int row1 = q0 + wq + (lane >> 2);
    const int row2 = row1 + 8;
    const size_t zo = (size_t)z * SEQ * EMB;

    if ((lane & 3) == 0) {
        int mo = z * NH * SEQ + h * SEQ;
        g_pm[mo + row1] = m1;
        g_pl[mo + row1] = l1;
        g_pm[mo + row2] = m2;
        g_pl[mo + row2] = l2;
    }

#pragma unroll
    for (int nt = 0; nt < 16; nt++) {
        int col = h * HD + nt * 8 + (lane & 3) * 2;
        float2 r0;
        float2 r1;
        r0.x = o[nt][0];
        r0.y = o[nt][1];
        r1.x = o[nt][2];
        r1.y = o[nt][3];
        *(float2*)(g_po + zo + (size_t)row1 * EMB + col) = r0;
        *(float2*)(g_po + zo + (size_t)row2 * EMB + col) = r1;
    }
}

// ============================================================================
// combine the two KV halves -> split-bf16 attention output
// one thread = one (row, col-pair); total SEQ*EMB/2 threads
// ============================================================================
__global__ __launch_bounds__(256)
void attn_combine()
{
    int idx = blockIdx.x * blockDim.x + threadIdx.x;   // < SEQ*EMB/2
    int row  = idx >> 11;          // EMB/2 = 2048 pairs per row
    int pc   = idx & 2047;
    int col  = pc * 2;
    int head = col >> 7;

    int mo = head * SEQ + row;
    float m1 = g_pm[mo];
    float l1 = g_pl[mo];
    float m2 = g_pm[NH * SEQ + mo];
    float l2 = g_pl[NH * SEQ + mo];

    float mm = fmaxf(m1, m2);
    float w1 = exp2f(m1 - mm);
    float w2 = exp2f(m2 - mm);
    float inv = 1.0f / (w1 * l1 + w2 * l2);
    w1 *= inv;
    w2 *= inv;

    size_t off = (size_t)row * EMB + col;
    float2 o1 = *(const float2*)(g_po + off);
    float2 o2 = *(const float2*)(g_po + (size_t)SEQ * EMB + off);

    float v0 = w1 * o1.x + w2 * o2.x;
    float v1 = w1 * o1.y + w2 * o2.y;
    uint32_t hw, lw;
    splitpack(v0, v1, hw, lw);
    *(uint32_t*)(g_awh + off) = hw;
    *(uint32_t*)(g_awl + off) = lw;
}

// ============================================================================
// launch
// ============================================================================
extern "C" void kernel_launch(void* const* d_in, const int* in_sizes, int n_in,
                              void* d_out, int out_size)
{
    const float* x   = (const float*)d_in[0];
    const float* q_w = (const float*)d_in[1];
    const float* q_b = (const float*)d_in[2];
    const float* k_w = (const float*)d_in[3];
    const float* k_b = (const float*)d_in[4];
    const float* v_w = (const float*)d_in[5];
    const float* v_b = (const float*)d_in[6];
    const float* o_w = (const float*)d_in[7];
    const float* o_b = (const float*)d_in[8];
    float* out = (float*)d_out;

    __nv_bfloat16* xh = 0;
    __nv_bfloat16* xl = 0;
    __nv_bfloat16* qwh = 0;
    __nv_bfloat16* qwl = 0;
    __nv_bfloat16* kwh = 0;
    __nv_bfloat16* kwl = 0;
    __nv_bfloat16* vwh = 0;
    __nv_bfloat16* vwl = 0;
    __nv_bfloat16* owh = 0;
    __nv_bfloat16* owl = 0;
    __nv_bfloat16* qh = 0;
    __nv_bfloat16* ql = 0;
    __nv_bfloat16* kh = 0;
    __nv_bfloat16* kl = 0;
    __nv_bfloat16* vh = 0;
    __nv_bfloat16* vl = 0;
    __nv_bfloat16* awh = 0;
    __nv_bfloat16* awl = 0;
    cudaGetSymbolAddress((void**)&xh,  g_xh);
    cudaGetSymbolAddress((void**)&xl,  g_xl);
    cudaGetSymbolAddress((void**)&qwh, g_qwh);
    cudaGetSymbolAddress((void**)&qwl, g_qwl);
    cudaGetSymbolAddress((void**)&kwh, g_kwh);
    cudaGetSymbolAddress((void**)&kwl, g_kwl);
    cudaGetSymbolAddress((void**)&vwh, g_vwh);
    cudaGetSymbolAddress((void**)&vwl, g_vwl);
    cudaGetSymbolAddress((void**)&owh, g_owh);
    cudaGetSymbolAddress((void**)&owl, g_owl);
    cudaGetSymbolAddress((void**)&qh,  g_qh);
    cudaGetSymbolAddress((void**)&ql,  g_ql);
    cudaGetSymbolAddress((void**)&kh,  g_kh);
    cudaGetSymbolAddress((void**)&kl,  g_kl);
    cudaGetSymbolAddress((void**)&vh,  g_vh);
    cudaGetSymbolAddress((void**)&vl,  g_vl);
    cudaGetSymbolAddress((void**)&awh, g_awh);
    cudaGetSymbolAddress((void**)&awl, g_awl);

    cudaFuncSetAttribute(gemm_qkv,
                         cudaFuncAttributeMaxDynamicSharedMemorySize,
                         GEMM_SMEM_BYTES);
    cudaFuncSetAttribute(gemm_oproj,
                         cudaFuncAttributeMaxDynamicSharedMemorySize,
                         GEMM_SMEM_BYTES);
    cudaFuncSetAttribute(flash_mma,
                         cudaFuncAttributeMaxDynamicSharedMemorySize,
                         FL_SMEM_BYTES);

    dim3 blk(256);
    const float qscale = 0.08838834764831845f;   // 1/sqrt(128)

    // merged split-conversion (12582912 float4s)
    cvt_all<<<49152, 256>>>((const float4*)x, (const float4*)q_w,
                            (const float4*)k_w, (const float4*)v_w,
                            (const float4*)o_w,
                            (uint32_t*)xh, (uint32_t*)xl,
                            (uint32_t*)qwh, (uint32_t*)qwl,
                            (uint32_t*)kwh, (uint32_t*)kwl,
                            (uint32_t*)vwh, (uint32_t*)vwl,
                            (uint32_t*)owh, (uint32_t*)owl);

    // merged QKV projection
    gemm_qkv<<<dim3(48, 16), blk, GEMM_SMEM_BYTES>>>(
        xh, xl, qwh, qwl, kwh, kwl, vwh, vwl, q_b, k_b, v_b,
        qh, ql, kh, kl, vh, vl, qscale);

    // split-KV attention + combine
    flash_mma<<<dim3(16, 32, 2), blk, FL_SMEM_BYTES>>>();
    attn_combine<<<(SEQ * EMB / 2) / 256, 256>>>();

    // out = A @ o_w^T + o_b
    gemm_oproj<<<dim3(32, 16), blk, GEMM_SMEM_BYTES>>>(awh, awl, owh, owl,
                                                       o_b, out);
}

// round 8
// speedup vs baseline: 4.1745x; 1.5770x over previous
#include <cuda_runtime.h>
#include <cuda_fp16.h>
#include <cstdint>
#include <math.h>

#define SEQ   2048
#define EMB   4096
#define KVD   1024
#define NH    32
#define HD    128

// -------- scratch (device globals; no allocation allowed) --------
__device__ __half g_xh[SEQ * EMB];          // x, single fp16 (A-side)
__device__ __half g_qwh[EMB * EMB];         // weights split hi/lo (B-side)
__device__ __half g_qwl[EMB * EMB];
__device__ __half g_kwh[KVD * EMB];
__device__ __half g_kwl[KVD * EMB];
__device__ __half g_vwh[KVD * EMB];
__device__ __half g_vwl[KVD * EMB];
__device__ __half g_owh[EMB * EMB];
__device__ __half g_owl[EMB * EMB];

__device__ __half g_qh[SEQ * EMB];          // scaled Q, single fp16 (A-side)
__device__ __half g_kh[SEQ * KVD];          // K split (B-side of S)
__device__ __half g_kl[SEQ * KVD];
__device__ __half g_vh[SEQ * KVD];          // V split (B-side of PV)
__device__ __half g_vl[SEQ * KVD];
__device__ __half g_ah[SEQ * EMB];          // attention out, single fp16 (A-side)

// split-KV attention partials
__device__ float g_po[2 * SEQ * EMB];
__device__ float g_pm[2 * NH * SEQ];
__device__ float g_pl[2 * NH * SEQ];

// ============================================================================
// helpers
// ============================================================================
__device__ __forceinline__ uint32_t smaddr(const void* p)
{
    return (uint32_t)__cvta_generic_to_shared(p);
}

__device__ __forceinline__ void cp16(uint32_t dst, const void* src)
{
    asm volatile("cp.async.cg.shared.global [%0], [%1], 16;"
                 :: "r"(dst), "l"(src));
}

__device__ __forceinline__ void cp_commit()
{
    asm volatile("cp.async.commit_group;");
}

template <int N>
__device__ __forceinline__ void cp_wait()
{
    asm volatile("cp.async.wait_group %0;" :: "n"(N));
}

__device__ __forceinline__ void ldsm_x4(uint32_t* r, const __half* p)
{
    uint32_t addr = smaddr(p);
    asm volatile("ldmatrix.sync.aligned.m8n8.x4.shared.b16 {%0,%1,%2,%3}, [%4];"
                 : "=r"(r[0]), "=r"(r[1]), "=r"(r[2]), "=r"(r[3])
                 : "r"(addr));
}

__device__ __forceinline__ void ldsm_x4t(uint32_t* r, const __half* p)
{
    uint32_t addr = smaddr(p);
    asm volatile("ldmatrix.sync.aligned.m8n8.x4.trans.shared.b16 {%0,%1,%2,%3}, [%4];"
                 : "=r"(r[0]), "=r"(r[1]), "=r"(r[2]), "=r"(r[3])
                 : "r"(addr));
}

__device__ __forceinline__ void mma16816(float* c, const uint32_t* a,
                                         uint32_t b0, uint32_t b1)
{
    asm volatile(
        "mma.sync.aligned.m16n8k16.row.col.f32.f16.f16.f32 "
        "{%0,%1,%2,%3}, {%4,%5,%6,%7}, {%8,%9}, {%0,%1,%2,%3};"
        : "+f"(c[0]), "+f"(c[1]), "+f"(c[2]), "+f"(c[3])
        : "r"(a[0]), "r"(a[1]), "r"(a[2]), "r"(a[3]), "r"(b0), "r"(b1));
}

__device__ __forceinline__ void splitpack_h(float a, float b,
                                            uint32_t& hi, uint32_t& lo)
{
    __half ha = __float2half_rn(a);
    __half hb = __float2half_rn(b);
    __half la = __float2half_rn(a - __half2float(ha));
    __half lb = __float2half_rn(b - __half2float(hb));
    __half2 th = __halves2half2(ha, hb);
    __half2 tl = __halves2half2(la, lb);
    hi = *(uint32_t*)&th;
    lo = *(uint32_t*)&tl;
}

__device__ __forceinline__ uint32_t pack_h(float a, float b)
{
    __half2 t = __halves2half2(__float2half_rn(a), __float2half_rn(b));
    return *(uint32_t*)&t;
}

__device__ __forceinline__ void split_store(const float4* in,
                                            uint32_t* hi, uint32_t* lo, int i)
{
    float4 v = in[i];
    uint32_t h0, l0, h1, l1;
    splitpack_h(v.x, v.y, h0, l0);
    splitpack_h(v.z, v.w, h1, l1);
    hi[i * 2 + 0] = h0;
    hi[i * 2 + 1] = h1;
    lo[i * 2 + 0] = l0;
    lo[i * 2 + 1] = l1;
}

__device__ __forceinline__ void single_store(const float4* in, uint32_t* hi, int i)
{
    float4 v = in[i];
    hi[i * 2 + 0] = pack_h(v.x, v.y);
    hi[i * 2 + 1] = pack_h(v.z, v.w);
}

// ============================================================================
// merged fp32 -> fp16 conversion: x single; weights split hi/lo
// float4 ranges: x 2097152 | qw 4194304 | kw 1048576 | vw 1048576 | ow 4194304
// ============================================================================
__global__ __launch_bounds__(256)
void cvt_all(const float4* __restrict__ x,  const float4* __restrict__ qw,
             const float4* __restrict__ kw, const float4* __restrict__ vw,
             const float4* __restrict__ ow,
             uint32_t* xh, uint32_t* qwh, uint32_t* qwl,
             uint32_t* kwh, uint32_t* kwl, uint32_t* vwh, uint32_t* vwl,
             uint32_t* owh, uint32_t* owl)
{
    int i = blockIdx.x * blockDim.x + threadIdx.x;
    if (i < 2097152) {
        single_store(x, xh, i);
    } else if (i < 6291456) {
        split_store(qw, qwh, qwl, i - 2097152);
    } else if (i < 7340032) {
        split_store(kw, kwh, kwl, i - 6291456);
    } else if (i < 8388608) {
        split_store(vw, vwh, vwl, i - 7340032);
    } else if (i < 12582912) {
        split_store(ow, owh, owl, i - 8388608);
    }
}

// ============================================================================
// fp16 2-pass GEMM (NT): C = A @ B^T + bias,  A single fp16, B split hi/lo.
// acc = Ah*Bh + Ah*Bl (fp32 accum). 3-stage cp.async pipeline.
// Block tile 128x128x32, 256 threads, warp tile 64x32.
// Output: Ch&Cl -> split fp16; Ch only -> single fp16; else fp32 C.
// ============================================================================
#define BKP 40
#define GSTG (3 * 128 * BKP)
#define GEMM_SMEM_BYTES (3 * GSTG * 2)   // 92160

__device__ __forceinline__
void gemm_body(const __half* __restrict__ Ahg,
               const __half* __restrict__ Bhg,
               const __half* __restrict__ Blg,
               const float* __restrict__ bias,
               float* __restrict__ C,
               __half* __restrict__ Ch,
               __half* __restrict__ Cl,
               float oscale, int N, int K, int row0, int col0)
{
    extern __shared__ __half smg[];

    const int tid  = threadIdx.x;
    const int warp = tid >> 5;
    const int lane = tid & 31;
    const int wm = (warp >> 2) * 64;
    const int wn = (warp & 3) * 32;

    const int lr = tid >> 1;
    const int lc = (tid & 1) * 16;

    const __half* pAh = Ahg + (size_t)(row0 + lr) * K + lc;
    const __half* pBh = Bhg + (size_t)(col0 + lr) * K + lc;
    const __half* pBl = Blg + (size_t)(col0 + lr) * K + lc;

    const int dstoff = lr * BKP + lc;

    float acc[4][4][4];
#pragma unroll
    for (int i = 0; i < 4; i++)
#pragma unroll
        for (int j = 0; j < 4; j++)
#pragma unroll
            for (int r = 0; r < 4; r++)
                acc[i][j][r] = 0.0f;

    const int lrow = lane & 15;
    const int lcol = (lane >> 4) * 8;

#define GPREFETCH(st, k0)                                                     \
    do {                                                                      \
        __half* sb = smg + (st) * GSTG + dstoff;                              \
        uint32_t d0 = smaddr(sb);                                             \
        cp16(d0,                          pAh + (k0));                        \
        cp16(d0 + 16,                     pAh + (k0) + 8);                    \
        cp16(d0 + 128 * BKP * 2,          pBh + (k0));                        \
        cp16(d0 + 128 * BKP * 2 + 16,     pBh + (k0) + 8);                    \
        cp16(d0 + 2 * 128 * BKP * 2,      pBl + (k0));                        \
        cp16(d0 + 2 * 128 * BKP * 2 + 16, pBl + (k0) + 8);                    \
    } while (0)

    GPREFETCH(0, 0);
    cp_commit();
    GPREFETCH(1, 32);
    cp_commit();

    int st = 0;
    for (int k0 = 0; k0 < K; k0 += 32) {
        if (k0 + 32 < K) cp_wait<1>(); else cp_wait<0>();
        __syncthreads();
        if (k0 + 64 < K) {
            int st2 = st + 2;
            if (st2 >= 3) st2 -= 3;
            GPREFETCH(st2, k0 + 64);
            cp_commit();
        }

        const __half* Ah = smg + st * GSTG;
        const __half* Bh = Ah + 128 * BKP;
        const __half* Bl = Bh + 128 * BKP;

#pragma unroll
        for (int ks = 0; ks < 2; ks++) {
            const int kk = ks * 16;
            uint32_t ah[4][4];
            uint32_t bh[2][4];
            uint32_t bl[2][4];
#pragma unroll
            for (int mi = 0; mi < 4; mi++) {
                ldsm_x4(ah[mi], Ah + (wm + mi * 16 + lrow) * BKP + kk + lcol);
            }
#pragma unroll
            for (int nb = 0; nb < 2; nb++) {
                ldsm_x4(bh[nb], Bh + (wn + nb * 16 + lrow) * BKP + kk + lcol);
                ldsm_x4(bl[nb], Bl + (wn + nb * 16 + lrow) * BKP + kk + lcol);
            }
#pragma unroll
            for (int mi = 0; mi < 4; mi++) {
#pragma unroll
                for (int nj = 0; nj < 4; nj++) {
                    const int nb = nj >> 1;
                    const int ns = nj & 1;
                    mma16816(acc[mi][nj], ah[mi], bh[nb][ns], bh[nb][ns + 2]);
                    mma16816(acc[mi][nj], ah[mi], bl[nb][ns], bl[nb][ns + 2]);
                }
            }
        }
        st = st + 1;
        if (st == 3) st = 0;
    }

#pragma unroll
    for (int mi = 0; mi < 4; mi++) {
#pragma unroll
        for (int nj = 0; nj < 4; nj++) {
            int row = row0 + wm + mi * 16 + (lane >> 2);
            int col = col0 + wn + nj * 8 + (lane & 3) * 2;
            float b0 = bias[col];
            float b1 = bias[col + 1];
            float v00 = acc[mi][nj][0] + b0;
            float v01 = acc[mi][nj][1] + b1;
            float v10 = acc[mi][nj][2] + b0;
            float v11 = acc[mi][nj][3] + b1;
            if (Ch && Cl) {
                uint32_t h0, l0, h1, l1;
                splitpack_h(v00 * oscale, v01 * oscale, h0, l0);
                splitpack_h(v10 * oscale, v11 * oscale, h1, l1);
                *(uint32_t*)(Ch + (size_t)row * N + col) = h0;
                *(uint32_t*)(Cl + (size_t)row * N + col) = l0;
                *(uint32_t*)(Ch + (size_t)(row + 8) * N + col) = h1;
                *(uint32_t*)(Cl + (size_t)(row + 8) * N + col) = l1;
            } else if (Ch) {
                *(uint32_t*)(Ch + (size_t)row * N + col) =
                    pack_h(v00 * oscale, v01 * oscale);
                *(uint32_t*)(Ch + (size_t)(row + 8) * N + col) =
                    pack_h(v10 * oscale, v11 * oscale);
            } else {
                float2 r0;
                float2 r1;
                r0.x = v00; r0.y = v01;
                r1.x = v10; r1.y = v11;
                *(float2*)(C + (size_t)row * N + col) = r0;
                *(float2*)(C + (size_t)(row + 8) * N + col) = r1;
            }
        }
    }
}

// merged Q/K/V projection: grid.x in [0,48): 0-31 Q tiles, 32-39 K, 40-47 V
__global__ __launch_bounds__(256)
void gemm_qkv(const __half* __restrict__ xh,
              const __half* __restrict__ qwh, const __half* __restrict__ qwl,
              const __half* __restrict__ kwh, const __half* __restrict__ kwl,
              const __half* __restrict__ vwh, const __half* __restrict__ vwl,
              const float* __restrict__ q_b,
              const float* __restrict__ k_b,
              const float* __restrict__ v_b,
              __half* __restrict__ qh,
              __half* __restrict__ kh, __half* __restrict__ kl,
              __half* __restrict__ vh, __half* __restrict__ vl,
              float qscale)
{
    const int bx = blockIdx.x;
    const int row0 = blockIdx.y * 128;

    if (bx < 32) {
        // Q: single fp16 out, pre-scaled
        gemm_body(xh, qwh, qwl, q_b, (float*)0, qh, (__half*)0,
                  qscale, EMB, EMB, row0, bx * 128);
    } else if (bx < 40) {
        gemm_body(xh, kwh, kwl, k_b, (float*)0, kh, kl,
                  1.0f, KVD, EMB, row0, (bx - 32) * 128);
    } else {
        gemm_body(xh, vwh, vwl, v_b, (float*)0, vh, vl,
                  1.0f, KVD, EMB, row0, (bx - 40) * 128);
    }
}

// O projection (fp32 out)
__global__ __launch_bounds__(256)
void gemm_oproj(const __half* __restrict__ ah,
                const __half* __restrict__ owh, const __half* __restrict__ owl,
                const float* __restrict__ o_b,
                float* __restrict__ out)
{
    gemm_body(ah, owh, owl, o_b, out, (__half*)0, (__half*)0,
              1.0f, EMB, EMB, blockIdx.y * 128, blockIdx.x * 128);
}

// ============================================================================
// Split-KV flash attention (mma.sync fp16 2-pass), base-2 softermax.
// Q single fp16 (A-side); K,V split hi/lo (B-side); P single fp16 (A-side).
// Grid (16, 32, 2): 128-query tile x head x KV-half. fp32 partials out.
// ============================================================================
#define KVP 136
#define FSTG (4 * 64 * KVP)
#define FL_SMEM_BYTES (2 * FSTG * 2)

__global__ __launch_bounds__(256)
void flash_mma()
{
    extern __shared__ __half smf[];

    const int tid  = threadIdx.x;
    const int warp = tid >> 5;
    const int lane = tid & 31;
    const int lrow = lane & 15;
    const int lcol = (lane >> 4) * 8;
    const int wq   = warp * 16;

    const int h   = blockIdx.y;
    const int hk  = h >> 2;
    const int q0  = blockIdx.x * 128;
    const int z   = blockIdx.z;
    const int kt0 = z * 16;

    // stage Q (single), pull fragments
    {
        __half* Qs = smf;
        for (int idx = tid; idx < 128 * 16; idx += 256) {
            int r = idx >> 4;
            int c = (idx & 15) * 8;
            size_t g = (size_t)(q0 + r) * EMB + h * HD + c;
            *(uint4*)&Qs[r * KVP + c] = *(const uint4*)(g_qh + g);
        }
    }
    __syncthreads();

    uint32_t qf[8][4];
    {
        const __half* Qs = smf;
#pragma unroll
        for (int ks = 0; ks < 8; ks++) {
            ldsm_x4(qf[ks], Qs + (wq + lrow) * KVP + ks * 16 + lcol);
        }
    }
    __syncthreads();

#define FPREFETCH(st, kt)                                                     \
    do {                                                                      \
        __half* sb = smf + (st) * FSTG;                                       \
        _Pragma("unroll")                                                     \
        for (int it = 0; it < 4; it++) {                                      \
            int idx = tid + it * 256;                                         \
            int r = idx >> 4;                                                 \
            int c = (idx & 15) * 8;                                           \
            size_t g = (size_t)((kt) * 64 + r) * KVD + hk * HD + c;           \
            uint32_t d0 = smaddr(sb + r * KVP + c);                           \
            cp16(d0,                    g_kh + g);                            \
            cp16(d0 + 64 * KVP * 2,     g_kl + g);                            \
            cp16(d0 + 2 * 64 * KVP * 2, g_vh + g);                            \
            cp16(d0 + 3 * 64 * KVP * 2, g_vl + g);                            \
        }                                                                     \
    } while (0)

    FPREFETCH(0, kt0);
    cp_commit();

    float o[16][4];
#pragma unroll
    for (int i = 0; i < 16; i++)
#pragma unroll
        for (int r = 0; r < 4; r++)
            o[i][r] = 0.0f;

    float m1 = -1e30f;
    float m2 = -1e30f;
    float l1 = 0.0f;
    float l2 = 0.0f;

    int st = 0;
    for (int kt = kt0; kt < kt0 + 16; kt++) {
        cp_wait<0>();
        __syncthreads();
        if (kt + 1 < kt0 + 16) {
            FPREFETCH(st ^ 1, kt + 1);
            cp_commit();
        }

        const __half* Kh = smf + st * FSTG;
        const __half* Kl = Kh + 64 * KVP;
        const __half* Vh = Kl + 64 * KVP;
        const __half* Vl = Vh + 64 * KVP;

        // ---- S = Q K^T (2-pass: qh*kh + qh*kl) ----
        float s[8][4];
#pragma unroll
        for (int t = 0; t < 8; t++)
#pragma unroll
            for (int r = 0; r < 4; r++)
                s[t][r] = 0.0f;

#pragma unroll
        for (int ks = 0; ks < 8; ks++) {
#pragma unroll
            for (int nsl = 0; nsl < 4; nsl++) {
                uint32_t kfh[4];
                uint32_t kfl[4];
                ldsm_x4(kfh, Kh + (nsl * 16 + lrow) * KVP + ks * 16 + lcol);
                ldsm_x4(kfl, Kl + (nsl * 16 + lrow) * KVP + ks * 16 + lcol);
#pragma unroll
                for (int ns = 0; ns < 2; ns++) {
                    float* sc = s[nsl * 2 + ns];
                    mma16816(sc, qf[ks], kfh[ns], kfh[ns + 2]);
                    mma16816(sc, qf[ks], kfl[ns], kfl[ns + 2]);
                }
            }
        }

        // ---- online base-2 softmax ----
        float mx1 = -1e30f;
        float mx2 = -1e30f;
#pragma unroll
        for (int t = 0; t < 8; t++) {
            mx1 = fmaxf(mx1, fmaxf(s[t][0], s[t][1]));
            mx2 = fmaxf(mx2, fmaxf(s[t][2], s[t][3]));
        }
        mx1 = fmaxf(mx1, __shfl_xor_sync(0xffffffffu, mx1, 1));
        mx1 = fmaxf(mx1, __shfl_xor_sync(0xffffffffu, mx1, 2));
        mx2 = fmaxf(mx2, __shfl_xor_sync(0xffffffffu, mx2, 1));
        mx2 = fmaxf(mx2, __shfl_xor_sync(0xffffffffu, mx2, 2));

        float newm1 = fmaxf(m1, mx1);
        float newm2 = fmaxf(m2, mx2);
        float corr1 = exp2f(m1 - newm1);
        float corr2 = exp2f(m2 - newm2);
        m1 = newm1;
        m2 = newm2;

        float ps1 = 0.0f;
        float ps2 = 0.0f;
#pragma unroll
        for (int t = 0; t < 8; t++) {
            s[t][0] = exp2f(s[t][0] - newm1);
            s[t][1] = exp2f(s[t][1] - newm1);
            s[t][2] = exp2f(s[t][2] - newm2);
            s[t][3] = exp2f(s[t][3] - newm2);
            ps1 += s[t][0] + s[t][1];
            ps2 += s[t][2] + s[t][3];
        }
        l1 = l1 * corr1 + ps1;
        l2 = l2 * corr2 + ps2;

#pragma unroll
        for (int i = 0; i < 16; i++) {
            o[i][0] *= corr1;
            o[i][1] *= corr1;
            o[i][2] *= corr2;
            o[i][3] *= corr2;
        }

        // ---- O += P V (2-pass: ph*vh + ph*vl; V via ldmatrix.trans) ----
#pragma unroll
        for (int ks2 = 0; ks2 < 4; ks2++) {
            uint32_t ph[4];
            ph[0] = pack_h(s[2 * ks2][0],     s[2 * ks2][1]);
            ph[1] = pack_h(s[2 * ks2][2],     s[2 * ks2][3]);
            ph[2] = pack_h(s[2 * ks2 + 1][0], s[2 * ks2 + 1][1]);
            ph[3] = pack_h(s[2 * ks2 + 1][2], s[2 * ks2 + 1][3]);
#pragma unroll
            for (int dsl = 0; dsl < 8; dsl++) {
                uint32_t vfh[4];
                uint32_t vfl[4];
                ldsm_x4t(vfh, Vh + (ks2 * 16 + lrow) * KVP + dsl * 16 + lcol);
                ldsm_x4t(vfl, Vl + (ks2 * 16 + lrow) * KVP + dsl * 16 + lcol);
                float* oc0 = o[dsl * 2];
                float* oc1 = o[dsl * 2 + 1];
                mma16816(oc0, ph, vfh[0], vfh[1]);
                mma16816(oc0, ph, vfl[0], vfl[1]);
                mma16816(oc1, ph, vfh[2], vfh[3]);
                mma16816(oc1, ph, vfl[2], vfl[3]);
            }
        }
        st ^= 1;
    }

    // ---- write fp32 partials + (m, l) ----
    l1 += __shfl_xor_sync(0xffffffffu, l1, 1);
    l1 += __shfl_xor_sync(0xffffffffu, l1, 2);
    l2 += __shfl_xor_sync(0xffffffffu, l2, 1);
    l2 += __shfl_xor_sync(0xffffffffu, l2, 2);

    const int row1 = q0 + wq + (lane >> 2);
    const int row2 = row1 + 8;
    const size_t zo = (size_t)z * SEQ * EMB;

    if ((lane & 3) == 0) {
        int mo = z * NH * SEQ + h * SEQ;
        g_pm[mo + row1] = m1;
        g_pl[mo + row1] = l1;
        g_pm[mo + row2] = m2;
        g_pl[mo + row2] = l2;
    }

#pragma unroll
    for (int nt = 0; nt < 16; nt++) {
        int col = h * HD + nt * 8 + (lane & 3) * 2;
        float2 r0;
        float2 r1;
        r0.x = o[nt][0];
        r0.y = o[nt][1];
        r1.x = o[nt][2];
        r1.y = o[nt][3];
        *(float2*)(g_po + zo + (size_t)row1 * EMB + col) = r0;
        *(float2*)(g_po + zo + (size_t)row2 * EMB + col) = r1;
    }
}

// ============================================================================
// combine KV halves -> single-fp16 attention output
// ============================================================================
__global__ __launch_bounds__(256)
void attn_combine()
{
    int idx = blockIdx.x * blockDim.x + threadIdx.x;   // < SEQ*EMB/2
    int row  = idx >> 11;
    int pc   = idx & 2047;
    int col  = pc * 2;
    int head = col >> 7;

    int mo = head * SEQ + row;
    float m1 = g_pm[mo];
    float l1 = g_pl[mo];
    float m2 = g_pm[NH * SEQ + mo];
    float l2 = g_pl[NH * SEQ + mo];

    float mm = fmaxf(m1, m2);
    float w1 = exp2f(m1 - mm);
    float w2 = exp2f(m2 - mm);
    float inv = 1.0f / (w1 * l1 + w2 * l2);
    w1 *= inv;
    w2 *= inv;

    size_t off = (size_t)row * EMB + col;
    float2 o1 = *(const float2*)(g_po + off);
    float2 o2 = *(const float2*)(g_po + (size_t)SEQ * EMB + off);

    float v0 = w1 * o1.x + w2 * o2.x;
    float v1 = w1 * o1.y + w2 * o2.y;
    *(uint32_t*)(g_ah + off) = pack_h(v0, v1);
}

// ============================================================================
// launch
// ============================================================================
extern "C" void kernel_launch(void* const* d_in, const int* in_sizes, int n_in,
                              void* d_out, int out_size)
{
    const float* x   = (const float*)d_in[0];
    const float* q_w = (const float*)d_in[1];
    const float* q_b = (const float*)d_in[2];
    const float* k_w = (const float*)d_in[3];
    const float* k_b = (const float*)d_in[4];
    const float* v_w = (const float*)d_in[5];
    const float* v_b = (const float*)d_in[6];
    const float* o_w = (const float*)d_in[7];
    const float* o_b = (const float*)d_in[8];
    float* out = (float*)d_out;

    __half* xh = 0;
    __half* qwh = 0;
    __half* qwl = 0;
    __half* kwh = 0;
    __half* kwl = 0;
    __half* vwh = 0;
    __half* vwl = 0;
    __half* owh = 0;
    __half* owl = 0;
    __half* qh = 0;
    __half* kh = 0;
    __half* kl = 0;
    __half* vh = 0;
    __half* vl = 0;
    __half* ah = 0;
    cudaGetSymbolAddress((void**)&xh,  g_xh);
    cudaGetSymbolAddress((void**)&qwh, g_qwh);
    cudaGetSymbolAddress((void**)&qwl, g_qwl);
    cudaGetSymbolAddress((void**)&kwh, g_kwh);
    cudaGetSymbolAddress((void**)&kwl, g_kwl);
    cudaGetSymbolAddress((void**)&vwh, g_vwh);
    cudaGetSymbolAddress((void**)&vwl, g_vwl);
    cudaGetSymbolAddress((void**)&owh, g_owh);
    cudaGetSymbolAddress((void**)&owl, g_owl);
    cudaGetSymbolAddress((void**)&qh,  g_qh);
    cudaGetSymbolAddress((void**)&kh,  g_kh);
    cudaGetSymbolAddress((void**)&kl,  g_kl);
    cudaGetSymbolAddress((void**)&vh,  g_vh);
    cudaGetSymbolAddress((void**)&vl,  g_vl);
    cudaGetSymbolAddress((void**)&ah,  g_ah);

    cudaFuncSetAttribute(gemm_qkv,
                         cudaFuncAttributeMaxDynamicSharedMemorySize,
                         GEMM_SMEM_BYTES);
    cudaFuncSetAttribute(gemm_oproj,
                         cudaFuncAttributeMaxDynamicSharedMemorySize,
                         GEMM_SMEM_BYTES);
    cudaFuncSetAttribute(flash_mma,
                         cudaFuncAttributeMaxDynamicSharedMemorySize,
                         FL_SMEM_BYTES);

    dim3 blk(256);
    const float qscale = 0.08838834764831845f;   // 1/sqrt(128)

    cvt_all<<<49152, 256>>>((const float4*)x, (const float4*)q_w,
                            (const float4*)k_w, (const float4*)v_w,
                            (const float4*)o_w,
                            (uint32_t*)xh,
                            (uint32_t*)qwh, (uint32_t*)qwl,
                            (uint32_t*)kwh, (uint32_t*)kwl,
                            (uint32_t*)vwh, (uint32_t*)vwl,
                            (uint32_t*)owh, (uint32_t*)owl);

    gemm_qkv<<<dim3(48, 16), blk, GEMM_SMEM_BYTES>>>(
        xh, qwh, qwl, kwh, kwl, vwh, vwl, q_b, k_b, v_b,
        qh, kh, kl, vh, vl, qscale);

    flash_mma<<<dim3(16, 32, 2), blk, FL_SMEM_BYTES>>>();
    attn_combine<<<(SEQ * EMB / 2) / 256, 256>>>();

    gemm_oproj<<<dim3(32, 16), blk, GEMM_SMEM_BYTES>>>(ah, owh, owl, o_b, out);
}

// round 9
// speedup vs baseline: 6.8194x; 1.6336x over previous
#include <cuda_runtime.h>
#include <cuda_fp16.h>
#include <cstdint>
#include <math.h>

#define SEQ   2048
#define EMB   4096
#define KVD   1024
#define NH    32
#define HD    128

// -------- scratch (device globals; no allocation allowed) --------
__device__ __half g_xh[SEQ * EMB];
__device__ __half g_qwh[EMB * EMB];
__device__ __half g_kwh[KVD * EMB];
__device__ __half g_vwh[KVD * EMB];
__device__ __half g_owh[EMB * EMB];

__device__ __half g_qh[SEQ * EMB];          // scaled Q
__device__ __half g_kh[SEQ * KVD];
__device__ __half g_vh[SEQ * KVD];
__device__ __half g_ah[SEQ * EMB];          // attention out

// split-KV attention partials
__device__ float g_po[2 * SEQ * EMB];
__device__ float g_pm[2 * NH * SEQ];
__device__ float g_pl[2 * NH * SEQ];

// ============================================================================
// helpers
// ============================================================================
__device__ __forceinline__ uint32_t smaddr(const void* p)
{
    return (uint32_t)__cvta_generic_to_shared(p);
}

__device__ __forceinline__ void cp16(uint32_t dst, const void* src)
{
    asm volatile("cp.async.cg.shared.global [%0], [%1], 16;"
                 :: "r"(dst), "l"(src));
}

__device__ __forceinline__ void cp_commit()
{
    asm volatile("cp.async.commit_group;");
}

template <int N>
__device__ __forceinline__ void cp_wait()
{
    asm volatile("cp.async.wait_group %0;" :: "n"(N));
}

__device__ __forceinline__ void ldsm_x4(uint32_t* r, const __half* p)
{
    uint32_t addr = smaddr(p);
    asm volatile("ldmatrix.sync.aligned.m8n8.x4.shared.b16 {%0,%1,%2,%3}, [%4];"
                 : "=r"(r[0]), "=r"(r[1]), "=r"(r[2]), "=r"(r[3])
                 : "r"(addr));
}

__device__ __forceinline__ void ldsm_x4t(uint32_t* r, const __half* p)
{
    uint32_t addr = smaddr(p);
    asm volatile("ldmatrix.sync.aligned.m8n8.x4.trans.shared.b16 {%0,%1,%2,%3}, [%4];"
                 : "=r"(r[0]), "=r"(r[1]), "=r"(r[2]), "=r"(r[3])
                 : "r"(addr));
}

__device__ __forceinline__ void mma16816(float* c, const uint32_t* a,
                                         uint32_t b0, uint32_t b1)
{
    asm volatile(
        "mma.sync.aligned.m16n8k16.row.col.f32.f16.f16.f32 "
        "{%0,%1,%2,%3}, {%4,%5,%6,%7}, {%8,%9}, {%0,%1,%2,%3};"
        : "+f"(c[0]), "+f"(c[1]), "+f"(c[2]), "+f"(c[3])
        : "r"(a[0]), "r"(a[1]), "r"(a[2]), "r"(a[3]), "r"(b0), "r"(b1));
}

__device__ __forceinline__ uint32_t pack_h(float a, float b)
{
    __half2 t = __halves2half2(__float2half_rn(a), __float2half_rn(b));
    return *(uint32_t*)&t;
}

__device__ __forceinline__ void single_store(const float4* in, uint32_t* hi, int i)
{
    float4 v = in[i];
    hi[i * 2 + 0] = pack_h(v.x, v.y);
    hi[i * 2 + 1] = pack_h(v.z, v.w);
}

// ============================================================================
// merged fp32 -> fp16 conversion (all tensors single fp16)
// float4 ranges: x 2097152 | qw 4194304 | kw 1048576 | vw 1048576 | ow 4194304
// ============================================================================
__global__ __launch_bounds__(256)
void cvt_all(const float4* __restrict__ x,  const float4* __restrict__ qw,
             const float4* __restrict__ kw, const float4* __restrict__ vw,
             const float4* __restrict__ ow,
             uint32_t* xh, uint32_t* qwh, uint32_t* kwh, uint32_t* vwh,
             uint32_t* owh)
{
    int i = blockIdx.x * blockDim.x + threadIdx.x;
    if (i < 2097152) {
        single_store(x, xh, i);
    } else if (i < 6291456) {
        single_store(qw, qwh, i - 2097152);
    } else if (i < 7340032) {
        single_store(kw, kwh, i - 6291456);
    } else if (i < 8388608) {
        single_store(vw, vwh, i - 7340032);
    } else if (i < 12582912) {
        single_store(ow, owh, i - 8388608);
    }
}

// ============================================================================
// fp16 single-pass GEMM (NT): C = A @ B^T + bias (fp32 accum).
// 3-stage cp.async pipeline. Block tile 128x128x32, 256 threads, warp 64x32.
// Output: Ch -> fp16 (scaled by oscale); else fp32 C.
// ============================================================================
#define BKP 40
#define GSTG (2 * 128 * BKP)
#define GEMM_SMEM_BYTES (3 * GSTG * 2)   // 61440

__device__ __forceinline__
void gemm_body(const __half* __restrict__ Ahg,
               const __half* __restrict__ Bhg,
               const float* __restrict__ bias,
               float* __restrict__ C,
               __half* __restrict__ Ch,
               float oscale, int N, int K, int row0, int col0)
{
    extern __shared__ __half smg[];

    const int tid  = threadIdx.x;
    const int warp = tid >> 5;
    const int lane = tid & 31;
    const int wm = (warp >> 2) * 64;
    const int wn = (warp & 3) * 32;

    const int lr = tid >> 1;
    const int lc = (tid & 1) * 16;

    const __half* pAh = Ahg + (size_t)(row0 + lr) * K + lc;
    const __half* pBh = Bhg + (size_t)(col0 + lr) * K + lc;

    const int dstoff = lr * BKP + lc;

    float acc[4][4][4];
#pragma unroll
    for (int i = 0; i < 4; i++)
#pragma unroll
        for (int j = 0; j < 4; j++)
#pragma unroll
            for (int r = 0; r < 4; r++)
                acc[i][j][r] = 0.0f;

    const int lrow = lane & 15;
    const int lcol = (lane >> 4) * 8;

#define GPREFETCH(st, k0)                                                     \
    do {                                                                      \
        __half* sb = smg + (st) * GSTG + dstoff;                              \
        uint32_t d0 = smaddr(sb);                                             \
        cp16(d0,                      pAh + (k0));                            \
        cp16(d0 + 16,                 pAh + (k0) + 8);                        \
        cp16(d0 + 128 * BKP * 2,      pBh + (k0));                            \
        cp16(d0 + 128 * BKP * 2 + 16, pBh + (k0) + 8);                        \
    } while (0)

    GPREFETCH(0, 0);
    cp_commit();
    GPREFETCH(1, 32);
    cp_commit();

    int st = 0;
    for (int k0 = 0; k0 < K; k0 += 32) {
        if (k0 + 32 < K) cp_wait<1>(); else cp_wait<0>();
        __syncthreads();
        if (k0 + 64 < K) {
            int st2 = st + 2;
            if (st2 >= 3) st2 -= 3;
            GPREFETCH(st2, k0 + 64);
            cp_commit();
        }

        const __half* Ah = smg + st * GSTG;
        const __half* Bh = Ah + 128 * BKP;

#pragma unroll
        for (int ks = 0; ks < 2; ks++) {
            const int kk = ks * 16;
            uint32_t ah[4][4];
            uint32_t bh[2][4];
#pragma unroll
            for (int mi = 0; mi < 4; mi++) {
                ldsm_x4(ah[mi], Ah + (wm + mi * 16 + lrow) * BKP + kk + lcol);
            }
#pragma unroll
            for (int nb = 0; nb < 2; nb++) {
                ldsm_x4(bh[nb], Bh + (wn + nb * 16 + lrow) * BKP + kk + lcol);
            }
#pragma unroll
            for (int mi = 0; mi < 4; mi++) {
#pragma unroll
                for (int nj = 0; nj < 4; nj++) {
                    const int nb = nj >> 1;
                    const int ns = nj & 1;
                    mma16816(acc[mi][nj], ah[mi], bh[nb][ns], bh[nb][ns + 2]);
                }
            }
        }
        st = st + 1;
        if (st == 3) st = 0;
    }

#pragma unroll
    for (int mi = 0; mi < 4; mi++) {
#pragma unroll
        for (int nj = 0; nj < 4; nj++) {
            int row = row0 + wm + mi * 16 + (lane >> 2);
            int col = col0 + wn + nj * 8 + (lane & 3) * 2;
            float b0 = bias[col];
            float b1 = bias[col + 1];
            float v00 = acc[mi][nj][0] + b0;
            float v01 = acc[mi][nj][1] + b1;
            float v10 = acc[mi][nj][2] + b0;
            float v11 = acc[mi][nj][3] + b1;
            if (Ch) {
                *(uint32_t*)(Ch + (size_t)row * N + col) =
                    pack_h(v00 * oscale, v01 * oscale);
                *(uint32_t*)(Ch + (size_t)(row + 8) * N + col) =
                    pack_h(v10 * oscale, v11 * oscale);
            } else {
                float2 r0;
                float2 r1;
                r0.x = v00; r0.y = v01;
                r1.x = v10; r1.y = v11;
                *(float2*)(C + (size_t)row * N + col) = r0;
                *(float2*)(C + (size_t)(row + 8) * N + col) = r1;
            }
        }
    }
}

// merged Q/K/V projection: grid.x in [0,48): 0-31 Q tiles, 32-39 K, 40-47 V
__global__ __launch_bounds__(256)
void gemm_qkv(const __half* __restrict__ xh,
              const __half* __restrict__ qwh,
              const __half* __restrict__ kwh,
              const __half* __restrict__ vwh,
              const float* __restrict__ q_b,
              const float* __restrict__ k_b,
              const float* __restrict__ v_b,
              __half* __restrict__ qh,
              __half* __restrict__ kh,
              __half* __restrict__ vh,
              float qscale)
{
    const int bx = blockIdx.x;
    const int row0 = blockIdx.y * 128;

    if (bx < 32) {
        gemm_body(xh, qwh, q_b, (float*)0, qh, qscale, EMB, EMB, row0, bx * 128);
    } else if (bx < 40) {
        gemm_body(xh, kwh, k_b, (float*)0, kh, 1.0f, KVD, EMB, row0,
                  (bx - 32) * 128);
    } else {
        gemm_body(xh, vwh, v_b, (float*)0, vh, 1.0f, KVD, EMB, row0,
                  (bx - 40) * 128);
    }
}

// O projection (fp32 out)
__global__ __launch_bounds__(256)
void gemm_oproj(const __half* __restrict__ ah,
                const __half* __restrict__ owh,
                const float* __restrict__ o_b,
                float* __restrict__ out)
{
    gemm_body(ah, owh, o_b, out, (__half*)0, 1.0f, EMB, EMB,
              blockIdx.y * 128, blockIdx.x * 128);
}

// ============================================================================
// Split-KV flash attention (mma.sync fp16 single-pass), base-2 softermax.
// Grid (16, 32, 2): 128-query tile x head x KV-half. fp32 partials out.
// ============================================================================
#define KVP 136
#define FSTG (2 * 64 * KVP)                // K + V per stage (halves)
#define FL_SMEM_BYTES (2 * FSTG * 2)       // 69632

__global__ __launch_bounds__(256)
void flash_mma()
{
    extern __shared__ __half smf[];

    const int tid  = threadIdx.x;
    const int warp = tid >> 5;
    const int lane = tid & 31;
    const int lrow = lane & 15;
    const int lcol = (lane >> 4) * 8;
    const int wq   = warp * 16;

    const int h   = blockIdx.y;
    const int hk  = h >> 2;
    const int q0  = blockIdx.x * 128;
    const int z   = blockIdx.z;
    const int kt0 = z * 16;

    // stage Q (uses both KV stages' area), pull fragments
    {
        __half* Qs = smf;
        for (int idx = tid; idx < 128 * 16; idx += 256) {
            int r = idx >> 4;
            int c = (idx & 15) * 8;
            size_t g = (size_t)(q0 + r) * EMB + h * HD + c;
            *(uint4*)&Qs[r * KVP + c] = *(const uint4*)(g_qh + g);
        }
    }
    __syncthreads();

    uint32_t qf[8][4];
    {
        const __half* Qs = smf;
#pragma unroll
        for (int ks = 0; ks < 8; ks++) {
            ldsm_x4(qf[ks], Qs + (wq + lrow) * KVP + ks * 16 + lcol);
        }
    }
    __syncthreads();

#define FPREFETCH(st, kt)                                                     \
    do {                                                                      \
        __half* sb = smf + (st) * FSTG;                                       \
        _Pragma("unroll")                                                     \
        for (int it = 0; it < 4; it++) {                                      \
            int idx = tid + it * 256;                                         \
            int r = idx >> 4;                                                 \
            int c = (idx & 15) * 8;                                           \
            size_t g = (size_t)((kt) * 64 + r) * KVD + hk * HD + c;           \
            uint32_t d0 = smaddr(sb + r * KVP + c);                           \
            cp16(d0,                g_kh + g);                                \
            cp16(d0 + 64 * KVP * 2, g_vh + g);                                \
        }                                                                     \
    } while (0)

    FPREFETCH(0, kt0);
    cp_commit();

    float o[16][4];
#pragma unroll
    for (int i = 0; i < 16; i++)
#pragma unroll
        for (int r = 0; r < 4; r++)
            o[i][r] = 0.0f;

    float m1 = -1e30f;
    float m2 = -1e30f;
    float l1 = 0.0f;
    float l2 = 0.0f;

    int st = 0;
    for (int kt = kt0; kt < kt0 + 16; kt++) {
        cp_wait<0>();
        __syncthreads();
        if (kt + 1 < kt0 + 16) {
            FPREFETCH(st ^ 1, kt + 1);
            cp_commit();
        }

        const __half* Kh = smf + st * FSTG;
        const __half* Vh = Kh + 64 * KVP;

        // ---- S = Q K^T ----
        float s[8][4];
#pragma unroll
        for (int t = 0; t < 8; t++)
#pragma unroll
            for (int r = 0; r < 4; r++)
                s[t][r] = 0.0f;

#pragma unroll
        for (int ks = 0; ks < 8; ks++) {
#pragma unroll
            for (int nsl = 0; nsl < 4; nsl++) {
                uint32_t kf[4];
                ldsm_x4(kf, Kh + (nsl * 16 + lrow) * KVP + ks * 16 + lcol);
                mma16816(s[nsl * 2],     qf[ks], kf[0], kf[2]);
                mma16816(s[nsl * 2 + 1], qf[ks], kf[1], kf[3]);
            }
        }

        // ---- online base-2 softmax ----
        float mx1 = -1e30f;
        float mx2 = -1e30f;
#pragma unroll
        for (int t = 0; t < 8; t++) {
            mx1 = fmaxf(mx1, fmaxf(s[t][0], s[t][1]));
            mx2 = fmaxf(mx2, fmaxf(s[t][2], s[t][3]));
        }
        mx1 = fmaxf(mx1, __shfl_xor_sync(0xffffffffu, mx1, 1));
        mx1 = fmaxf(mx1, __shfl_xor_sync(0xffffffffu, mx1, 2));
        mx2 = fmaxf(mx2, __shfl_xor_sync(0xffffffffu, mx2, 1));
        mx2 = fmaxf(mx2, __shfl_xor_sync(0xffffffffu, mx2, 2));

        float newm1 = fmaxf(m1, mx1);
        float newm2 = fmaxf(m2, mx2);
        float corr1 = exp2f(m1 - newm1);
        float corr2 = exp2f(m2 - newm2);
        m1 = newm1;
        m2 = newm2;

        float ps1 = 0.0f;
        float ps2 = 0.0f;
#pragma unroll
        for (int t = 0; t < 8; t++) {
            s[t][0] = exp2f(s[t][0] - newm1);
            s[t][1] = exp2f(s[t][1] - newm1);
            s[t][2] = exp2f(s[t][2] - newm2);
            s[t][3] = exp2f(s[t][3] - newm2);
            ps1 += s[t][0] + s[t][1];
            ps2 += s[t][2] + s[t][3];
        }
        l1 = l1 * corr1 + ps1;
        l2 = l2 * corr2 + ps2;

#pragma unroll
        for (int i = 0; i < 16; i++) {
            o[i][0] *= corr1;
            o[i][1] *= corr1;
            o[i][2] *= corr2;
            o[i][3] *= corr2;
        }

        // ---- O += P V (V via ldmatrix.trans) ----
#pragma unroll
        for (int ks2 = 0; ks2 < 4; ks2++) {
            uint32_t ph[4];
            ph[0] = pack_h(s[2 * ks2][0],     s[2 * ks2][1]);
            ph[1] = pack_h(s[2 * ks2][2],     s[2 * ks2][3]);
            ph[2] = pack_h(s[2 * ks2 + 1][0], s[2 * ks2 + 1][1]);
            ph[3] = pack_h(s[2 * ks2 + 1][2], s[2 * ks2 + 1][3]);
#pragma unroll
            for (int dsl = 0; dsl < 8; dsl++) {
                uint32_t vf[4];
                ldsm_x4t(vf, Vh + (ks2 * 16 + lrow) * KVP + dsl * 16 + lcol);
                mma16816(o[dsl * 2],     ph, vf[0], vf[1]);
                mma16816(o[dsl * 2 + 1], ph, vf[2], vf[3]);
            }
        }
        st ^= 1;
    }

    // ---- write fp32 partials + (m, l) ----
    l1 += __shfl_xor_sync(0xffffffffu, l1, 1);
    l1 += __shfl_xor_sync(0xffffffffu, l1, 2);
    l2 += __shfl_xor_sync(0xffffffffu, l2, 1);
    l2 += __shfl_xor_sync(0xffffffffu, l2, 2);

    const int row1 = q0 + wq + (lane >> 2);
    const int row2 = row1 + 8;
    const size_t zo = (size_t)z * SEQ * EMB;

    if ((lane & 3) == 0) {
        int mo = z * NH * SEQ + h * SEQ;
        g_pm[mo + row1] = m1;
        g_pl[mo + row1] = l1;
        g_pm[mo + row2] = m2;
        g_pl[mo + row2] = l2;
    }

#pragma unroll
    for (int nt = 0; nt < 16; nt++) {
        int col = h * HD + nt * 8 + (lane & 3) * 2;
        float2 r0;
        float2 r1;
        r0.x = o[nt][0];
        r0.y = o[nt][1];
        r1.x = o[nt][2];
        r1.y = o[nt][3];
        *(float2*)(g_po + zo + (size_t)row1 * EMB + col) = r0;
        *(float2*)(g_po + zo + (size_t)row2 * EMB + col) = r1;
    }
}

// ============================================================================
// combine KV halves -> fp16 attention output
// ============================================================================
__global__ __launch_bounds__(256)
void attn_combine()
{
    int idx = blockIdx.x * blockDim.x + threadIdx.x;   // < SEQ*EMB/2
    int row  = idx >> 11;
    int pc   = idx & 2047;
    int col  = pc * 2;
    int head = col >> 7;

    int mo = head * SEQ + row;
    float m1 = g_pm[mo];
    float l1 = g_pl[mo];
    float m2 = g_pm[NH * SEQ + mo];
    float l2 = g_pl[NH * SEQ + mo];

    float mm = fmaxf(m1, m2);
    float w1 = exp2f(m1 - mm);
    float w2 = exp2f(m2 - mm);
    float inv = 1.0f / (w1 * l1 + w2 * l2);
    w1 *= inv;
    w2 *= inv;

    size_t off = (size_t)row * EMB + col;
    float2 o1 = *(const float2*)(g_po + off);
    float2 o2 = *(const float2*)(g_po + (size_t)SEQ * EMB + off);

    float v0 = w1 * o1.x + w2 * o2.x;
    float v1 = w1 * o1.y + w2 * o2.y;
    *(uint32_t*)(g_ah + off) = pack_h(v0, v1);
}

// ============================================================================
// launch
// ============================================================================
extern "C" void kernel_launch(void* const* d_in, const int* in_sizes, int n_in,
                              void* d_out, int out_size)
{
    const float* x   = (const float*)d_in[0];
    const float* q_w = (const float*)d_in[1];
    const float* q_b = (const float*)d_in[2];
    const float* k_w = (const float*)d_in[3];
    const float* k_b = (const float*)d_in[4];
    const float* v_w = (const float*)d_in[5];
    const float* v_b = (const float*)d_in[6];
    const float* o_w = (const float*)d_in[7];
    const float* o_b = (const float*)d_in[8];
    float* out = (float*)d_out;

    __half* xh = 0;
    __half* qwh = 0;
    __half* kwh = 0;
    __half* vwh = 0;
    __half* owh = 0;
    __half* qh = 0;
    __half* kh = 0;
    __half* vh = 0;
    __half* ah = 0;
    cudaGetSymbolAddress((void**)&xh,  g_xh);
    cudaGetSymbolAddress((void**)&qwh, g_qwh);
    cudaGetSymbolAddress((void**)&kwh, g_kwh);
    cudaGetSymbolAddress((void**)&vwh, g_vwh);
    cudaGetSymbolAddress((void**)&owh, g_owh);
    cudaGetSymbolAddress((void**)&qh,  g_qh);
    cudaGetSymbolAddress((void**)&kh,  g_kh);
    cudaGetSymbolAddress((void**)&vh,  g_vh);
    cudaGetSymbolAddress((void**)&ah,  g_ah);

    cudaFuncSetAttribute(gemm_qkv,
                         cudaFuncAttributeMaxDynamicSharedMemorySize,
                         GEMM_SMEM_BYTES);
    cudaFuncSetAttribute(gemm_oproj,
                         cudaFuncAttributeMaxDynamicSharedMemorySize,
                         GEMM_SMEM_BYTES);
    cudaFuncSetAttribute(flash_mma,
                         cudaFuncAttributeMaxDynamicSharedMemorySize,
                         FL_SMEM_BYTES);

    dim3 blk(256);
    const float qscale = 0.08838834764831845f;   // 1/sqrt(128)

    cvt_all<<<49152, 256>>>((const float4*)x, (const float4*)q_w,
                            (const float4*)k_w, (const float4*)v_w,
                            (const float4*)o_w,
                            (uint32_t*)xh, (uint32_t*)qwh, (uint32_t*)kwh,
                            (uint32_t*)vwh, (uint32_t*)owh);

    gemm_qkv<<<dim3(48, 16), blk, GEMM_SMEM_BYTES>>>(
        xh, qwh, kwh, vwh, q_b, k_b, v_b, qh, kh, vh, qscale);

    flash_mma<<<dim3(16, 32, 2), blk, FL_SMEM_BYTES>>>();
    attn_combine<<<(SEQ * EMB / 2) / 256, 256>>>();

    gemm_oproj<<<dim3(32, 16), blk, GEMM_SMEM_BYTES>>>(ah, owh, o_b, out);
}

// round 10
// speedup vs baseline: 7.1954x; 1.0551x over previous
#include <cuda_runtime.h>
#include <cuda_fp16.h>
#include <cstdint>
#include <math.h>

#define SEQ   2048
#define EMB   4096
#define KVD   1024
#define NH    32
#define HD    128

// -------- scratch (device globals; no allocation allowed) --------
__device__ __half g_xh[SEQ * EMB];
__device__ __half g_qwh[EMB * EMB];
__device__ __half g_kwh[KVD * EMB];
__device__ __half g_vwh[KVD * EMB];
__device__ __half g_owh[EMB * EMB];

__device__ __half g_qh[SEQ * EMB];          // scaled Q
__device__ __half g_kh[SEQ * KVD];
__device__ __half g_vh[SEQ * KVD];
__device__ __half g_ah[SEQ * EMB];          // attention out

// split-KV attention partials
__device__ float g_po[2 * SEQ * EMB];
__device__ float g_pm[2 * NH * SEQ];
__device__ float g_pl[2 * NH * SEQ];

// ============================================================================
// helpers
// ============================================================================
__device__ __forceinline__ uint32_t smaddr(const void* p)
{
    return (uint32_t)__cvta_generic_to_shared(p);
}

__device__ __forceinline__ void cp16(uint32_t dst, const void* src)
{
    asm volatile("cp.async.cg.shared.global [%0], [%1], 16;"
                 :: "r"(dst), "l"(src));
}

__device__ __forceinline__ void cp_commit()
{
    asm volatile("cp.async.commit_group;");
}

template <int N>
__device__ __forceinline__ void cp_wait()
{
    asm volatile("cp.async.wait_group %0;" :: "n"(N));
}

__device__ __forceinline__ void ldsm_x4(uint32_t* r, const __half* p)
{
    uint32_t addr = smaddr(p);
    asm volatile("ldmatrix.sync.aligned.m8n8.x4.shared.b16 {%0,%1,%2,%3}, [%4];"
                 : "=r"(r[0]), "=r"(r[1]), "=r"(r[2]), "=r"(r[3])
                 : "r"(addr));
}

__device__ __forceinline__ void ldsm_x4t(uint32_t* r, const __half* p)
{
    uint32_t addr = smaddr(p);
    asm volatile("ldmatrix.sync.aligned.m8n8.x4.trans.shared.b16 {%0,%1,%2,%3}, [%4];"
                 : "=r"(r[0]), "=r"(r[1]), "=r"(r[2]), "=r"(r[3])
                 : "r"(addr));
}

__device__ __forceinline__ void mma16816(float* c, const uint32_t* a,
                                         uint32_t b0, uint32_t b1)
{
    asm volatile(
        "mma.sync.aligned.m16n8k16.row.col.f32.f16.f16.f32 "
        "{%0,%1,%2,%3}, {%4,%5,%6,%7}, {%8,%9}, {%0,%1,%2,%3};"
        : "+f"(c[0]), "+f"(c[1]), "+f"(c[2]), "+f"(c[3])
        : "r"(a[0]), "r"(a[1]), "r"(a[2]), "r"(a[3]), "r"(b0), "r"(b1));
}

__device__ __forceinline__ uint32_t pack_h(float a, float b)
{
    __half2 t = __halves2half2(__float2half_rn(a), __float2half_rn(b));
    return *(uint32_t*)&t;
}

__device__ __forceinline__ void single_store(const float4* in, uint32_t* hi, int i)
{
    float4 v = in[i];
    hi[i * 2 + 0] = pack_h(v.x, v.y);
    hi[i * 2 + 1] = pack_h(v.z, v.w);
}

// ============================================================================
// merged fp32 -> fp16 conversion (all tensors single fp16)
// float4 ranges: x 2097152 | qw 4194304 | kw 1048576 | vw 1048576 | ow 4194304
// ============================================================================
__global__ __launch_bounds__(256)
void cvt_all(const float4* __restrict__ x,  const float4* __restrict__ qw,
             const float4* __restrict__ kw, const float4* __restrict__ vw,
             const float4* __restrict__ ow,
             uint32_t* xh, uint32_t* qwh, uint32_t* kwh, uint32_t* vwh,
             uint32_t* owh)
{
    int i = blockIdx.x * blockDim.x + threadIdx.x;
    if (i < 2097152) {
        single_store(x, xh, i);
    } else if (i < 6291456) {
        single_store(qw, qwh, i - 2097152);
    } else if (i < 7340032) {
        single_store(kw, kwh, i - 6291456);
    } else if (i < 8388608) {
        single_store(vw, vwh, i - 7340032);
    } else if (i < 12582912) {
        single_store(ow, owh, i - 8388608);
    }
}

// ============================================================================
// fp16 single-pass GEMM (NT): C = A @ B^T + bias (fp32 accum).
// 3-stage cp.async pipeline. Block tile 128x128x32, 256 threads, warp 64x32.
// Output: Ch -> fp16 (scaled by oscale); else fp32 C.
// ============================================================================
#define BKP 40
#define GSTG (2 * 128 * BKP)
#define GEMM_SMEM_BYTES (3 * GSTG * 2)   // 61440

__device__ __forceinline__
void gemm_body(const __half* __restrict__ Ahg,
               const __half* __restrict__ Bhg,
               const float* __restrict__ bias,
               float* __restrict__ C,
               __half* __restrict__ Ch,
               float oscale, int N, int K, int row0, int col0)
{
    extern __shared__ __half smg[];

    const int tid  = threadIdx.x;
    const int warp = tid >> 5;
    const int lane = tid & 31;
    const int wm = (warp >> 2) * 64;
    const int wn = (warp & 3) * 32;

    const int lr = tid >> 1;
    const int lc = (tid & 1) * 16;

    const __half* pAh = Ahg + (size_t)(row0 + lr) * K + lc;
    const __half* pBh = Bhg + (size_t)(col0 + lr) * K + lc;

    const int dstoff = lr * BKP + lc;

    float acc[4][4][4];
#pragma unroll
    for (int i = 0; i < 4; i++)
#pragma unroll
        for (int j = 0; j < 4; j++)
#pragma unroll
            for (int r = 0; r < 4; r++)
                acc[i][j][r] = 0.0f;

    const int lrow = lane & 15;
    const int lcol = (lane >> 4) * 8;

#define GPREFETCH(st, k0)                                                     \
    do {                                                                      \
        __half* sb = smg + (st) * GSTG + dstoff;                              \
        uint32_t d0 = smaddr(sb);                                             \
        cp16(d0,                      pAh + (k0));                            \
        cp16(d0 + 16,                 pAh + (k0) + 8);                        \
        cp16(d0 + 128 * BKP * 2,      pBh + (k0));                            \
        cp16(d0 + 128 * BKP * 2 + 16, pBh + (k0) + 8);                        \
    } while (0)

    GPREFETCH(0, 0);
    cp_commit();
    GPREFETCH(1, 32);
    cp_commit();

    int st = 0;
    for (int k0 = 0; k0 < K; k0 += 32) {
        if (k0 + 32 < K) cp_wait<1>(); else cp_wait<0>();
        __syncthreads();
        if (k0 + 64 < K) {
            int st2 = st + 2;
            if (st2 >= 3) st2 -= 3;
            GPREFETCH(st2, k0 + 64);
            cp_commit();
        }

        const __half* Ah = smg + st * GSTG;
        const __half* Bh = Ah + 128 * BKP;

#pragma unroll
        for (int ks = 0; ks < 2; ks++) {
            const int kk = ks * 16;
            uint32_t ah[4][4];
            uint32_t bh[2][4];
#pragma unroll
            for (int mi = 0; mi < 4; mi++) {
                ldsm_x4(ah[mi], Ah + (wm + mi * 16 + lrow) * BKP + kk + lcol);
            }
#pragma unroll
            for (int nb = 0; nb < 2; nb++) {
                ldsm_x4(bh[nb], Bh + (wn + nb * 16 + lrow) * BKP + kk + lcol);
            }
#pragma unroll
            for (int mi = 0; mi < 4; mi++) {
#pragma unroll
                for (int nj = 0; nj < 4; nj++) {
                    const int nb = nj >> 1;
                    const int ns = nj & 1;
                    mma16816(acc[mi][nj], ah[mi], bh[nb][ns], bh[nb][ns + 2]);
                }
            }
        }
        st = st + 1;
        if (st == 3) st = 0;
    }

#pragma unroll
    for (int mi = 0; mi < 4; mi++) {
#pragma unroll
        for (int nj = 0; nj < 4; nj++) {
            int row = row0 + wm + mi * 16 + (lane >> 2);
            int col = col0 + wn + nj * 8 + (lane & 3) * 2;
            float b0 = bias[col];
            float b1 = bias[col + 1];
            float v00 = acc[mi][nj][0] + b0;
            float v01 = acc[mi][nj][1] + b1;
            float v10 = acc[mi][nj][2] + b0;
            float v11 = acc[mi][nj][3] + b1;
            if (Ch) {
                *(uint32_t*)(Ch + (size_t)row * N + col) =
                    pack_h(v00 * oscale, v01 * oscale);
                *(uint32_t*)(Ch + (size_t)(row + 8) * N + col) =
                    pack_h(v10 * oscale, v11 * oscale);
            } else {
                float2 r0;
                float2 r1;
                r0.x = v00; r0.y = v01;
                r1.x = v10; r1.y = v11;
                *(float2*)(C + (size_t)row * N + col) = r0;
                *(float2*)(C + (size_t)(row + 8) * N + col) = r1;
            }
        }
    }
}

// merged Q/K/V projection: grid.x in [0,48): 0-31 Q tiles, 32-39 K, 40-47 V
__global__ __launch_bounds__(256, 2)
void gemm_qkv(const __half* __restrict__ xh,
              const __half* __restrict__ qwh,
              const __half* __restrict__ kwh,
              const __half* __restrict__ vwh,
              const float* __restrict__ q_b,
              const float* __restrict__ k_b,
              const float* __restrict__ v_b,
              __half* __restrict__ qh,
              __half* __restrict__ kh,
              __half* __restrict__ vh,
              float qscale)
{
    const int bx = blockIdx.x;
    const int row0 = blockIdx.y * 128;

    if (bx < 32) {
        gemm_body(xh, qwh, q_b, (float*)0, qh, qscale, EMB, EMB, row0, bx * 128);
    } else if (bx < 40) {
        gemm_body(xh, kwh, k_b, (float*)0, kh, 1.0f, KVD, EMB, row0,
                  (bx - 32) * 128);
    } else {
        gemm_body(xh, vwh, v_b, (float*)0, vh, 1.0f, KVD, EMB, row0,
                  (bx - 40) * 128);
    }
}

// O projection (fp32 out)
__global__ __launch_bounds__(256, 2)
void gemm_oproj(const __half* __restrict__ ah,
                const __half* __restrict__ owh,
                const float* __restrict__ o_b,
                float* __restrict__ out)
{
    gemm_body(ah, owh, o_b, out, (__half*)0, 1.0f, EMB, EMB,
              blockIdx.y * 128, blockIdx.x * 128);
}

// ============================================================================
// Split-KV flash attention (mma.sync fp16 single-pass), base-2 softermax.
// Q held in a persistent smem region (fragments re-ldsm'd each tile) to cut
// registers and allow 2 CTAs/SM. Grid (16, 32, 2). fp32 partials out.
// ============================================================================
#define KVP 136
#define QBYTES (128 * KVP * 2)             // persistent Q region: 34816
#define FSTG (2 * 64 * KVP)                // K + V per stage (halves)
#define FL_SMEM_BYTES (QBYTES + 2 * FSTG * 2)   // 104448

__global__ __launch_bounds__(256, 2)
void flash_mma()
{
    extern __shared__ __half smf[];
    __half* Qs = smf;                       // persistent [128][KVP]
    __half* KV = smf + 128 * KVP;           // 2 stages of K|V

    const int tid  = threadIdx.x;
    const int warp = tid >> 5;
    const int lane = tid & 31;
    const int lrow = lane & 15;
    const int lcol = (lane >> 4) * 8;
    const int wq   = warp * 16;

    const int h   = blockIdx.y;
    const int hk  = h >> 2;
    const int q0  = blockIdx.x * 128;
    const int z   = blockIdx.z;
    const int kt0 = z * 16;

    // stage Q into its persistent region
    for (int idx = tid; idx < 128 * 16; idx += 256) {
        int r = idx >> 4;
        int c = (idx & 15) * 8;
        size_t g = (size_t)(q0 + r) * EMB + h * HD + c;
        *(uint4*)&Qs[r * KVP + c] = *(const uint4*)(g_qh + g);
    }

#define FPREFETCH(st, kt)                                                     \
    do {                                                                      \
        __half* sb = KV + (st) * FSTG;                                        \
        _Pragma("unroll")                                                     \
        for (int it = 0; it < 4; it++) {                                      \
            int idx = tid + it * 256;                                         \
            int r = idx >> 4;                                                 \
            int c = (idx & 15) * 8;                                           \
            size_t g = (size_t)((kt) * 64 + r) * KVD + hk * HD + c;           \
            uint32_t d0 = smaddr(sb + r * KVP + c);                           \
            cp16(d0,                g_kh + g);                                \
            cp16(d0 + 64 * KVP * 2, g_vh + g);                                \
        }                                                                     \
    } while (0)

    FPREFETCH(0, kt0);
    cp_commit();
    __syncthreads();   // Q staged (also covers stage-0 owner sync via wait below)

    float o[16][4];
#pragma unroll
    for (int i = 0; i < 16; i++)
#pragma unroll
        for (int r = 0; r < 4; r++)
            o[i][r] = 0.0f;

    float m1 = -1e30f;
    float m2 = -1e30f;
    float l1 = 0.0f;
    float l2 = 0.0f;

    int st = 0;
    for (int kt = kt0; kt < kt0 + 16; kt++) {
        cp_wait<0>();
        __syncthreads();
        if (kt + 1 < kt0 + 16) {
            FPREFETCH(st ^ 1, kt + 1);
            cp_commit();
        }

        const __half* Kh = KV + st * FSTG;
        const __half* Vh = Kh + 64 * KVP;

        // ---- S = Q K^T (Q fragments re-ldsm'd from smem) ----
        float s[8][4];
#pragma unroll
        for (int t = 0; t < 8; t++)
#pragma unroll
            for (int r = 0; r < 4; r++)
                s[t][r] = 0.0f;

#pragma unroll
        for (int ks = 0; ks < 8; ks++) {
            uint32_t qf[4];
            ldsm_x4(qf, Qs + (wq + lrow) * KVP + ks * 16 + lcol);
#pragma unroll
            for (int nsl = 0; nsl < 4; nsl++) {
                uint32_t kf[4];
                ldsm_x4(kf, Kh + (nsl * 16 + lrow) * KVP + ks * 16 + lcol);
                mma16816(s[nsl * 2],     qf, kf[0], kf[2]);
                mma16816(s[nsl * 2 + 1], qf, kf[1], kf[3]);
            }
        }

        // ---- online base-2 softmax ----
        float mx1 = -1e30f;
        float mx2 = -1e30f;
#pragma unroll
        for (int t = 0; t < 8; t++) {
            mx1 = fmaxf(mx1, fmaxf(s[t][0], s[t][1]));
            mx2 = fmaxf(mx2, fmaxf(s[t][2], s[t][3]));
        }
        mx1 = fmaxf(mx1, __shfl_xor_sync(0xffffffffu, mx1, 1));
        mx1 = fmaxf(mx1, __shfl_xor_sync(0xffffffffu, mx1, 2));
        mx2 = fmaxf(mx2, __shfl_xor_sync(0xffffffffu, mx2, 1));
        mx2 = fmaxf(mx2, __shfl_xor_sync(0xffffffffu, mx2, 2));

        float newm1 = fmaxf(m1, mx1);
        float newm2 = fmaxf(m2, mx2);
        float corr1 = exp2f(m1 - newm1);
        float corr2 = exp2f(m2 - newm2);
        m1 = newm1;
        m2 = newm2;

        float ps1 = 0.0f;
        float ps2 = 0.0f;
#pragma unroll
        for (int t = 0; t < 8; t++) {
            s[t][0] = exp2f(s[t][0] - newm1);
            s[t][1] = exp2f(s[t][1] - newm1);
            s[t][2] = exp2f(s[t][2] - newm2);
            s[t][3] = exp2f(s[t][3] - newm2);
            ps1 += s[t][0] + s[t][1];
            ps2 += s[t][2] + s[t][3];
        }
        l1 = l1 * corr1 + ps1;
        l2 = l2 * corr2 + ps2;

#pragma unroll
        for (int i = 0; i < 16; i++) {
            o[i][0] *= corr1;
            o[i][1] *= corr1;
            o[i][2] *= corr2;
            o[i][3] *= corr2;
        }

        // ---- O += P V (V via ldmatrix.trans) ----
#pragma unroll
        for (int ks2 = 0; ks2 < 4; ks2++) {
            uint32_t ph[4];
            ph[0] = pack_h(s[2 * ks2][0],     s[2 * ks2][1]);
            ph[1] = pack_h(s[2 * ks2][2],     s[2 * ks2][3]);
            ph[2] = pack_h(s[2 * ks2 + 1][0], s[2 * ks2 + 1][1]);
            ph[3] = pack_h(s[2 * ks2 + 1][2], s[2 * ks2 + 1][3]);
#pragma unroll
            for (int dsl = 0; dsl < 8; dsl++) {
                uint32_t vf[4];
                ldsm_x4t(vf, Vh + (ks2 * 16 + lrow) * KVP + dsl * 16 + lcol);
                mma16816(o[dsl * 2],     ph, vf[0], vf[1]);
                mma16816(o[dsl * 2 + 1], ph, vf[2], vf[3]);
            }
        }
        st ^= 1;
    }

    // ---- write fp32 partials + (m, l) ----
    l1 += __shfl_xor_sync(0xffffffffu, l1, 1);
    l1 += __shfl_xor_sync(0xffffffffu, l1, 2);
    l2 += __shfl_xor_sync(0xffffffffu, l2, 1);
    l2 += __shfl_xor_sync(0xffffffffu, l2, 2);

    const int row1 = q0 + wq + (lane >> 2);
    const int row2 = row1 + 8;
    const size_t zo = (size_t)z * SEQ * EMB;

    if ((lane & 3) == 0) {
        int mo = z * NH * SEQ + h * SEQ;
        g_pm[mo + row1] = m1;
        g_pl[mo + row1] = l1;
        g_pm[mo + row2] = m2;
        g_pl[mo + row2] = l2;
    }

#pragma unroll
    for (int nt = 0; nt < 16; nt++) {
        int col = h * HD + nt * 8 + (lane & 3) * 2;
        float2 r0;
        float2 r1;
        r0.x = o[nt][0];
        r0.y = o[nt][1];
        r1.x = o[nt][2];
        r1.y = o[nt][3];
        *(float2*)(g_po + zo + (size_t)row1 * EMB + col) = r0;
        *(float2*)(g_po + zo + (size_t)row2 * EMB + col) = r1;
    }
}

// ============================================================================
// combine KV halves -> fp16 attention output (float4 vectorized)
// one thread = 4 consecutive cols; total SEQ*EMB/4 threads
// ============================================================================
__global__ __launch_bounds__(256)
void attn_combine()
{
    int idx = blockIdx.x * blockDim.x + threadIdx.x;   // < SEQ*EMB/4
    int row  = idx >> 10;          // EMB/4 = 1024 quads per row
    int qc   = idx & 1023;
    int col  = qc * 4;
    int head = col >> 7;

    int mo = head * SEQ + row;
    float m1 = g_pm[mo];
    float l1 = g_pl[mo];
    float m2 = g_pm[NH * SEQ + mo];
    float l2 = g_pl[NH * SEQ + mo];

    float mm = fmaxf(m1, m2);
    float w1 = exp2f(m1 - mm);
    float w2 = exp2f(m2 - mm);
    float inv = 1.0f / (w1 * l1 + w2 * l2);
    w1 *= inv;
    w2 *= inv;

    size_t off = (size_t)row * EMB + col;
    float4 o1 = *(const float4*)(g_po + off);
    float4 o2 = *(const float4*)(g_po + (size_t)SEQ * EMB + off);

    uint2 r;
    r.x = pack_h(w1 * o1.x + w2 * o2.x, w1 * o1.y + w2 * o2.y);
    r.y = pack_h(w1 * o1.z + w2 * o2.z, w1 * o1.w + w2 * o2.w);
    *(uint2*)(g_ah + off) = r;
}

// ============================================================================
// launch
// ============================================================================
extern "C" void kernel_launch(void* const* d_in, const int* in_sizes, int n_in,
                              void* d_out, int out_size)
{
    const float* x   = (const float*)d_in[0];
    const float* q_w = (const float*)d_in[1];
    const float* q_b = (const float*)d_in[2];
    const float* k_w = (const float*)d_in[3];
    const float* k_b = (const float*)d_in[4];
    const float* v_w = (const float*)d_in[5];
    const float* v_b = (const float*)d_in[6];
    const float* o_w = (const float*)d_in[7];
    const float* o_b = (const float*)d_in[8];
    float* out = (float*)d_out;

    __half* xh = 0;
    __half* qwh = 0;
    __half* kwh = 0;
    __half* vwh = 0;
    __half* owh = 0;
    __half* qh = 0;
    __half* kh = 0;
    __half* vh = 0;
    __half* ah = 0;
    cudaGetSymbolAddress((void**)&xh,  g_xh);
    cudaGetSymbolAddress((void**)&qwh, g_qwh);
    cudaGetSymbolAddress((void**)&kwh, g_kwh);
    cudaGetSymbolAddress((void**)&vwh, g_vwh);
    cudaGetSymbolAddress((void**)&owh, g_owh);
    cudaGetSymbolAddress((void**)&qh,  g_qh);
    cudaGetSymbolAddress((void**)&kh,  g_kh);
    cudaGetSymbolAddress((void**)&vh,  g_vh);
    cudaGetSymbolAddress((void**)&ah,  g_ah);

    cudaFuncSetAttribute(gemm_qkv,
                         cudaFuncAttributeMaxDynamicSharedMemorySize,
                         GEMM_SMEM_BYTES);
    cudaFuncSetAttribute(gemm_oproj,
                         cudaFuncAttributeMaxDynamicSharedMemorySize,
                         GEMM_SMEM_BYTES);
    cudaFuncSetAttribute(flash_mma,
                         cudaFuncAttributeMaxDynamicSharedMemorySize,
                         FL_SMEM_BYTES);

    dim3 blk(256);
    const float qscale = 0.08838834764831845f;   // 1/sqrt(128)

    cvt_all<<<49152, 256>>>((const float4*)x, (const float4*)q_w,
                            (const float4*)k_w, (const float4*)v_w,
                            (const float4*)o_w,
                            (uint32_t*)xh, (uint32_t*)qwh, (uint32_t*)kwh,
                            (uint32_t*)vwh, (uint32_t*)owh);

    gemm_qkv<<<dim3(48, 16), blk, GEMM_SMEM_BYTES>>>(
        xh, qwh, kwh, vwh, q_b, k_b, v_b, qh, kh, vh, qscale);

    flash_mma<<<dim3(16, 32, 2), blk, FL_SMEM_BYTES>>>();
    attn_combine<<<(SEQ * EMB / 4) / 256, 256>>>();

    gemm_oproj<<<dim3(32, 16), blk, GEMM_SMEM_BYTES>>>(ah, owh, o_b, out);
}

// round 11
// speedup vs baseline: 7.2739x; 1.0109x over previous
#include <cuda_runtime.h>
#include <cuda_fp16.h>
#include <cstdint>
#include <math.h>

#define SEQ   2048
#define EMB   4096
#define KVD   1024
#define NH    32
#define HD    128

// -------- scratch (device globals; no allocation allowed) --------
__device__ __half g_xh[SEQ * EMB];
__device__ __half g_qwh[EMB * EMB];
__device__ __half g_kwh[KVD * EMB];
__device__ __half g_vwh[KVD * EMB];
__device__ __half g_owh[EMB * EMB];

__device__ __half g_qh[SEQ * EMB];          // scaled Q
__device__ __half g_kh[SEQ * KVD];
__device__ __half g_vh[SEQ * KVD];
__device__ __half g_ah[SEQ * EMB];          // attention out

// split-KV attention partials
__device__ float g_po[2 * SEQ * EMB];
__device__ float g_pm[2 * NH * SEQ];
__device__ float g_pl[2 * NH * SEQ];

// ============================================================================
// helpers
// ============================================================================
__device__ __forceinline__ uint32_t smaddr(const void* p)
{
    return (uint32_t)__cvta_generic_to_shared(p);
}

__device__ __forceinline__ void cp16(uint32_t dst, const void* src)
{
    asm volatile("cp.async.cg.shared.global [%0], [%1], 16;"
                 :: "r"(dst), "l"(src));
}

__device__ __forceinline__ void cp_commit()
{
    asm volatile("cp.async.commit_group;");
}

template <int N>
__device__ __forceinline__ void cp_wait()
{
    asm volatile("cp.async.wait_group %0;" :: "n"(N));
}

__device__ __forceinline__ void ldsm_x4(uint32_t* r, const __half* p)
{
    uint32_t addr = smaddr(p);
    asm volatile("ldmatrix.sync.aligned.m8n8.x4.shared.b16 {%0,%1,%2,%3}, [%4];"
                 : "=r"(r[0]), "=r"(r[1]), "=r"(r[2]), "=r"(r[3])
                 : "r"(addr));
}

__device__ __forceinline__ void ldsm_x4t(uint32_t* r, const __half* p)
{
    uint32_t addr = smaddr(p);
    asm volatile("ldmatrix.sync.aligned.m8n8.x4.trans.shared.b16 {%0,%1,%2,%3}, [%4];"
                 : "=r"(r[0]), "=r"(r[1]), "=r"(r[2]), "=r"(r[3])
                 : "r"(addr));
}

__device__ __forceinline__ void mma16816(float* c, const uint32_t* a,
                                         uint32_t b0, uint32_t b1)
{
    asm volatile(
        "mma.sync.aligned.m16n8k16.row.col.f32.f16.f16.f32 "
        "{%0,%1,%2,%3}, {%4,%5,%6,%7}, {%8,%9}, {%0,%1,%2,%3};"
        : "+f"(c[0]), "+f"(c[1]), "+f"(c[2]), "+f"(c[3])
        : "r"(a[0]), "r"(a[1]), "r"(a[2]), "r"(a[3]), "r"(b0), "r"(b1));
}

__device__ __forceinline__ uint32_t pack_h(float a, float b)
{
    __half2 t = __halves2half2(__float2half_rn(a), __float2half_rn(b));
    return *(uint32_t*)&t;
}

__device__ __forceinline__ void single_store(const float4* in, uint32_t* hi, int i)
{
    float4 v = in[i];
    hi[i * 2 + 0] = pack_h(v.x, v.y);
    hi[i * 2 + 1] = pack_h(v.z, v.w);
}

// ============================================================================
// merged fp32 -> fp16 conversion; each thread converts 4 consecutive float4s
// (MLP=4). float4 region bounds: x 2097152 | qw 6291456 | kw 7340032 |
// vw 8388608 | ow 12582912.  grid*256*4 = 12582912.
// ============================================================================
__global__ __launch_bounds__(256)
void cvt_all(const float4* __restrict__ x,  const float4* __restrict__ qw,
             const float4* __restrict__ kw, const float4* __restrict__ vw,
             const float4* __restrict__ ow,
             uint32_t* xh, uint32_t* qwh, uint32_t* kwh, uint32_t* vwh,
             uint32_t* owh)
{
    int base = (blockIdx.x * blockDim.x + threadIdx.x) * 4;
    const float4* src;
    uint32_t* dst;
    int off;
    if (base < 2097152) {
        src = x;  dst = xh;  off = 0;
    } else if (base < 6291456) {
        src = qw; dst = qwh; off = 2097152;
    } else if (base < 7340032) {
        src = kw; dst = kwh; off = 6291456;
    } else if (base < 8388608) {
        src = vw; dst = vwh; off = 7340032;
    } else {
        src = ow; dst = owh; off = 8388608;
    }
    int i = base - off;
    float4 v0 = src[i];
    float4 v1 = src[i + 1];
    float4 v2 = src[i + 2];
    float4 v3 = src[i + 3];
    uint4 r0;
    uint4 r1;
    r0.x = pack_h(v0.x, v0.y);
    r0.y = pack_h(v0.z, v0.w);
    r0.z = pack_h(v1.x, v1.y);
    r0.w = pack_h(v1.z, v1.w);
    r1.x = pack_h(v2.x, v2.y);
    r1.y = pack_h(v2.z, v2.w);
    r1.z = pack_h(v3.x, v3.y);
    r1.w = pack_h(v3.z, v3.w);
    *(uint4*)(dst + i * 2)     = r0;
    *(uint4*)(dst + i * 2 + 4) = r1;
}

// ============================================================================
// fp16 single-pass GEMM (NT): C = A @ B^T + bias (fp32 accum).
// 3-stage cp.async pipeline. Block tile 128x128x32, 256 threads, warp 64x32.
// Output: Ch -> fp16 (scaled by oscale); else fp32 C.
// ============================================================================
#define BKP 40
#define GSTG (2 * 128 * BKP)
#define GEMM_SMEM_BYTES (3 * GSTG * 2)   // 61440

__device__ __forceinline__
void gemm_body(const __half* __restrict__ Ahg,
               const __half* __restrict__ Bhg,
               const float* __restrict__ bias,
               float* __restrict__ C,
               __half* __restrict__ Ch,
               float oscale, int N, int K, int row0, int col0)
{
    extern __shared__ __half smg[];

    const int tid  = threadIdx.x;
    const int warp = tid >> 5;
    const int lane = tid & 31;
    const int wm = (warp >> 2) * 64;
    const int wn = (warp & 3) * 32;

    const int lr = tid >> 1;
    const int lc = (tid & 1) * 16;

    const __half* pAh = Ahg + (size_t)(row0 + lr) * K + lc;
    const __half* pBh = Bhg + (size_t)(col0 + lr) * K + lc;

    const int dstoff = lr * BKP + lc;

    float acc[4][4][4];
#pragma unroll
    for (int i = 0; i < 4; i++)
#pragma unroll
        for (int j = 0; j < 4; j++)
#pragma unroll
            for (int r = 0; r < 4; r++)
                acc[i][j][r] = 0.0f;

    const int lrow = lane & 15;
    const int lcol = (lane >> 4) * 8;

#define GPREFETCH(st, k0)                                                     \
    do {                                                                      \
        __half* sb = smg + (st) * GSTG + dstoff;                              \
        uint32_t d0 = smaddr(sb);                                             \
        cp16(d0,                      pAh + (k0));                            \
        cp16(d0 + 16,                 pAh + (k0) + 8);                        \
        cp16(d0 + 128 * BKP * 2,      pBh + (k0));                            \
        cp16(d0 + 128 * BKP * 2 + 16, pBh + (k0) + 8);                        \
    } while (0)

    GPREFETCH(0, 0);
    cp_commit();
    GPREFETCH(1, 32);
    cp_commit();

    int st = 0;
    for (int k0 = 0; k0 < K; k0 += 32) {
        if (k0 + 32 < K) cp_wait<1>(); else cp_wait<0>();
        __syncthreads();
        if (k0 + 64 < K) {
            int st2 = st + 2;
            if (st2 >= 3) st2 -= 3;
            GPREFETCH(st2, k0 + 64);
            cp_commit();
        }

        const __half* Ah = smg + st * GSTG;
        const __half* Bh = Ah + 128 * BKP;

#pragma unroll
        for (int ks = 0; ks < 2; ks++) {
            const int kk = ks * 16;
            uint32_t ah[4][4];
            uint32_t bh[2][4];
#pragma unroll
            for (int mi = 0; mi < 4; mi++) {
                ldsm_x4(ah[mi], Ah + (wm + mi * 16 + lrow) * BKP + kk + lcol);
            }
#pragma unroll
            for (int nb = 0; nb < 2; nb++) {
                ldsm_x4(bh[nb], Bh + (wn + nb * 16 + lrow) * BKP + kk + lcol);
            }
#pragma unroll
            for (int mi = 0; mi < 4; mi++) {
#pragma unroll
                for (int nj = 0; nj < 4; nj++) {
                    const int nb = nj >> 1;
                    const int ns = nj & 1;
                    mma16816(acc[mi][nj], ah[mi], bh[nb][ns], bh[nb][ns + 2]);
                }
            }
        }
        st = st + 1;
        if (st == 3) st = 0;
    }

#pragma unroll
    for (int mi = 0; mi < 4; mi++) {
#pragma unroll
        for (int nj = 0; nj < 4; nj++) {
            int row = row0 + wm + mi * 16 + (lane >> 2);
            int col = col0 + wn + nj * 8 + (lane & 3) * 2;
            float b0 = bias[col];
            float b1 = bias[col + 1];
            float v00 = acc[mi][nj][0] + b0;
            float v01 = acc[mi][nj][1] + b1;
            float v10 = acc[mi][nj][2] + b0;
            float v11 = acc[mi][nj][3] + b1;
            if (Ch) {
                *(uint32_t*)(Ch + (size_t)row * N + col) =
                    pack_h(v00 * oscale, v01 * oscale);
                *(uint32_t*)(Ch + (size_t)(row + 8) * N + col) =
                    pack_h(v10 * oscale, v11 * oscale);
            } else {
                float2 r0;
                float2 r1;
                r0.x = v00; r0.y = v01;
                r1.x = v10; r1.y = v11;
                *(float2*)(C + (size_t)row * N + col) = r0;
                *(float2*)(C + (size_t)(row + 8) * N + col) = r1;
            }
        }
    }
}

// merged Q/K/V projection: grid.x in [0,48): 0-31 Q tiles, 32-39 K, 40-47 V
__global__ __launch_bounds__(256, 2)
void gemm_qkv(const __half* __restrict__ xh,
              const __half* __restrict__ qwh,
              const __half* __restrict__ kwh,
              const __half* __restrict__ vwh,
              const float* __restrict__ q_b,
              const float* __restrict__ k_b,
              const float* __restrict__ v_b,
              __half* __restrict__ qh,
              __half* __restrict__ kh,
              __half* __restrict__ vh,
              float qscale)
{
    const int bx = blockIdx.x;
    const int row0 = blockIdx.y * 128;

    if (bx < 32) {
        gemm_body(xh, qwh, q_b, (float*)0, qh, qscale, EMB, EMB, row0, bx * 128);
    } else if (bx < 40) {
        gemm_body(xh, kwh, k_b, (float*)0, kh, 1.0f, KVD, EMB, row0,
                  (bx - 32) * 128);
    } else {
        gemm_body(xh, vwh, v_b, (float*)0, vh, 1.0f, KVD, EMB, row0,
                  (bx - 40) * 128);
    }
}

// O projection (fp32 out)
__global__ __launch_bounds__(256, 2)
void gemm_oproj(const __half* __restrict__ ah,
                const __half* __restrict__ owh,
                const float* __restrict__ o_b,
                float* __restrict__ out)
{
    gemm_body(ah, owh, o_b, out, (__half*)0, 1.0f, EMB, EMB,
              blockIdx.y * 128, blockIdx.x * 128);
}

// ============================================================================
// Split-KV flash attention (mma.sync fp16 single-pass), base-2 softermax.
// Q persistent in smem (fragments re-ldsm'd per tile); Q staged via cp.async
// together with the stage-0 KV prefetch. 2 CTAs/SM. Grid (16, 32, 2).
// ============================================================================
#define KVP 136
#define QBYTES (128 * KVP * 2)             // persistent Q region: 34816
#define FSTG (2 * 64 * KVP)                // K + V per stage (halves)
#define FL_SMEM_BYTES (QBYTES + 2 * FSTG * 2)   // 104448

__global__ __launch_bounds__(256, 2)
void flash_mma()
{
    extern __shared__ __half smf[];
    __half* Qs = smf;                       // persistent [128][KVP]
    __half* KV = smf + 128 * KVP;           // 2 stages of K|V

    const int tid  = threadIdx.x;
    const int warp = tid >> 5;
    const int lane = tid & 31;
    const int lrow = lane & 15;
    const int lcol = (lane >> 4) * 8;
    const int wq   = warp * 16;

    const int h   = blockIdx.y;
    const int hk  = h >> 2;
    const int q0  = blockIdx.x * 128;
    const int z   = blockIdx.z;
    const int kt0 = z * 16;

    // stage Q via cp.async (8 quads per thread)
#pragma unroll
    for (int it = 0; it < 8; it++) {
        int idx = tid + it * 256;
        int r = idx >> 4;
        int c = (idx & 15) * 8;
        size_t g = (size_t)(q0 + r) * EMB + h * HD + c;
        cp16(smaddr(Qs + r * KVP + c), g_qh + g);
    }

#define FPREFETCH(st, kt)                                                     \
    do {                                                                      \
        __half* sb = KV + (st) * FSTG;                                        \
        _Pragma("unroll")                                                     \
        for (int it = 0; it < 4; it++) {                                      \
            int idx = tid + it * 256;                                         \
            int r = idx >> 4;                                                 \
            int c = (idx & 15) * 8;                                           \
            size_t g = (size_t)((kt) * 64 + r) * KVD + hk * HD + c;           \
            uint32_t d0 = smaddr(sb + r * KVP + c);                           \
            cp16(d0,                g_kh + g);                                \
            cp16(d0 + 64 * KVP * 2, g_vh + g);                                \
        }                                                                     \
    } while (0)

    FPREFETCH(0, kt0);
    cp_commit();   // one group: Q + stage-0 KV

    float o[16][4];
#pragma unroll
    for (int i = 0; i < 16; i++)
#pragma unroll
        for (int r = 0; r < 4; r++)
            o[i][r] = 0.0f;

    float m1 = -1e30f;
    float m2 = -1e30f;
    float l1 = 0.0f;
    float l2 = 0.0f;

    int st = 0;
    for (int kt = kt0; kt < kt0 + 16; kt++) {
        cp_wait<0>();
        __syncthreads();
        if (kt + 1 < kt0 + 16) {
            FPREFETCH(st ^ 1, kt + 1);
            cp_commit();
        }

        const __half* Kh = KV + st * FSTG;
        const __half* Vh = Kh + 64 * KVP;

        // ---- S = Q K^T (Q fragments re-ldsm'd from smem) ----
        float s[8][4];
#pragma unroll
        for (int t = 0; t < 8; t++)
#pragma unroll
            for (int r = 0; r < 4; r++)
                s[t][r] = 0.0f;

#pragma unroll
        for (int ks = 0; ks < 8; ks++) {
            uint32_t qf[4];
            ldsm_x4(qf, Qs + (wq + lrow) * KVP + ks * 16 + lcol);
#pragma unroll
            for (int nsl = 0; nsl < 4; nsl++) {
                uint32_t kf[4];
                ldsm_x4(kf, Kh + (nsl * 16 + lrow) * KVP + ks * 16 + lcol);
                mma16816(s[nsl * 2],     qf, kf[0], kf[2]);
                mma16816(s[nsl * 2 + 1], qf, kf[1], kf[3]);
            }
        }

        // ---- online base-2 softmax ----
        float mx1 = -1e30f;
        float mx2 = -1e30f;
#pragma unroll
        for (int t = 0; t < 8; t++) {
            mx1 = fmaxf(mx1, fmaxf(s[t][0], s[t][1]));
            mx2 = fmaxf(mx2, fmaxf(s[t][2], s[t][3]));
        }
        mx1 = fmaxf(mx1, __shfl_xor_sync(0xffffffffu, mx1, 1));
        mx1 = fmaxf(mx1, __shfl_xor_sync(0xffffffffu, mx1, 2));
        mx2 = fmaxf(mx2, __shfl_xor_sync(0xffffffffu, mx2, 1));
        mx2 = fmaxf(mx2, __shfl_xor_sync(0xffffffffu, mx2, 2));

        float newm1 = fmaxf(m1, mx1);
        float newm2 = fmaxf(m2, mx2);
        float corr1 = exp2f(m1 - newm1);
        float corr2 = exp2f(m2 - newm2);
        m1 = newm1;
        m2 = newm2;

        float ps1 = 0.0f;
        float ps2 = 0.0f;
#pragma unroll
        for (int t = 0; t < 8; t++) {
            s[t][0] = exp2f(s[t][0] - newm1);
            s[t][1] = exp2f(s[t][1] - newm1);
            s[t][2] = exp2f(s[t][2] - newm2);
            s[t][3] = exp2f(s[t][3] - newm2);
            ps1 += s[t][0] + s[t][1];
            ps2 += s[t][2] + s[t][3];
        }
        l1 = l1 * corr1 + ps1;
        l2 = l2 * corr2 + ps2;

#pragma unroll
        for (int i = 0; i < 16; i++) {
            o[i][0] *= corr1;
            o[i][1] *= corr1;
            o[i][2] *= corr2;
            o[i][3] *= corr2;
        }

        // ---- O += P V (V via ldmatrix.trans) ----
#pragma unroll
        for (int ks2 = 0; ks2 < 4; ks2++) {
            uint32_t ph[4];
            ph[0] = pack_h(s[2 * ks2][0],     s[2 * ks2][1]);
            ph[1] = pack_h(s[2 * ks2][2],     s[2 * ks2][3]);
            ph[2] = pack_h(s[2 * ks2 + 1][0], s[2 * ks2 + 1][1]);
            ph[3] = pack_h(s[2 * ks2 + 1][2], s[2 * ks2 + 1][3]);
#pragma unroll
            for (int dsl = 0; dsl < 8; dsl++) {
                uint32_t vf[4];
                ldsm_x4t(vf, Vh + (ks2 * 16 + lrow) * KVP + dsl * 16 + lcol);
                mma16816(o[dsl * 2],     ph, vf[0], vf[1]);
                mma16816(o[dsl * 2 + 1], ph, vf[2], vf[3]);
            }
        }
        st ^= 1;
    }

    // ---- write fp32 partials + (m, l) ----
    l1 += __shfl_xor_sync(0xffffffffu, l1, 1);
    l1 += __shfl_xor_sync(0xffffffffu, l1, 2);
    l2 += __shfl_xor_sync(0xffffffffu, l2, 1);
    l2 += __shfl_xor_sync(0xffffffffu, l2, 2);

    const int row1 = q0 + wq + (lane >> 2);
    const int row2 = row1 + 8;
    const size_t zo = (size_t)z * SEQ * EMB;

    if ((lane & 3) == 0) {
        int mo = z * NH * SEQ + h * SEQ;
        g_pm[mo + row1] = m1;
        g_pl[mo + row1] = l1;
        g_pm[mo + row2] = m2;
        g_pl[mo + row2] = l2;
    }

#pragma unroll
    for (int nt = 0; nt < 16; nt++) {
        int col = h * HD + nt * 8 + (lane & 3) * 2;
        float2 r0;
        float2 r1;
        r0.x = o[nt][0];
        r0.y = o[nt][1];
        r1.x = o[nt][2];
        r1.y = o[nt][3];
        *(float2*)(g_po + zo + (size_t)row1 * EMB + col) = r0;
        *(float2*)(g_po + zo + (size_t)row2 * EMB + col) = r1;
    }
}

// ============================================================================
// combine KV halves -> fp16 attention output (float4 vectorized)
// ============================================================================
__global__ __launch_bounds__(256)
void attn_combine()
{
    int idx = blockIdx.x * blockDim.x + threadIdx.x;   // < SEQ*EMB/4
    int row  = idx >> 10;          // EMB/4 = 1024 quads per row
    int qc   = idx & 1023;
    int col  = qc * 4;
    int head = col >> 7;

    int mo = head * SEQ + row;
    float m1 = g_pm[mo];
    float l1 = g_pl[mo];
    float m2 = g_pm[NH * SEQ + mo];
    float l2 = g_pl[NH * SEQ + mo];

    float mm = fmaxf(m1, m2);
    float w1 = exp2f(m1 - mm);
    float w2 = exp2f(m2 - mm);
    float inv = 1.0f / (w1 * l1 + w2 * l2);
    w1 *= inv;
    w2 *= inv;

    size_t off = (size_t)row * EMB + col;
    float4 o1 = *(const float4*)(g_po + off);
    float4 o2 = *(const float4*)(g_po + (size_t)SEQ * EMB + off);

    uint2 r;
    r.x = pack_h(w1 * o1.x + w2 * o2.x, w1 * o1.y + w2 * o2.y);
    r.y = pack_h(w1 * o1.z + w2 * o2.z, w1 * o1.w + w2 * o2.w);
    *(uint2*)(g_ah + off) = r;
}

// ============================================================================
// launch
// ============================================================================
extern "C" void kernel_launch(void* const* d_in, const int* in_sizes, int n_in,
                              void* d_out, int out_size)
{
    const float* x   = (const float*)d_in[0];
    const float* q_w = (const float*)d_in[1];
    const float* q_b = (const float*)d_in[2];
    const float* k_w = (const float*)d_in[3];
    const float* k_b = (const float*)d_in[4];
    const float* v_w = (const float*)d_in[5];
    const float* v_b = (const float*)d_in[6];
    const float* o_w = (const float*)d_in[7];
    const float* o_b = (const float*)d_in[8];
    float* out = (float*)d_out;

    __half* xh = 0;
    __half* qwh = 0;
    __half* kwh = 0;
    __half* vwh = 0;
    __half* owh = 0;
    __half* qh = 0;
    __half* kh = 0;
    __half* vh = 0;
    __half* ah = 0;
    cudaGetSymbolAddress((void**)&xh,  g_xh);
    cudaGetSymbolAddress((void**)&qwh, g_qwh);
    cudaGetSymbolAddress((void**)&kwh, g_kwh);
    cudaGetSymbolAddress((void**)&vwh, g_vwh);
    cudaGetSymbolAddress((void**)&owh, g_owh);
    cudaGetSymbolAddress((void**)&qh,  g_qh);
    cudaGetSymbolAddress((void**)&kh,  g_kh);
    cudaGetSymbolAddress((void**)&vh,  g_vh);
    cudaGetSymbolAddress((void**)&ah,  g_ah);

    cudaFuncSetAttribute(gemm_qkv,
                         cudaFuncAttributeMaxDynamicSharedMemorySize,
                         GEMM_SMEM_BYTES);
    cudaFuncSetAttribute(gemm_oproj,
                         cudaFuncAttributeMaxDynamicSharedMemorySize,
                         GEMM_SMEM_BYTES);
    cudaFuncSetAttribute(flash_mma,
                         cudaFuncAttributeMaxDynamicSharedMemorySize,
                         FL_SMEM_BYTES);

    dim3 blk(256);
    const float qscale = 0.08838834764831845f;   // 1/sqrt(128)

    cvt_all<<<12288, 256>>>((const float4*)x, (const float4*)q_w,
                            (const float4*)k_w, (const float4*)v_w,
                            (const float4*)o_w,
                            (uint32_t*)xh, (uint32_t*)qwh, (uint32_t*)kwh,
                            (uint32_t*)vwh, (uint32_t*)owh);

    gemm_qkv<<<dim3(48, 16), blk, GEMM_SMEM_BYTES>>>(
        xh, qwh, kwh, vwh, q_b, k_b, v_b, qh, kh, vh, qscale);

    flash_mma<<<dim3(16, 32, 2), blk, FL_SMEM_BYTES>>>();
    attn_combine<<<(SEQ * EMB / 4) / 256, 256>>>();

    gemm_oproj<<<dim3(32, 16), blk, GEMM_SMEM_BYTES>>>(ah, owh, o_b, out);
}